// round 1
// baseline (speedup 1.0000x reference)
#include <cuda_runtime.h>
#include <math.h>

#define BB   2
#define TT   4096
#define DD   768
#define HH   12
#define HDIM 64
#define QKV3 (3*DD)       // 2304
#define ATT_SCALE 0.125f  // 1/sqrt(64)

// Scratch (device globals: allocation-free per harness rules)
__device__ float g_qkv[(size_t)BB*TT*QKV3];   // [B,T,3*D]  (s*768 + h*64 + d)
__device__ float g_att[(size_t)BB*TT*DD];     // [B,T,D]    (h*64 + d)

// ---------------------------------------------------------------------------
// Generic fp32 GEMM + bias: C[M,N] = A[M,K] @ B[K,N] + bias[N]
// 128x128 block tile, BK=16, 8x8 per thread, 256 threads.
// Requires M%128==0, N%128==0, K%16==0 (true for all our shapes).
// ---------------------------------------------------------------------------
__global__ __launch_bounds__(256) void gemm_bias_128(
    const float* __restrict__ A, const float* __restrict__ Bm,
    const float* __restrict__ bias, float* __restrict__ C,
    int M, int N, int K)
{
    __shared__ float As[16][128];   // transposed A tile: As[k][m]
    __shared__ float Bs[16][128];   // Bs[k][n]

    const int tid  = threadIdx.x;
    const int brow = blockIdx.y;
    const int bcol = blockIdx.x;
    const int tr   = tid >> 4;      // 0..15
    const int tc   = tid & 15;      // 0..15

    float acc[8][8];
#pragma unroll
    for (int i = 0; i < 8; i++)
#pragma unroll
        for (int j = 0; j < 8; j++) acc[i][j] = 0.f;

    for (int k0 = 0; k0 < K; k0 += 16) {
#pragma unroll
        for (int p = 0; p < 2; p++) {
            int v  = tid + 256 * p;                 // 0..511
            // A tile: 128 rows x 16 k  (512 float4)
            int ra = v >> 2, ca = (v & 3) << 2;
            float4 a4 = *(const float4*)(A + (size_t)(brow*128 + ra)*K + k0 + ca);
            As[ca+0][ra] = a4.x; As[ca+1][ra] = a4.y;
            As[ca+2][ra] = a4.z; As[ca+3][ra] = a4.w;
            // B tile: 16 k x 128 n (512 float4)
            int rb = v >> 5, cb = (v & 31) << 2;
            float4 b4 = *(const float4*)(Bm + (size_t)(k0 + rb)*N + bcol*128 + cb);
            *(float4*)&Bs[rb][cb] = b4;
        }
        __syncthreads();

#pragma unroll
        for (int kk = 0; kk < 16; kk++) {
            float4 a0 = *(const float4*)&As[kk][tr*8];
            float4 a1 = *(const float4*)&As[kk][tr*8 + 4];
            float4 b0 = *(const float4*)&Bs[kk][tc*8];
            float4 b1 = *(const float4*)&Bs[kk][tc*8 + 4];
            float a[8] = {a0.x,a0.y,a0.z,a0.w,a1.x,a1.y,a1.z,a1.w};
            float b[8] = {b0.x,b0.y,b0.z,b0.w,b1.x,b1.y,b1.z,b1.w};
#pragma unroll
            for (int i = 0; i < 8; i++)
#pragma unroll
                for (int j = 0; j < 8; j++)
                    acc[i][j] = fmaf(a[i], b[j], acc[i][j]);
        }
        __syncthreads();
    }

    const float* bp = bias + bcol*128 + tc*8;
    float bb[8];
#pragma unroll
    for (int j = 0; j < 8; j++) bb[j] = bp[j];

#pragma unroll
    for (int i = 0; i < 8; i++) {
        int row = brow*128 + tr*8 + i;
        float* crow = C + (size_t)row*N + bcol*128 + tc*8;
        float4 o0 = make_float4(acc[i][0]+bb[0], acc[i][1]+bb[1],
                                acc[i][2]+bb[2], acc[i][3]+bb[3]);
        float4 o1 = make_float4(acc[i][4]+bb[4], acc[i][5]+bb[5],
                                acc[i][6]+bb[6], acc[i][7]+bb[7]);
        *(float4*)(crow)     = o0;
        *(float4*)(crow + 4) = o1;
    }
}

// ---------------------------------------------------------------------------
// Causal flash attention, fp32, online softmax.
// One CTA per (b, h, q-tile of 64 rows). 256 threads = 16x16, 4x4 microtile.
// Smem (dynamic): Qs[64][64] (d-major), Ks[64][64] (d-major), Vs[64][64],
//                 Ps[64][65] (padded).
// ---------------------------------------------------------------------------
__global__ __launch_bounds__(256) void attn_kernel()
{
    extern __shared__ float smem[];
    float (*Qs)[64] = (float(*)[64])(smem);          // [d][r]
    float (*Ks)[64] = (float(*)[64])(smem + 4096);   // [d][c]
    float (*Vs)[64] = (float(*)[64])(smem + 8192);   // [k][d]
    float (*Ps)[65] = (float(*)[65])(smem + 12288);  // [r][k], padded

    const int tid = threadIdx.x;
    const int ty  = tid >> 4;   // 0..15 -> rows ty*4..+3
    const int tx  = tid & 15;   // 0..15 -> cols tx*4..+3
    const int bh  = blockIdx.y;
    const int b   = bh / HH, h = bh % HH;
    const int qt  = gridDim.x - 1 - blockIdx.x;   // big tiles scheduled first
    const int q0  = qt * 64;

    const float* qb = g_qkv + (size_t)b*TT*QKV3 + h*HDIM;
    const float* kb = qb + DD;
    const float* vb = qb + 2*DD;

    // Load Q tile transposed into smem: Qs[d][r]
#pragma unroll
    for (int p = 0; p < 4; p++) {
        int v  = tid + 256 * p;          // 0..1023 float4 slots
        int r  = v >> 4;                 // 0..63 row
        int c4 = (v & 15) << 2;          // 0..60 d-offset
        float4 q4 = *(const float4*)(qb + (size_t)(q0 + r)*QKV3 + c4);
        Qs[c4+0][r] = q4.x; Qs[c4+1][r] = q4.y;
        Qs[c4+2][r] = q4.z; Qs[c4+3][r] = q4.w;
    }

    float m[4], l[4], O[4][4];
#pragma unroll
    for (int i = 0; i < 4; i++) {
        m[i] = -INFINITY; l[i] = 0.f;
#pragma unroll
        for (int c = 0; c < 4; c++) O[i][c] = 0.f;
    }

    for (int kt = 0; kt <= qt; kt++) {
        const int k0 = kt * 64;
        __syncthreads();   // prior iter's Vs/Ps reads done; iter0: Qs visible

        // Load K (transposed) and V (natural)
#pragma unroll
        for (int p = 0; p < 4; p++) {
            int v  = tid + 256 * p;
            int r  = v >> 4;
            int c4 = (v & 15) << 2;
            float4 k4 = *(const float4*)(kb + (size_t)(k0 + r)*QKV3 + c4);
            Ks[c4+0][r] = k4.x; Ks[c4+1][r] = k4.y;
            Ks[c4+2][r] = k4.z; Ks[c4+3][r] = k4.w;
            float4 v4 = *(const float4*)(vb + (size_t)(k0 + r)*QKV3 + c4);
            *(float4*)&Vs[r][c4] = v4;
        }
        __syncthreads();

        // S = Q K^T  (4x4 per thread)
        float s[4][4];
#pragma unroll
        for (int i = 0; i < 4; i++)
#pragma unroll
            for (int j = 0; j < 4; j++) s[i][j] = 0.f;

#pragma unroll 8
        for (int d = 0; d < 64; d++) {
            float4 av = *(const float4*)&Qs[d][ty*4];
            float4 bv = *(const float4*)&Ks[d][tx*4];
            float a[4] = {av.x, av.y, av.z, av.w};
            float bvv[4] = {bv.x, bv.y, bv.z, bv.w};
#pragma unroll
            for (int i = 0; i < 4; i++)
#pragma unroll
                for (int j = 0; j < 4; j++)
                    s[i][j] = fmaf(a[i], bvv[j], s[i][j]);
        }

#pragma unroll
        for (int i = 0; i < 4; i++)
#pragma unroll
            for (int j = 0; j < 4; j++) s[i][j] *= ATT_SCALE;

        if (kt == qt) {  // diagonal tile: causal mask
#pragma unroll
            for (int i = 0; i < 4; i++) {
                int qq = ty*4 + i;
#pragma unroll
                for (int j = 0; j < 4; j++)
                    if (tx*4 + j > qq) s[i][j] = -INFINITY;
            }
        }

        // Online softmax (row groups owned by same ty across 16 tx lanes)
#pragma unroll
        for (int i = 0; i < 4; i++) {
            float rm = fmaxf(fmaxf(s[i][0], s[i][1]), fmaxf(s[i][2], s[i][3]));
            rm = fmaxf(rm, __shfl_xor_sync(0xffffffffu, rm, 8, 16));
            rm = fmaxf(rm, __shfl_xor_sync(0xffffffffu, rm, 4, 16));
            rm = fmaxf(rm, __shfl_xor_sync(0xffffffffu, rm, 2, 16));
            rm = fmaxf(rm, __shfl_xor_sync(0xffffffffu, rm, 1, 16));
            float mn    = fmaxf(m[i], rm);
            float alpha = __expf(m[i] - mn);  // -inf -> 0 on first tile
            m[i] = mn;
            float rs = 0.f;
#pragma unroll
            for (int j = 0; j < 4; j++) {
                float pij = __expf(s[i][j] - mn);
                s[i][j] = pij;
                rs += pij;
            }
            rs += __shfl_xor_sync(0xffffffffu, rs, 8, 16);
            rs += __shfl_xor_sync(0xffffffffu, rs, 4, 16);
            rs += __shfl_xor_sync(0xffffffffu, rs, 2, 16);
            rs += __shfl_xor_sync(0xffffffffu, rs, 1, 16);
            l[i] = l[i]*alpha + rs;
#pragma unroll
            for (int c = 0; c < 4; c++) O[i][c] *= alpha;
        }

        // Stage P to smem
#pragma unroll
        for (int i = 0; i < 4; i++)
#pragma unroll
            for (int j = 0; j < 4; j++)
                Ps[ty*4 + i][tx*4 + j] = s[i][j];
        __syncthreads();

        // O += P @ V
#pragma unroll 8
        for (int kk = 0; kk < 64; kk++) {
            float a0 = Ps[ty*4 + 0][kk];
            float a1 = Ps[ty*4 + 1][kk];
            float a2 = Ps[ty*4 + 2][kk];
            float a3 = Ps[ty*4 + 3][kk];
            float4 bv = *(const float4*)&Vs[kk][tx*4];
            O[0][0] = fmaf(a0, bv.x, O[0][0]); O[0][1] = fmaf(a0, bv.y, O[0][1]);
            O[0][2] = fmaf(a0, bv.z, O[0][2]); O[0][3] = fmaf(a0, bv.w, O[0][3]);
            O[1][0] = fmaf(a1, bv.x, O[1][0]); O[1][1] = fmaf(a1, bv.y, O[1][1]);
            O[1][2] = fmaf(a1, bv.z, O[1][2]); O[1][3] = fmaf(a1, bv.w, O[1][3]);
            O[2][0] = fmaf(a2, bv.x, O[2][0]); O[2][1] = fmaf(a2, bv.y, O[2][1]);
            O[2][2] = fmaf(a2, bv.z, O[2][2]); O[2][3] = fmaf(a2, bv.w, O[2][3]);
            O[3][0] = fmaf(a3, bv.x, O[3][0]); O[3][1] = fmaf(a3, bv.y, O[3][1]);
            O[3][2] = fmaf(a3, bv.z, O[3][2]); O[3][3] = fmaf(a3, bv.w, O[3][3]);
        }
    }

    // Normalize + store to g_att[b, q0+r, h*64 + c]
    float* ob = g_att + ((size_t)b*TT + q0)*DD + h*HDIM;
#pragma unroll
    for (int i = 0; i < 4; i++) {
        float inv = 1.f / l[i];
        float4 o = make_float4(O[i][0]*inv, O[i][1]*inv, O[i][2]*inv, O[i][3]*inv);
        *(float4*)(ob + (size_t)(ty*4 + i)*DD + tx*4) = o;
    }
}

// ---------------------------------------------------------------------------
extern "C" void kernel_launch(void* const* d_in, const int* in_sizes, int n_in,
                              void* d_out, int out_size)
{
    const float* x     = (const float*)d_in[0];
    const float* W_qkv = (const float*)d_in[1];
    const float* b_qkv = (const float*)d_in[2];
    const float* W_out = (const float*)d_in[3];
    const float* b_out = (const float*)d_in[4];
    float* out = (float*)d_out;

    void* p;
    cudaGetSymbolAddress(&p, g_qkv); float* qkv = (float*)p;
    cudaGetSymbolAddress(&p, g_att); float* att = (float*)p;

    const int M = BB * TT;  // 8192
    dim3 blk(256);

    // 1) QKV projection: [8192,768] @ [768,2304] + b
    gemm_bias_128<<<dim3(QKV3/128, M/128), blk>>>(x, W_qkv, b_qkv, qkv, M, QKV3, DD);

    // 2) Causal flash attention
    const int smem_bytes = (4096*3 + 64*65) * (int)sizeof(float);  // 65792 B
    cudaFuncSetAttribute(attn_kernel,
                         cudaFuncAttributeMaxDynamicSharedMemorySize, smem_bytes);
    attn_kernel<<<dim3(TT/64, BB*HH), blk, smem_bytes>>>();

    // 3) Output projection: [8192,768] @ [768,768] + b
    gemm_bias_128<<<dim3(DD/128, M/128), blk>>>(att, W_out, b_out, out, M, DD, DD);
}

// round 3
// speedup vs baseline: 2.1522x; 2.1522x over previous
#include <cuda_runtime.h>
#include <cuda_bf16.h>
#include <math.h>
#include <cstdint>

#define BB   2
#define TT   4096
#define DD   768
#define HH   12
#define HDIM 64
#define QKV3 (3*DD)       // 2304
#define ATT_SCALE 0.125f  // 1/sqrt(64)

// tcgen05 is an arch-specific ('a') feature. The harness build also assembles a
// plain compute_103 PTX target where tcgen05 is illegal, so gate the tensor-core
// body on the arch-feature macros and give that target a SIMT fp32 fallback.
#if !defined(__CUDA_ARCH__)
#define HAS_TC 1   // host pass: body text irrelevant
#elif defined(__CUDA_ARCH_FEAT_SM103_ALL)
#define HAS_TC 1
#elif defined(__CUDA_ARCH_SPECIFIC__) && (__CUDA_ARCH_SPECIFIC__ == 1030)
#define HAS_TC 1
#elif defined(__CUDA_ARCH_FAMILY_SPECIFIC__) && (__CUDA_ARCH_FAMILY_SPECIFIC__ >= 1000)
#define HAS_TC 1
#else
#define HAS_TC 0
#endif

// ---------------- scratch (device globals; allocation-free) ----------------
__device__ float         g_qkv [(size_t)BB*TT*QKV3];   // [B,T,3D] fp32
__device__ float         g_att [(size_t)BB*TT*DD];     // [B,T,D]  fp32
__device__ __nv_bfloat16 g_xhi [(size_t)BB*TT*DD];
__device__ __nv_bfloat16 g_xlo [(size_t)BB*TT*DD];
__device__ __nv_bfloat16 g_ahi [(size_t)BB*TT*DD];
__device__ __nv_bfloat16 g_alo [(size_t)BB*TT*DD];
__device__ __nv_bfloat16 g_wqt_hi[(size_t)QKV3*DD];    // W_qkv^T [N=2304][K=768]
__device__ __nv_bfloat16 g_wqt_lo[(size_t)QKV3*DD];
__device__ __nv_bfloat16 g_wot_hi[(size_t)DD*DD];      // W_out^T [768][768]
__device__ __nv_bfloat16 g_wot_lo[(size_t)DD*DD];

// ---------------- minimal PTX helpers (sm_103a only) ------------------------
__device__ __forceinline__ uint32_t smem_u32(const void* p) {
    uint32_t a;
    asm("{ .reg .u64 t; cvta.to.shared.u64 t, %1; cvt.u32.u64 %0, t; }"
        : "=r"(a) : "l"(p));
    return a;
}
#define SMEM_SWIZZLE_128B(off) ((off) ^ (((off) >> 3) & 0x70))

#if HAS_TC
__device__ __forceinline__ uint32_t elect_one() {
    uint32_t pred;
    asm volatile("{\n\t.reg .pred p;\n\telect.sync _|p, 0xFFFFFFFF;\n\t"
                 "selp.b32 %0, 1, 0, p;\n\t}" : "=r"(pred));
    return pred;
}
static constexpr uint64_t SMEM_DESC_BASE_SW128 =
    (uint64_t(2) << 61) | (uint64_t(1) << 46) | (uint64_t(64) << 32) | (uint64_t(1) << 16);
#define MAKE_SMEM_DESC(addr) (SMEM_DESC_BASE_SW128 | ((uint64_t)((addr) >> 4) & 0x3FFF))

#define TCGEN05_ALLOC(sa, n) \
    asm volatile("tcgen05.alloc.cta_group::1.sync.aligned.shared::cta.b32 [%0], %1;" \
                 :: "r"((uint32_t)(sa)), "r"((uint32_t)(n)) : "memory")
#define TCGEN05_DEALLOC(t, n) \
    asm volatile("tcgen05.dealloc.cta_group::1.sync.aligned.b32 %0, %1;" :: "r"(t), "r"(n))
#define TCGEN05_RELINQ() \
    asm volatile("tcgen05.relinquish_alloc_permit.cta_group::1.sync.aligned;")
#define TCGEN05_COMMIT(mb) \
    asm volatile("tcgen05.commit.cta_group::1.mbarrier::arrive::one.shared::cluster.b64 [%0];" \
                 :: "r"((uint32_t)(mb)) : "memory")
#define TCGEN05_FENCE_AFTER() \
    asm volatile("tcgen05.fence::after_thread_sync;" ::: "memory")
#define TCGEN05_WAIT_LD() \
    asm volatile("tcgen05.wait::ld.sync.aligned;" ::: "memory")
#define FENCE_PROXY_ASYNC() \
    asm volatile("fence.proxy.async.shared::cta;" ::: "memory")
#define MBARRIER_INIT(mb, cnt) \
    asm volatile("mbarrier.init.shared.b64 [%0], %1;" \
                 :: "r"((uint32_t)(mb)), "r"((uint32_t)(cnt)) : "memory")
#define MBARRIER_WAIT_PARITY(mb, ph) do {                                   \
    uint32_t _m = (uint32_t)(mb); uint32_t _p = (uint32_t)(ph);             \
    asm volatile("{\n\t.reg .pred P1;\n\t"                                  \
        "WL_%=:\n\t"                                                        \
        "mbarrier.try_wait.parity.acquire.cta.shared::cta.b64 P1, [%0], %1, 0x989680;\n\t" \
        "@P1 bra.uni WD_%=;\n\t"                                            \
        "bra.uni WL_%=;\n\t"                                                \
        "WD_%=:\n\t}" :: "r"(_m), "r"(_p) : "memory");                      \
} while (0)

__device__ __forceinline__ void mma_f16_ss_cg1(
    uint32_t d_tmem, uint64_t a_desc, uint64_t b_desc, uint32_t idesc, uint32_t en)
{
    asm volatile(
        "{\n\t.reg .pred p;\n\tsetp.ne.u32 p, %5, 0;\n\t"
        "tcgen05.mma.cta_group::1.kind::f16 [%0], %1, %2, %3, {%4, %4, %4, %4}, p;\n\t}"
        :: "r"(d_tmem), "l"(a_desc), "l"(b_desc), "r"(idesc), "r"(0u), "r"(en)
        : "memory");
}
#define LDTM_X32(r, addr)                                                    \
    asm volatile("tcgen05.ld.sync.aligned.32x32b.x32.b32 "                   \
        "{%0, %1, %2, %3, %4, %5, %6, %7, %8, %9, %10, %11, %12, %13, %14, %15, " \
        " %16, %17, %18, %19, %20, %21, %22, %23, %24, %25, %26, %27, %28, %29, %30, %31}, [%32];" \
        : "=r"((r)[0]),  "=r"((r)[1]),  "=r"((r)[2]),  "=r"((r)[3]),         \
          "=r"((r)[4]),  "=r"((r)[5]),  "=r"((r)[6]),  "=r"((r)[7]),         \
          "=r"((r)[8]),  "=r"((r)[9]),  "=r"((r)[10]), "=r"((r)[11]),        \
          "=r"((r)[12]), "=r"((r)[13]), "=r"((r)[14]), "=r"((r)[15]),        \
          "=r"((r)[16]), "=r"((r)[17]), "=r"((r)[18]), "=r"((r)[19]),        \
          "=r"((r)[20]), "=r"((r)[21]), "=r"((r)[22]), "=r"((r)[23]),        \
          "=r"((r)[24]), "=r"((r)[25]), "=r"((r)[26]), "=r"((r)[27]),        \
          "=r"((r)[28]), "=r"((r)[29]), "=r"((r)[30]), "=r"((r)[31])         \
        : "r"(addr))
#endif  // HAS_TC

// ---------------- split / transpose prep kernels ---------------------------
__global__ __launch_bounds__(256) void split_hl(
    const float* __restrict__ src, __nv_bfloat16* __restrict__ hi,
    __nv_bfloat16* __restrict__ lo, int n4)
{
    int i = blockIdx.x * 256 + threadIdx.x;
    if (i >= n4) return;
    float4 v = ((const float4*)src)[i];
    float vs[4] = {v.x, v.y, v.z, v.w};
    __nv_bfloat16 h[4], l[4];
#pragma unroll
    for (int j = 0; j < 4; j++) {
        h[j] = __float2bfloat16(vs[j]);
        l[j] = __float2bfloat16(vs[j] - __bfloat162float(h[j]));
    }
    ((__nv_bfloat162*)hi)[2*i]   = __halves2bfloat162(h[0], h[1]);
    ((__nv_bfloat162*)hi)[2*i+1] = __halves2bfloat162(h[2], h[3]);
    ((__nv_bfloat162*)lo)[2*i]   = __halves2bfloat162(l[0], l[1]);
    ((__nv_bfloat162*)lo)[2*i+1] = __halves2bfloat162(l[2], l[3]);
}

// W[K][N] fp32 -> Thi/Tlo[N][K] bf16 (transposed, K-major)
__global__ void tsplit_kernel(
    const float* __restrict__ W, __nv_bfloat16* __restrict__ Thi,
    __nv_bfloat16* __restrict__ Tlo, int K, int N)
{
    __shared__ float t[32][33];
    int kb = blockIdx.x * 32, nb = blockIdx.y * 32;
    int tx = threadIdx.x, ty = threadIdx.y;
#pragma unroll
    for (int i = 0; i < 4; i++) {
        int k = ty + i * 8;
        t[k][tx] = W[(size_t)(kb + k) * N + nb + tx];
    }
    __syncthreads();
#pragma unroll
    for (int i = 0; i < 4; i++) {
        int nr = ty + i * 8;
        float v = t[tx][nr];
        __nv_bfloat16 h = __float2bfloat16(v);
        __nv_bfloat16 l = __float2bfloat16(v - __bfloat162float(h));
        size_t o = (size_t)(nb + nr) * K + kb + tx;
        Thi[o] = h; Tlo[o] = l;
    }
}

// ---------------- unified GEMM: tcgen05 on sm_103a, SIMT fp32 otherwise ----
// C[M,N] = A @ B + bias. tc path: split-bf16 SS MMA, CTA tile 128x128, K=64
// chunks, 3-combo (hi*hi + hi*lo + lo*hi). Fallback: fp32 128x128x16 tiling.
#define SM_A   1024
#define SM_AL  (SM_A  + 16384)
#define SM_B   (SM_AL + 16384)
#define SM_BL  (SM_B  + 16384)
#define GEMM_SMEM (SM_BL + 16384)     // 66560 B
#define GEMM_IDESC 0x8200490u          // f32 accum, bf16 x bf16, M=128, N=128

#if HAS_TC
__device__ __forceinline__ void load_tile64(
    char* smem, int dst, const __nv_bfloat16* __restrict__ g,
    int ld, int row0, int k0, int tid)
{
    const char* base = (const char*)g;
#pragma unroll
    for (int p = 0; p < 4; p++) {
        int i = tid + p * 256;
        int r = i >> 3;
        int c16 = (i & 7) << 4;
        uint4 v = *(const uint4*)(base + ((size_t)(row0 + r) * ld + k0) * 2 + c16);
        *(uint4*)(smem + dst + SMEM_SWIZZLE_128B(r * 128 + c16)) = v;
    }
}
#endif

__global__ __launch_bounds__(256) void gemm_any(
    const float* __restrict__ A, const float* __restrict__ W,       // fp32 path
    const __nv_bfloat16* __restrict__ Ahi, const __nv_bfloat16* __restrict__ Alo,
    const __nv_bfloat16* __restrict__ Bthi, const __nv_bfloat16* __restrict__ Btlo,
    const float* __restrict__ bias, float* __restrict__ C,
    int M, int N, int K)
{
    extern __shared__ char smem[];
#if HAS_TC
    const uint32_t sb = smem_u32(smem);
    const int tid = threadIdx.x;
    const int wid = tid >> 5, lid = tid & 31;
    const int m0 = blockIdx.y * 128, n0 = blockIdx.x * 128;

    if (wid == 0) { TCGEN05_ALLOC(sb, 128); TCGEN05_RELINQ(); }
    if (tid == 0) MBARRIER_INIT(sb + 8, 1);
    __syncthreads();
    uint32_t tmem;
    asm volatile("ld.shared.b32 %0, [%1];" : "=r"(tmem) : "r"(sb));

    const uint64_t dAh = MAKE_SMEM_DESC(sb + SM_A);
    const uint64_t dAl = MAKE_SMEM_DESC(sb + SM_AL);
    const uint64_t dBh = MAKE_SMEM_DESC(sb + SM_B);
    const uint64_t dBl = MAKE_SMEM_DESC(sb + SM_BL);

    const int nchunks = K >> 6;
    for (int c = 0; c < nchunks; c++) {
        const int k0 = c << 6;
        load_tile64(smem, SM_A,  Ahi,  K, m0, k0, tid);
        load_tile64(smem, SM_AL, Alo,  K, m0, k0, tid);
        load_tile64(smem, SM_B,  Bthi, K, n0, k0, tid);
        load_tile64(smem, SM_BL, Btlo, K, n0, k0, tid);
        FENCE_PROXY_ASYNC();
        __syncthreads();

        if (wid == 0 && elect_one()) {
#pragma unroll
            for (int ks = 0; ks < 4; ks++) {
                uint32_t en0 = (c > 0 || ks > 0) ? 1u : 0u;
                mma_f16_ss_cg1(tmem, dAh + ks*2, dBh + ks*2, GEMM_IDESC, en0);
                mma_f16_ss_cg1(tmem, dAh + ks*2, dBl + ks*2, GEMM_IDESC, 1u);
                mma_f16_ss_cg1(tmem, dAl + ks*2, dBh + ks*2, GEMM_IDESC, 1u);
            }
            TCGEN05_COMMIT(sb + 8);
        }
        MBARRIER_WAIT_PARITY(sb + 8, c & 1);
    }

    TCGEN05_FENCE_AFTER();
    if (wid < 4) {
        const int row = m0 + wid * 32 + lid;
#pragma unroll
        for (int base = 0; base < 128; base += 32) {
            uint32_t r[32];
            LDTM_X32(r, tmem + base);
            TCGEN05_WAIT_LD();
            float* crow = C + (size_t)row * N + n0 + base;
            const float* bp = bias + n0 + base;
#pragma unroll
            for (int j = 0; j < 32; j += 4) {
                float4 o = make_float4(__uint_as_float(r[j])   + bp[j],
                                       __uint_as_float(r[j+1]) + bp[j+1],
                                       __uint_as_float(r[j+2]) + bp[j+2],
                                       __uint_as_float(r[j+3]) + bp[j+3]);
                *(float4*)(crow + j) = o;
            }
        }
    }
    __syncthreads();
    if (wid == 0) TCGEN05_DEALLOC(tmem, 128);

#else  // ---------------- SIMT fp32 fallback (non-'a' target) --------------
    float (*As)[128] = (float(*)[128])(smem);            // [k][m]
    float (*Bs)[128] = (float(*)[128])(smem + 8192);     // [k][n]

    const int tid  = threadIdx.x;
    const int brow = blockIdx.y;
    const int bcol = blockIdx.x;
    const int tr   = tid >> 4;
    const int tc   = tid & 15;

    float acc[8][8];
#pragma unroll
    for (int i = 0; i < 8; i++)
#pragma unroll
        for (int j = 0; j < 8; j++) acc[i][j] = 0.f;

    for (int k0 = 0; k0 < K; k0 += 16) {
#pragma unroll
        for (int p = 0; p < 2; p++) {
            int v  = tid + 256 * p;
            int ra = v >> 2, ca = (v & 3) << 2;
            float4 a4 = *(const float4*)(A + (size_t)(brow*128 + ra)*K + k0 + ca);
            As[ca+0][ra] = a4.x; As[ca+1][ra] = a4.y;
            As[ca+2][ra] = a4.z; As[ca+3][ra] = a4.w;
            int rb = v >> 5, cb = (v & 31) << 2;
            float4 b4 = *(const float4*)(W + (size_t)(k0 + rb)*N + bcol*128 + cb);
            *(float4*)&Bs[rb][cb] = b4;
        }
        __syncthreads();

#pragma unroll
        for (int kk = 0; kk < 16; kk++) {
            float4 a0 = *(const float4*)&As[kk][tr*8];
            float4 a1 = *(const float4*)&As[kk][tr*8 + 4];
            float4 b0 = *(const float4*)&Bs[kk][tc*8];
            float4 b1 = *(const float4*)&Bs[kk][tc*8 + 4];
            float a[8] = {a0.x,a0.y,a0.z,a0.w,a1.x,a1.y,a1.z,a1.w};
            float b[8] = {b0.x,b0.y,b0.z,b0.w,b1.x,b1.y,b1.z,b1.w};
#pragma unroll
            for (int i = 0; i < 8; i++)
#pragma unroll
                for (int j = 0; j < 8; j++)
                    acc[i][j] = fmaf(a[i], b[j], acc[i][j]);
        }
        __syncthreads();
    }

    const float* bp = bias + bcol*128 + tc*8;
    float bb2[8];
#pragma unroll
    for (int j = 0; j < 8; j++) bb2[j] = bp[j];

#pragma unroll
    for (int i = 0; i < 8; i++) {
        int row = brow*128 + tr*8 + i;
        float* crow = C + (size_t)row*N + bcol*128 + tc*8;
        float4 o0 = make_float4(acc[i][0]+bb2[0], acc[i][1]+bb2[1],
                                acc[i][2]+bb2[2], acc[i][3]+bb2[3]);
        float4 o1 = make_float4(acc[i][4]+bb2[4], acc[i][5]+bb2[5],
                                acc[i][6]+bb2[6], acc[i][7]+bb2[7]);
        *(float4*)(crow)     = o0;
        *(float4*)(crow + 4) = o1;
    }
#endif
}

// ---------------- causal flash attention (fp32, unchanged/verified) --------
__global__ __launch_bounds__(256) void attn_kernel()
{
    extern __shared__ float fsm[];
    float (*Qs)[64] = (float(*)[64])(fsm);
    float (*Ks)[64] = (float(*)[64])(fsm + 4096);
    float (*Vs)[64] = (float(*)[64])(fsm + 8192);
    float (*Ps)[65] = (float(*)[65])(fsm + 12288);

    const int tid = threadIdx.x;
    const int ty  = tid >> 4;
    const int tx  = tid & 15;
    const int bh  = blockIdx.y;
    const int b   = bh / HH, h = bh % HH;
    const int qt  = gridDim.x - 1 - blockIdx.x;
    const int q0  = qt * 64;

    const float* qb = g_qkv + (size_t)b*TT*QKV3 + h*HDIM;
    const float* kb = qb + DD;
    const float* vb = qb + 2*DD;

#pragma unroll
    for (int p = 0; p < 4; p++) {
        int v  = tid + 256 * p;
        int r  = v >> 4;
        int c4 = (v & 15) << 2;
        float4 q4 = *(const float4*)(qb + (size_t)(q0 + r)*QKV3 + c4);
        Qs[c4+0][r] = q4.x; Qs[c4+1][r] = q4.y;
        Qs[c4+2][r] = q4.z; Qs[c4+3][r] = q4.w;
    }

    float m[4], l[4], O[4][4];
#pragma unroll
    for (int i = 0; i < 4; i++) {
        m[i] = -INFINITY; l[i] = 0.f;
#pragma unroll
        for (int c = 0; c < 4; c++) O[i][c] = 0.f;
    }

    for (int kt = 0; kt <= qt; kt++) {
        const int k0 = kt * 64;
        __syncthreads();

#pragma unroll
        for (int p = 0; p < 4; p++) {
            int v  = tid + 256 * p;
            int r  = v >> 4;
            int c4 = (v & 15) << 2;
            float4 k4 = *(const float4*)(kb + (size_t)(k0 + r)*QKV3 + c4);
            Ks[c4+0][r] = k4.x; Ks[c4+1][r] = k4.y;
            Ks[c4+2][r] = k4.z; Ks[c4+3][r] = k4.w;
            float4 v4 = *(const float4*)(vb + (size_t)(k0 + r)*QKV3 + c4);
            *(float4*)&Vs[r][c4] = v4;
        }
        __syncthreads();

        float s[4][4];
#pragma unroll
        for (int i = 0; i < 4; i++)
#pragma unroll
            for (int j = 0; j < 4; j++) s[i][j] = 0.f;

#pragma unroll 8
        for (int d = 0; d < 64; d++) {
            float4 av = *(const float4*)&Qs[d][ty*4];
            float4 bv = *(const float4*)&Ks[d][tx*4];
            float a[4] = {av.x, av.y, av.z, av.w};
            float bvv[4] = {bv.x, bv.y, bv.z, bv.w};
#pragma unroll
            for (int i = 0; i < 4; i++)
#pragma unroll
                for (int j = 0; j < 4; j++)
                    s[i][j] = fmaf(a[i], bvv[j], s[i][j]);
        }

#pragma unroll
        for (int i = 0; i < 4; i++)
#pragma unroll
            for (int j = 0; j < 4; j++) s[i][j] *= ATT_SCALE;

        if (kt == qt) {
#pragma unroll
            for (int i = 0; i < 4; i++) {
                int qq = ty*4 + i;
#pragma unroll
                for (int j = 0; j < 4; j++)
                    if (tx*4 + j > qq) s[i][j] = -INFINITY;
            }
        }

#pragma unroll
        for (int i = 0; i < 4; i++) {
            float rm = fmaxf(fmaxf(s[i][0], s[i][1]), fmaxf(s[i][2], s[i][3]));
            rm = fmaxf(rm, __shfl_xor_sync(0xffffffffu, rm, 8, 16));
            rm = fmaxf(rm, __shfl_xor_sync(0xffffffffu, rm, 4, 16));
            rm = fmaxf(rm, __shfl_xor_sync(0xffffffffu, rm, 2, 16));
            rm = fmaxf(rm, __shfl_xor_sync(0xffffffffu, rm, 1, 16));
            float mn    = fmaxf(m[i], rm);
            float alpha = __expf(m[i] - mn);
            m[i] = mn;
            float rs = 0.f;
#pragma unroll
            for (int j = 0; j < 4; j++) {
                float pij = __expf(s[i][j] - mn);
                s[i][j] = pij;
                rs += pij;
            }
            rs += __shfl_xor_sync(0xffffffffu, rs, 8, 16);
            rs += __shfl_xor_sync(0xffffffffu, rs, 4, 16);
            rs += __shfl_xor_sync(0xffffffffu, rs, 2, 16);
            rs += __shfl_xor_sync(0xffffffffu, rs, 1, 16);
            l[i] = l[i]*alpha + rs;
#pragma unroll
            for (int c = 0; c < 4; c++) O[i][c] *= alpha;
        }

#pragma unroll
        for (int i = 0; i < 4; i++)
#pragma unroll
            for (int j = 0; j < 4; j++)
                Ps[ty*4 + i][tx*4 + j] = s[i][j];
        __syncthreads();

#pragma unroll 8
        for (int kk = 0; kk < 64; kk++) {
            float a0 = Ps[ty*4 + 0][kk];
            float a1 = Ps[ty*4 + 1][kk];
            float a2 = Ps[ty*4 + 2][kk];
            float a3 = Ps[ty*4 + 3][kk];
            float4 bv = *(const float4*)&Vs[kk][tx*4];
            O[0][0] = fmaf(a0, bv.x, O[0][0]); O[0][1] = fmaf(a0, bv.y, O[0][1]);
            O[0][2] = fmaf(a0, bv.z, O[0][2]); O[0][3] = fmaf(a0, bv.w, O[0][3]);
            O[1][0] = fmaf(a1, bv.x, O[1][0]); O[1][1] = fmaf(a1, bv.y, O[1][1]);
            O[1][2] = fmaf(a1, bv.z, O[1][2]); O[1][3] = fmaf(a1, bv.w, O[1][3]);
            O[2][0] = fmaf(a2, bv.x, O[2][0]); O[2][1] = fmaf(a2, bv.y, O[2][1]);
            O[2][2] = fmaf(a2, bv.z, O[2][2]); O[2][3] = fmaf(a2, bv.w, O[2][3]);
            O[3][0] = fmaf(a3, bv.x, O[3][0]); O[3][1] = fmaf(a3, bv.y, O[3][1]);
            O[3][2] = fmaf(a3, bv.z, O[3][2]); O[3][3] = fmaf(a3, bv.w, O[3][3]);
        }
    }

    float* ob = g_att + ((size_t)b*TT + q0)*DD + h*HDIM;
#pragma unroll
    for (int i = 0; i < 4; i++) {
        float inv = 1.f / l[i];
        float4 o = make_float4(O[i][0]*inv, O[i][1]*inv, O[i][2]*inv, O[i][3]*inv);
        *(float4*)(ob + (size_t)(ty*4 + i)*DD + tx*4) = o;
    }
}

// ---------------------------------------------------------------------------
extern "C" void kernel_launch(void* const* d_in, const int* in_sizes, int n_in,
                              void* d_out, int out_size)
{
    const float* x     = (const float*)d_in[0];
    const float* W_qkv = (const float*)d_in[1];
    const float* b_qkv = (const float*)d_in[2];
    const float* W_out = (const float*)d_in[3];
    const float* b_out = (const float*)d_in[4];
    float* out = (float*)d_out;

    void* p;
    cudaGetSymbolAddress(&p, g_qkv);   float* qkv = (float*)p;
    cudaGetSymbolAddress(&p, g_att);   float* att = (float*)p;
    cudaGetSymbolAddress(&p, g_xhi);   __nv_bfloat16* xhi = (__nv_bfloat16*)p;
    cudaGetSymbolAddress(&p, g_xlo);   __nv_bfloat16* xlo = (__nv_bfloat16*)p;
    cudaGetSymbolAddress(&p, g_ahi);   __nv_bfloat16* ahi = (__nv_bfloat16*)p;
    cudaGetSymbolAddress(&p, g_alo);   __nv_bfloat16* alo = (__nv_bfloat16*)p;
    cudaGetSymbolAddress(&p, g_wqt_hi); __nv_bfloat16* wqh = (__nv_bfloat16*)p;
    cudaGetSymbolAddress(&p, g_wqt_lo); __nv_bfloat16* wql = (__nv_bfloat16*)p;
    cudaGetSymbolAddress(&p, g_wot_hi); __nv_bfloat16* woh = (__nv_bfloat16*)p;
    cudaGetSymbolAddress(&p, g_wot_lo); __nv_bfloat16* wol = (__nv_bfloat16*)p;

    const int M = BB * TT;  // 8192

    // Prep: splits + weight transposes (cheap; harmless on fallback target too)
    {
        int n4 = M * DD / 4;
        split_hl<<<(n4 + 255) / 256, 256>>>(x, xhi, xlo, n4);
        tsplit_kernel<<<dim3(DD/32, QKV3/32), dim3(32, 8)>>>(W_qkv, wqh, wql, DD, QKV3);
        tsplit_kernel<<<dim3(DD/32, DD/32),   dim3(32, 8)>>>(W_out, woh, wol, DD, DD);
    }

    cudaFuncSetAttribute(gemm_any, cudaFuncAttributeMaxDynamicSharedMemorySize, GEMM_SMEM);

    // 1) QKV projection: [8192,768] @ [768,2304] + b
    gemm_any<<<dim3(QKV3/128, M/128), 256, GEMM_SMEM>>>(
        x, W_qkv, xhi, xlo, wqh, wql, b_qkv, qkv, M, QKV3, DD);

    // 2) Causal flash attention (fp32)
    const int asmem = (4096*3 + 64*65) * (int)sizeof(float);  // 65792 B
    cudaFuncSetAttribute(attn_kernel, cudaFuncAttributeMaxDynamicSharedMemorySize, asmem);
    attn_kernel<<<dim3(TT/64, BB*HH), 256, asmem>>>();

    // 3) split attention output, then output projection
    {
        int n4 = M * DD / 4;
        split_hl<<<(n4 + 255) / 256, 256>>>(att, ahi, alo, n4);
    }
    gemm_any<<<dim3(DD/128, M/128), 256, GEMM_SMEM>>>(
        att, W_out, ahi, alo, woh, wol, b_out, out, M, DD, DD);
}

// round 4
// speedup vs baseline: 4.6924x; 2.1803x over previous
#include <cuda_runtime.h>
#include <cuda_bf16.h>
#include <math.h>
#include <cstdint>

#define BB   2
#define TT   4096
#define DD   768
#define HH   12
#define HDIM 64
#define QKV3 (3*DD)       // 2304
#define ATT_SCALE 0.125f  // 1/sqrt(64)

// tcgen05 is arch-specific: gate on the 'a'/family feature macros; plain
// compute_103 PTX gets stub/SIMT fallbacks so ptxas succeeds on every target.
#if !defined(__CUDA_ARCH__)
#define HAS_TC 1
#elif defined(__CUDA_ARCH_FEAT_SM103_ALL)
#define HAS_TC 1
#elif defined(__CUDA_ARCH_SPECIFIC__) && (__CUDA_ARCH_SPECIFIC__ == 1030)
#define HAS_TC 1
#elif defined(__CUDA_ARCH_FAMILY_SPECIFIC__) && (__CUDA_ARCH_FAMILY_SPECIFIC__ >= 1000)
#define HAS_TC 1
#else
#define HAS_TC 0
#endif

// ---------------- scratch (device globals; allocation-free) ----------------
__device__ float         g_qkv [(size_t)BB*TT*QKV3];   // [B,T,3D] fp32
__device__ __nv_bfloat16 g_xhi [(size_t)BB*TT*DD];
__device__ __nv_bfloat16 g_xlo [(size_t)BB*TT*DD];
__device__ __nv_bfloat16 g_ahi [(size_t)BB*TT*DD];     // attention out hi
__device__ __nv_bfloat16 g_alo [(size_t)BB*TT*DD];     // attention out lo
__device__ __nv_bfloat16 g_wqt_hi[(size_t)QKV3*DD];
__device__ __nv_bfloat16 g_wqt_lo[(size_t)QKV3*DD];
__device__ __nv_bfloat16 g_wot_hi[(size_t)DD*DD];
__device__ __nv_bfloat16 g_wot_lo[(size_t)DD*DD];
// per-head split planes
__device__ __nv_bfloat16 g_qh [(size_t)BB*HH*TT*HDIM];  // [bh][t][d]
__device__ __nv_bfloat16 g_ql [(size_t)BB*HH*TT*HDIM];
__device__ __nv_bfloat16 g_kh [(size_t)BB*HH*TT*HDIM];
__device__ __nv_bfloat16 g_kl [(size_t)BB*HH*TT*HDIM];
__device__ __nv_bfloat16 g_vth[(size_t)BB*HH*HDIM*TT];  // [bh][d][t] (V^T)
__device__ __nv_bfloat16 g_vtl[(size_t)BB*HH*HDIM*TT];

// ---------------- helpers ---------------------------------------------------
__device__ __forceinline__ uint32_t smem_u32(const void* p) {
    uint32_t a;
    asm("{ .reg .u64 t; cvta.to.shared.u64 t, %1; cvt.u32.u64 %0, t; }"
        : "=r"(a) : "l"(p));
    return a;
}
#define SMEM_SWIZZLE_128B(off) ((off) ^ (((off) >> 3) & 0x70))

#if HAS_TC
__device__ __forceinline__ uint32_t elect_one() {
    uint32_t pred;
    asm volatile("{\n\t.reg .pred p;\n\telect.sync _|p, 0xFFFFFFFF;\n\t"
                 "selp.b32 %0, 1, 0, p;\n\t}" : "=r"(pred));
    return pred;
}
static constexpr uint64_t SMEM_DESC_BASE_SW128 =
    (uint64_t(2) << 61) | (uint64_t(1) << 46) | (uint64_t(64) << 32) | (uint64_t(1) << 16);
#define MAKE_SMEM_DESC(addr) (SMEM_DESC_BASE_SW128 | ((uint64_t)((addr) >> 4) & 0x3FFF))

#define TCGEN05_ALLOC(sa, n) \
    asm volatile("tcgen05.alloc.cta_group::1.sync.aligned.shared::cta.b32 [%0], %1;" \
                 :: "r"((uint32_t)(sa)), "r"((uint32_t)(n)) : "memory")
#define TCGEN05_DEALLOC(t, n) \
    asm volatile("tcgen05.dealloc.cta_group::1.sync.aligned.b32 %0, %1;" :: "r"(t), "r"(n))
#define TCGEN05_RELINQ() \
    asm volatile("tcgen05.relinquish_alloc_permit.cta_group::1.sync.aligned;")
#define TCGEN05_COMMIT(mb) \
    asm volatile("tcgen05.commit.cta_group::1.mbarrier::arrive::one.shared::cluster.b64 [%0];" \
                 :: "r"((uint32_t)(mb)) : "memory")
#define TCGEN05_FENCE_AFTER() \
    asm volatile("tcgen05.fence::after_thread_sync;" ::: "memory")
#define TCGEN05_WAIT_LD() \
    asm volatile("tcgen05.wait::ld.sync.aligned;" ::: "memory")
#define FENCE_PROXY_ASYNC() \
    asm volatile("fence.proxy.async.shared::cta;" ::: "memory")
#define MBARRIER_INIT(mb, cnt) \
    asm volatile("mbarrier.init.shared.b64 [%0], %1;" \
                 :: "r"((uint32_t)(mb)), "r"((uint32_t)(cnt)) : "memory")
#define MBARRIER_WAIT_PARITY(mb, ph) do {                                   \
    uint32_t _m = (uint32_t)(mb); uint32_t _p = (uint32_t)(ph);             \
    asm volatile("{\n\t.reg .pred P1;\n\t"                                  \
        "WL_%=:\n\t"                                                        \
        "mbarrier.try_wait.parity.acquire.cta.shared::cta.b64 P1, [%0], %1, 0x989680;\n\t" \
        "@P1 bra.uni WD_%=;\n\t"                                            \
        "bra.uni WL_%=;\n\t"                                                \
        "WD_%=:\n\t}" :: "r"(_m), "r"(_p) : "memory");                      \
} while (0)

__device__ __forceinline__ void mma_f16_ss_cg1(
    uint32_t d_tmem, uint64_t a_desc, uint64_t b_desc, uint32_t idesc, uint32_t en)
{
    asm volatile(
        "{\n\t.reg .pred p;\n\tsetp.ne.u32 p, %5, 0;\n\t"
        "tcgen05.mma.cta_group::1.kind::f16 [%0], %1, %2, %3, {%4, %4, %4, %4}, p;\n\t}"
        :: "r"(d_tmem), "l"(a_desc), "l"(b_desc), "r"(idesc), "r"(0u), "r"(en)
        : "memory");
}
#define LDTM_X32(r, addr)                                                    \
    asm volatile("tcgen05.ld.sync.aligned.32x32b.x32.b32 "                   \
        "{%0, %1, %2, %3, %4, %5, %6, %7, %8, %9, %10, %11, %12, %13, %14, %15, " \
        " %16, %17, %18, %19, %20, %21, %22, %23, %24, %25, %26, %27, %28, %29, %30, %31}, [%32];" \
        : "=r"((r)[0]),  "=r"((r)[1]),  "=r"((r)[2]),  "=r"((r)[3]),         \
          "=r"((r)[4]),  "=r"((r)[5]),  "=r"((r)[6]),  "=r"((r)[7]),         \
          "=r"((r)[8]),  "=r"((r)[9]),  "=r"((r)[10]), "=r"((r)[11]),        \
          "=r"((r)[12]), "=r"((r)[13]), "=r"((r)[14]), "=r"((r)[15]),        \
          "=r"((r)[16]), "=r"((r)[17]), "=r"((r)[18]), "=r"((r)[19]),        \
          "=r"((r)[20]), "=r"((r)[21]), "=r"((r)[22]), "=r"((r)[23]),        \
          "=r"((r)[24]), "=r"((r)[25]), "=r"((r)[26]), "=r"((r)[27]),        \
          "=r"((r)[28]), "=r"((r)[29]), "=r"((r)[30]), "=r"((r)[31])         \
        : "r"(addr))
#endif  // HAS_TC

// ---------------- prep kernels ---------------------------------------------
__global__ __launch_bounds__(256) void split_hl(
    const float* __restrict__ src, __nv_bfloat16* __restrict__ hi,
    __nv_bfloat16* __restrict__ lo, int n4)
{
    int i = blockIdx.x * 256 + threadIdx.x;
    if (i >= n4) return;
    float4 v = ((const float4*)src)[i];
    float vs[4] = {v.x, v.y, v.z, v.w};
    __nv_bfloat16 h[4], l[4];
#pragma unroll
    for (int j = 0; j < 4; j++) {
        h[j] = __float2bfloat16(vs[j]);
        l[j] = __float2bfloat16(vs[j] - __bfloat162float(h[j]));
    }
    ((__nv_bfloat162*)hi)[2*i]   = __halves2bfloat162(h[0], h[1]);
    ((__nv_bfloat162*)hi)[2*i+1] = __halves2bfloat162(h[2], h[3]);
    ((__nv_bfloat162*)lo)[2*i]   = __halves2bfloat162(l[0], l[1]);
    ((__nv_bfloat162*)lo)[2*i+1] = __halves2bfloat162(l[2], l[3]);
}

__global__ void tsplit_kernel(
    const float* __restrict__ W, __nv_bfloat16* __restrict__ Thi,
    __nv_bfloat16* __restrict__ Tlo, int K, int N)
{
    __shared__ float t[32][33];
    int kb = blockIdx.x * 32, nb = blockIdx.y * 32;
    int tx = threadIdx.x, ty = threadIdx.y;
#pragma unroll
    for (int i = 0; i < 4; i++) {
        int k = ty + i * 8;
        t[k][tx] = W[(size_t)(kb + k) * N + nb + tx];
    }
    __syncthreads();
#pragma unroll
    for (int i = 0; i < 4; i++) {
        int nr = ty + i * 8;
        float v = t[tx][nr];
        __nv_bfloat16 h = __float2bfloat16(v);
        __nv_bfloat16 l = __float2bfloat16(v - __bfloat162float(h));
        size_t o = (size_t)(nb + nr) * K + kb + tx;
        Thi[o] = h; Tlo[o] = l;
    }
}

// g_qkv -> per-head split planes (q, k natural; v transposed)
__global__ __launch_bounds__(256) void prep_split()
{
    const int bh = blockIdx.y;
    const int b = bh / HH, h = bh % HH;
    const int t0 = blockIdx.x * 64;
    const int tid = threadIdx.x;
    const float* base = g_qkv + (size_t)b*TT*QKV3 + h*HDIM;
    __shared__ float vs[64][65];

#pragma unroll
    for (int sel = 0; sel < 2; sel++) {
        const float* src = base + sel * DD;
        __nv_bfloat16* dh = (sel ? g_kh : g_qh) + (size_t)bh*TT*HDIM;
        __nv_bfloat16* dl = (sel ? g_kl : g_ql) + (size_t)bh*TT*HDIM;
#pragma unroll
        for (int p = 0; p < 4; p++) {
            int i = tid + p*256; int r = i >> 4; int c4 = (i & 15) << 2;
            float4 v = *(const float4*)(src + (size_t)(t0 + r)*QKV3 + c4);
            float e[4] = {v.x, v.y, v.z, v.w};
            __nv_bfloat16 hh[4], ll[4];
#pragma unroll
            for (int j = 0; j < 4; j++) {
                hh[j] = __float2bfloat16(e[j]);
                ll[j] = __float2bfloat16(e[j] - __bfloat162float(hh[j]));
            }
            __nv_bfloat162 h01 = __halves2bfloat162(hh[0], hh[1]);
            __nv_bfloat162 h23 = __halves2bfloat162(hh[2], hh[3]);
            __nv_bfloat162 l01 = __halves2bfloat162(ll[0], ll[1]);
            __nv_bfloat162 l23 = __halves2bfloat162(ll[2], ll[3]);
            uint2 hv = make_uint2(*(uint32_t*)&h01, *(uint32_t*)&h23);
            uint2 lv = make_uint2(*(uint32_t*)&l01, *(uint32_t*)&l23);
            *(uint2*)((char*)dh + ((size_t)(t0 + r)*HDIM + c4)*2) = hv;
            *(uint2*)((char*)dl + ((size_t)(t0 + r)*HDIM + c4)*2) = lv;
        }
    }
    // V: load 64x64, transpose, split
#pragma unroll
    for (int p = 0; p < 4; p++) {
        int i = tid + p*256; int r = i >> 4; int c4 = (i & 15) << 2;
        float4 v = *(const float4*)(base + 2*DD + (size_t)(t0 + r)*QKV3 + c4);
        vs[r][c4] = v.x; vs[r][c4+1] = v.y; vs[r][c4+2] = v.z; vs[r][c4+3] = v.w;
    }
    __syncthreads();
    {
        int d = tid >> 2;               // 0..63
        int tq = (tid & 3) << 4;        // 0,16,32,48
        uint32_t hp[8], lp[8];
#pragma unroll
        for (int j2 = 0; j2 < 8; j2++) {
            float e0 = vs[tq + 2*j2][d];
            float e1 = vs[tq + 2*j2 + 1][d];
            __nv_bfloat16 h0 = __float2bfloat16(e0), h1 = __float2bfloat16(e1);
            __nv_bfloat16 l0 = __float2bfloat16(e0 - __bfloat162float(h0));
            __nv_bfloat16 l1 = __float2bfloat16(e1 - __bfloat162float(h1));
            __nv_bfloat162 hh = __halves2bfloat162(h0, h1);
            __nv_bfloat162 ll = __halves2bfloat162(l0, l1);
            hp[j2] = *(uint32_t*)&hh; lp[j2] = *(uint32_t*)&ll;
        }
        size_t oo = ((size_t)bh*HDIM*TT + (size_t)d*TT + t0 + tq) * 2;
#pragma unroll
        for (int k4 = 0; k4 < 2; k4++) {
            *(uint4*)((char*)g_vth + oo + k4*16) = ((uint4*)hp)[k4];
            *(uint4*)((char*)g_vtl + oo + k4*16) = ((uint4*)lp)[k4];
        }
    }
}

// ---------------- tcgen05 GEMM (verified round 3) ---------------------------
#define SM_A   1024
#define SM_AL  (SM_A  + 16384)
#define SM_B   (SM_AL + 16384)
#define SM_BL  (SM_B  + 16384)
#define GEMM_SMEM (SM_BL + 16384)
#define GEMM_IDESC 0x8200490u

#if HAS_TC
__device__ __forceinline__ void load_tile64(
    char* smem, int dst, const __nv_bfloat16* __restrict__ g,
    int ld, int row0, int k0, int tid)
{
    const char* base = (const char*)g;
#pragma unroll
    for (int p = 0; p < 4; p++) {
        int i = tid + p * 256;
        int r = i >> 3;
        int c16 = (i & 7) << 4;
        uint4 v = *(const uint4*)(base + ((size_t)(row0 + r) * ld + k0) * 2 + c16);
        *(uint4*)(smem + dst + SMEM_SWIZZLE_128B(r * 128 + c16)) = v;
    }
}
#endif

__global__ __launch_bounds__(256) void gemm_any(
    const float* __restrict__ A, const float* __restrict__ W,
    const __nv_bfloat16* __restrict__ Ahi, const __nv_bfloat16* __restrict__ Alo,
    const __nv_bfloat16* __restrict__ Bthi, const __nv_bfloat16* __restrict__ Btlo,
    const float* __restrict__ bias, float* __restrict__ C,
    int M, int N, int K)
{
    extern __shared__ char smem[];
#if HAS_TC
    const uint32_t sb = smem_u32(smem);
    const int tid = threadIdx.x;
    const int wid = tid >> 5, lid = tid & 31;
    const int m0 = blockIdx.y * 128, n0 = blockIdx.x * 128;

    if (wid == 0) { TCGEN05_ALLOC(sb, 128); TCGEN05_RELINQ(); }
    if (tid == 0) MBARRIER_INIT(sb + 8, 1);
    __syncthreads();
    uint32_t tmem;
    asm volatile("ld.shared.b32 %0, [%1];" : "=r"(tmem) : "r"(sb));

    const uint64_t dAh = MAKE_SMEM_DESC(sb + SM_A);
    const uint64_t dAl = MAKE_SMEM_DESC(sb + SM_AL);
    const uint64_t dBh = MAKE_SMEM_DESC(sb + SM_B);
    const uint64_t dBl = MAKE_SMEM_DESC(sb + SM_BL);

    const int nchunks = K >> 6;
    for (int c = 0; c < nchunks; c++) {
        const int k0 = c << 6;
        load_tile64(smem, SM_A,  Ahi,  K, m0, k0, tid);
        load_tile64(smem, SM_AL, Alo,  K, m0, k0, tid);
        load_tile64(smem, SM_B,  Bthi, K, n0, k0, tid);
        load_tile64(smem, SM_BL, Btlo, K, n0, k0, tid);
        FENCE_PROXY_ASYNC();
        __syncthreads();

        if (wid == 0 && elect_one()) {
#pragma unroll
            for (int ks = 0; ks < 4; ks++) {
                uint32_t en0 = (c > 0 || ks > 0) ? 1u : 0u;
                mma_f16_ss_cg1(tmem, dAh + ks*2, dBh + ks*2, GEMM_IDESC, en0);
                mma_f16_ss_cg1(tmem, dAh + ks*2, dBl + ks*2, GEMM_IDESC, 1u);
                mma_f16_ss_cg1(tmem, dAl + ks*2, dBh + ks*2, GEMM_IDESC, 1u);
            }
            TCGEN05_COMMIT(sb + 8);
        }
        MBARRIER_WAIT_PARITY(sb + 8, c & 1);
    }

    TCGEN05_FENCE_AFTER();
    if (wid < 4) {
        const int row = m0 + wid * 32 + lid;
#pragma unroll
        for (int base = 0; base < 128; base += 32) {
            uint32_t r[32];
            LDTM_X32(r, tmem + base);
            TCGEN05_WAIT_LD();
            float* crow = C + (size_t)row * N + n0 + base;
            const float* bp = bias + n0 + base;
#pragma unroll
            for (int j = 0; j < 32; j += 4) {
                float4 o = make_float4(__uint_as_float(r[j])   + bp[j],
                                       __uint_as_float(r[j+1]) + bp[j+1],
                                       __uint_as_float(r[j+2]) + bp[j+2],
                                       __uint_as_float(r[j+3]) + bp[j+3]);
                *(float4*)(crow + j) = o;
            }
        }
    }
    __syncthreads();
    if (wid == 0) TCGEN05_DEALLOC(tmem, 128);

#else  // SIMT fp32 fallback (never executes on sm_103a SASS)
    float (*As)[128] = (float(*)[128])(smem);
    float (*Bs)[128] = (float(*)[128])(smem + 8192);
    const int tid  = threadIdx.x;
    const int brow = blockIdx.y, bcol = blockIdx.x;
    const int tr = tid >> 4, tc = tid & 15;
    float acc[8][8];
#pragma unroll
    for (int i = 0; i < 8; i++)
#pragma unroll
        for (int j = 0; j < 8; j++) acc[i][j] = 0.f;
    for (int k0 = 0; k0 < K; k0 += 16) {
#pragma unroll
        for (int p = 0; p < 2; p++) {
            int v  = tid + 256 * p;
            int ra = v >> 2, ca = (v & 3) << 2;
            float4 a4 = *(const float4*)(A + (size_t)(brow*128 + ra)*K + k0 + ca);
            As[ca+0][ra] = a4.x; As[ca+1][ra] = a4.y;
            As[ca+2][ra] = a4.z; As[ca+3][ra] = a4.w;
            int rb = v >> 5, cb = (v & 31) << 2;
            float4 b4 = *(const float4*)(W + (size_t)(k0 + rb)*N + bcol*128 + cb);
            *(float4*)&Bs[rb][cb] = b4;
        }
        __syncthreads();
#pragma unroll
        for (int kk = 0; kk < 16; kk++) {
            float4 a0 = *(const float4*)&As[kk][tr*8];
            float4 a1 = *(const float4*)&As[kk][tr*8 + 4];
            float4 b0 = *(const float4*)&Bs[kk][tc*8];
            float4 b1 = *(const float4*)&Bs[kk][tc*8 + 4];
            float a[8] = {a0.x,a0.y,a0.z,a0.w,a1.x,a1.y,a1.z,a1.w};
            float b[8] = {b0.x,b0.y,b0.z,b0.w,b1.x,b1.y,b1.z,b1.w};
#pragma unroll
            for (int i = 0; i < 8; i++)
#pragma unroll
                for (int j = 0; j < 8; j++)
                    acc[i][j] = fmaf(a[i], b[j], acc[i][j]);
        }
        __syncthreads();
    }
    const float* bp = bias + bcol*128 + tc*8;
#pragma unroll
    for (int i = 0; i < 8; i++) {
        int row = brow*128 + tr*8 + i;
        float* crow = C + (size_t)row*N + bcol*128 + tc*8;
#pragma unroll
        for (int j = 0; j < 8; j++) crow[j] = acc[i][j] + bp[j];
    }
#endif
}

// ---------------- tcgen05 flash attention -----------------------------------
#define ASM_TPTR 0
#define ASM_MBAR 8
#define ASM_QH   1024
#define ASM_QL   (ASM_QH + 16384)
#define ASM_KH   (ASM_QL + 16384)
#define ASM_KL   (ASM_KH + 16384)
#define ASM_VH   (ASM_KL + 16384)
#define ASM_VL   (ASM_VH + 16384)
#define ASM_PH   (ASM_VL + 16384)
#define ASM_PL   (ASM_PH + 32768)
#define ASM_LP   (ASM_PL + 32768)
#define ATT_SMEM (ASM_LP + 1024)
#define IDESC_S  0x8200490u   // M=128 N=128 bf16->f32
#define IDESC_PV 0x8100490u   // M=128 N=64

__global__ __launch_bounds__(256) void attn_tc()
{
#if HAS_TC
    extern __shared__ char smem[];
    const uint32_t sb = smem_u32(smem);
    const int tid = threadIdx.x;
    const int w = tid >> 5, lid = tid & 31;
    const int bh = blockIdx.y;
    const int qt = gridDim.x - 1 - blockIdx.x;   // big tiles first
    const int q0 = qt * 128;
    const int r  = (w & 3) * 32 + lid;           // owned S/O row
    const int ch = w >> 2;                       // column half

    const char* qh = (const char*)(g_qh + (size_t)bh*TT*HDIM);
    const char* ql = (const char*)(g_ql + (size_t)bh*TT*HDIM);
    const char* kh = (const char*)(g_kh + (size_t)bh*TT*HDIM);
    const char* kl = (const char*)(g_kl + (size_t)bh*TT*HDIM);
    const char* vh = (const char*)(g_vth + (size_t)bh*HDIM*TT);
    const char* vl = (const char*)(g_vtl + (size_t)bh*HDIM*TT);

    if (w == 0) { TCGEN05_ALLOC(sb + ASM_TPTR, 256); TCGEN05_RELINQ(); }
    if (tid == 0) MBARRIER_INIT(sb + ASM_MBAR, 1);

    // Q tile (SW128 K-major, 128 rows x 128B)
#pragma unroll
    for (int p = 0; p < 4; p++) {
        int i = tid + p*256; int rr = i >> 3; int c16 = (i & 7) << 4;
        uint32_t so = SMEM_SWIZZLE_128B(rr*128 + c16);
        *(uint4*)(smem + ASM_QH + so) = *(const uint4*)(qh + (size_t)(q0+rr)*128 + c16);
        *(uint4*)(smem + ASM_QL + so) = *(const uint4*)(ql + (size_t)(q0+rr)*128 + c16);
    }
    __syncthreads();
    uint32_t tmem;
    asm volatile("ld.shared.b32 %0, [%1];" : "=r"(tmem) : "r"(sb + ASM_TPTR));

    const uint64_t dQh = MAKE_SMEM_DESC(sb+ASM_QH), dQl = MAKE_SMEM_DESC(sb+ASM_QL);
    const uint64_t dKh = MAKE_SMEM_DESC(sb+ASM_KH), dKl = MAKE_SMEM_DESC(sb+ASM_KL);
    const uint64_t dVh = MAKE_SMEM_DESC(sb+ASM_VH), dVl = MAKE_SMEM_DESC(sb+ASM_VL);
    const uint64_t dPh = MAKE_SMEM_DESC(sb+ASM_PH), dPl = MAKE_SMEM_DESC(sb+ASM_PL);

    float lsum = 0.f;
    int pc = 0;
    const uint32_t prow = (uint32_t)((((r>>3) + ch*16) << 10) + ((r & 7) << 7));

    for (int kt = 0; kt <= qt; kt++) {
        const int k0 = kt * 128;
        if (kt > 0) { MBARRIER_WAIT_PARITY(sb+ASM_MBAR, pc & 1); pc++; }  // PV(kt-1)

        // K tile (same layout as Q)
#pragma unroll
        for (int p = 0; p < 4; p++) {
            int i = tid + p*256; int rr = i >> 3; int c16 = (i & 7) << 4;
            uint32_t so = SMEM_SWIZZLE_128B(rr*128 + c16);
            *(uint4*)(smem + ASM_KH + so) = *(const uint4*)(kh + (size_t)(k0+rr)*128 + c16);
            *(uint4*)(smem + ASM_KL + so) = *(const uint4*)(kl + (size_t)(k0+rr)*128 + c16);
        }
        // Vt tile: 64 rows(d) x 128 cols(kk) bf16, blocked atoms (2 cols x 8 rows)
#pragma unroll
        for (int p = 0; p < 4; p++) {
            int i = tid + p*256; int d = i >> 4; int j = i & 15;
            size_t go = ((size_t)d*TT + k0 + j*8) * 2;
            uint32_t bo = (uint32_t)(((((d>>3) + (j>>3)*8)) << 10) + ((d & 7) << 7) + ((j & 7) << 4));
            uint32_t so = SMEM_SWIZZLE_128B(bo);
            *(uint4*)(smem + ASM_VH + so) = *(const uint4*)(vh + go);
            *(uint4*)(smem + ASM_VL + so) = *(const uint4*)(vl + go);
        }
        FENCE_PROXY_ASYNC();
        __syncthreads();

        if (w == 0 && elect_one()) {
#pragma unroll
            for (int ks = 0; ks < 4; ks++) {
                mma_f16_ss_cg1(tmem, dQh + ks*2, dKh + ks*2, IDESC_S, ks > 0);
                mma_f16_ss_cg1(tmem, dQh + ks*2, dKl + ks*2, IDESC_S, 1u);
                mma_f16_ss_cg1(tmem, dQl + ks*2, dKh + ks*2, IDESC_S, 1u);
            }
            TCGEN05_COMMIT(sb + ASM_MBAR);
        }
        MBARRIER_WAIT_PARITY(sb+ASM_MBAR, pc & 1); pc++;
        TCGEN05_FENCE_AFTER();

        // softmax epilogue: exp, split to bf16 hi/lo, stage P
        const bool diag = (kt == qt);
#pragma unroll
        for (int cb = 0; cb < 64; cb += 32) {
            uint32_t sreg[32];
            LDTM_X32(sreg, tmem + ch*64 + cb);
            TCGEN05_WAIT_LD();
            uint32_t hp[16], lp[16];
#pragma unroll
            for (int j2 = 0; j2 < 16; j2++) {
                float e0 = __expf(__uint_as_float(sreg[2*j2])   * ATT_SCALE);
                float e1 = __expf(__uint_as_float(sreg[2*j2+1]) * ATT_SCALE);
                if (diag) {
                    int c = ch*64 + cb + 2*j2;
                    if (c     > r) e0 = 0.f;
                    if (c + 1 > r) e1 = 0.f;
                }
                lsum += e0 + e1;
                __nv_bfloat16 h0 = __float2bfloat16(e0), h1 = __float2bfloat16(e1);
                __nv_bfloat16 l0 = __float2bfloat16(e0 - __bfloat162float(h0));
                __nv_bfloat16 l1 = __float2bfloat16(e1 - __bfloat162float(h1));
                __nv_bfloat162 hh = __halves2bfloat162(h0, h1);
                __nv_bfloat162 ll = __halves2bfloat162(l0, l1);
                hp[j2] = *(uint32_t*)&hh; lp[j2] = *(uint32_t*)&ll;
            }
#pragma unroll
            for (int k4 = 0; k4 < 4; k4++) {
                uint32_t so = SMEM_SWIZZLE_128B(prow + cb*2 + k4*16);
                *(uint4*)(smem + ASM_PH + so) = ((uint4*)hp)[k4];
                *(uint4*)(smem + ASM_PL + so) = ((uint4*)lp)[k4];
            }
        }
        FENCE_PROXY_ASYNC();
        __syncthreads();

        if (w == 0 && elect_one()) {
#pragma unroll
            for (int ks = 0; ks < 8; ks++) {
                uint32_t po = (ks < 4) ? ks*2 : 1024 + (ks-4)*2;
                uint32_t vo = (ks < 4) ? ks*2 : 512  + (ks-4)*2;
                uint32_t en0 = (kt > 0 || ks > 0) ? 1u : 0u;
                mma_f16_ss_cg1(tmem + 128, dPh + po, dVh + vo, IDESC_PV, en0);
                mma_f16_ss_cg1(tmem + 128, dPh + po, dVl + vo, IDESC_PV, 1u);
                mma_f16_ss_cg1(tmem + 128, dPl + po, dVh + vo, IDESC_PV, 1u);
            }
            TCGEN05_COMMIT(sb + ASM_MBAR);
        }
    }
    MBARRIER_WAIT_PARITY(sb+ASM_MBAR, pc & 1); pc++;
    TCGEN05_FENCE_AFTER();

    // O epilogue: normalize by row sum, write split bf16 directly
    *(float*)(smem + ASM_LP + (ch*128 + r)*4) = lsum;
    __syncthreads();
    {
        uint32_t oreg[32];
        LDTM_X32(oreg, tmem + 128 + ch*32);
        TCGEN05_WAIT_LD();
        float lt = *(float*)(smem + ASM_LP + r*4)
                 + *(float*)(smem + ASM_LP + (128 + r)*4);
        float inv = 1.f / lt;
        const int b2 = bh / HH, h2 = bh % HH;
        size_t oo = ((size_t)(b2*TT + q0 + r)*DD + h2*HDIM + ch*32) * 2;
        uint32_t hp[16], lp[16];
#pragma unroll
        for (int j2 = 0; j2 < 16; j2++) {
            float e0 = __uint_as_float(oreg[2*j2])   * inv;
            float e1 = __uint_as_float(oreg[2*j2+1]) * inv;
            __nv_bfloat16 h0 = __float2bfloat16(e0), h1 = __float2bfloat16(e1);
            __nv_bfloat16 l0 = __float2bfloat16(e0 - __bfloat162float(h0));
            __nv_bfloat16 l1 = __float2bfloat16(e1 - __bfloat162float(h1));
            __nv_bfloat162 hh = __halves2bfloat162(h0, h1);
            __nv_bfloat162 ll = __halves2bfloat162(l0, l1);
            hp[j2] = *(uint32_t*)&hh; lp[j2] = *(uint32_t*)&ll;
        }
#pragma unroll
        for (int k4 = 0; k4 < 4; k4++) {
            *(uint4*)((char*)g_ahi + oo + k4*16) = ((uint4*)hp)[k4];
            *(uint4*)((char*)g_alo + oo + k4*16) = ((uint4*)lp)[k4];
        }
    }
    __syncthreads();
    if (w == 0) TCGEN05_DEALLOC(tmem, 256);
#endif
}

// ---------------------------------------------------------------------------
extern "C" void kernel_launch(void* const* d_in, const int* in_sizes, int n_in,
                              void* d_out, int out_size)
{
    const float* x     = (const float*)d_in[0];
    const float* W_qkv = (const float*)d_in[1];
    const float* b_qkv = (const float*)d_in[2];
    const float* W_out = (const float*)d_in[3];
    const float* b_out = (const float*)d_in[4];
    float* out = (float*)d_out;

    void* p;
    cudaGetSymbolAddress(&p, g_qkv);    float* qkv = (float*)p;
    cudaGetSymbolAddress(&p, g_xhi);    __nv_bfloat16* xhi = (__nv_bfloat16*)p;
    cudaGetSymbolAddress(&p, g_xlo);    __nv_bfloat16* xlo = (__nv_bfloat16*)p;
    cudaGetSymbolAddress(&p, g_ahi);    __nv_bfloat16* ahi = (__nv_bfloat16*)p;
    cudaGetSymbolAddress(&p, g_alo);    __nv_bfloat16* alo = (__nv_bfloat16*)p;
    cudaGetSymbolAddress(&p, g_wqt_hi); __nv_bfloat16* wqh = (__nv_bfloat16*)p;
    cudaGetSymbolAddress(&p, g_wqt_lo); __nv_bfloat16* wql = (__nv_bfloat16*)p;
    cudaGetSymbolAddress(&p, g_wot_hi); __nv_bfloat16* woh = (__nv_bfloat16*)p;
    cudaGetSymbolAddress(&p, g_wot_lo); __nv_bfloat16* wol = (__nv_bfloat16*)p;

    const int M = BB * TT;  // 8192

    // Prep: input split + weight transposes
    {
        int n4 = M * DD / 4;
        split_hl<<<(n4 + 255) / 256, 256>>>(x, xhi, xlo, n4);
        tsplit_kernel<<<dim3(DD/32, QKV3/32), dim3(32, 8)>>>(W_qkv, wqh, wql, DD, QKV3);
        tsplit_kernel<<<dim3(DD/32, DD/32),   dim3(32, 8)>>>(W_out, woh, wol, DD, DD);
    }

    cudaFuncSetAttribute(gemm_any, cudaFuncAttributeMaxDynamicSharedMemorySize, GEMM_SMEM);

    // 1) QKV projection
    gemm_any<<<dim3(QKV3/128, M/128), 256, GEMM_SMEM>>>(
        x, W_qkv, xhi, xlo, wqh, wql, b_qkv, qkv, M, QKV3, DD);

    // 2) per-head split planes (q, k, v^T)
    prep_split<<<dim3(TT/64, BB*HH), 256>>>();

    // 3) tcgen05 causal flash attention -> g_ahi/g_alo
    cudaFuncSetAttribute(attn_tc, cudaFuncAttributeMaxDynamicSharedMemorySize, ATT_SMEM);
    attn_tc<<<dim3(TT/128, BB*HH), 256, ATT_SMEM>>>();

    // 4) output projection
    gemm_any<<<dim3(DD/128, M/128), 256, GEMM_SMEM>>>(
        nullptr, nullptr, ahi, alo, woh, wol, b_out, out, M, DD, DD);
}

// round 5
// speedup vs baseline: 10.6571x; 2.2711x over previous
#include <cuda_runtime.h>
#include <cuda_bf16.h>
#include <cuda_fp16.h>
#include <math.h>
#include <cstdint>

#define BB   2
#define TT   4096
#define DD   768
#define HH   12
#define HDIM 64
#define QKV3 (3*DD)       // 2304
#define ATT_SCALE 0.125f  // 1/sqrt(64)

// tcgen05 is arch-specific: gate on the 'a'/family feature macros; plain
// compute_103 PTX gets stub/SIMT fallbacks so ptxas succeeds on every target.
#if !defined(__CUDA_ARCH__)
#define HAS_TC 1
#elif defined(__CUDA_ARCH_FEAT_SM103_ALL)
#define HAS_TC 1
#elif defined(__CUDA_ARCH_SPECIFIC__) && (__CUDA_ARCH_SPECIFIC__ == 1030)
#define HAS_TC 1
#elif defined(__CUDA_ARCH_FAMILY_SPECIFIC__) && (__CUDA_ARCH_FAMILY_SPECIFIC__ >= 1000)
#define HAS_TC 1
#else
#define HAS_TC 0
#endif

// ---------------- scratch (device globals; allocation-free) ----------------
__device__ float         g_qkv [(size_t)BB*TT*QKV3];   // [B,T,3D] fp32
__device__ __nv_bfloat16 g_xhi [(size_t)BB*TT*DD];
__device__ __nv_bfloat16 g_xlo [(size_t)BB*TT*DD];
__device__ __nv_bfloat16 g_ahi [(size_t)BB*TT*DD];     // attention out hi
__device__ __nv_bfloat16 g_alo [(size_t)BB*TT*DD];     // attention out lo
__device__ __nv_bfloat16 g_wqt_hi[(size_t)QKV3*DD];
__device__ __nv_bfloat16 g_wqt_lo[(size_t)QKV3*DD];
__device__ __nv_bfloat16 g_wot_hi[(size_t)DD*DD];
__device__ __nv_bfloat16 g_wot_lo[(size_t)DD*DD];
// per-head planes
__device__ __nv_bfloat16 g_qh [(size_t)BB*HH*TT*HDIM];  // [bh][t][d]
__device__ __nv_bfloat16 g_ql [(size_t)BB*HH*TT*HDIM];
__device__ __nv_bfloat16 g_kh [(size_t)BB*HH*TT*HDIM];
__device__ __nv_bfloat16 g_kl [(size_t)BB*HH*TT*HDIM];
__device__ __half        g_vt [(size_t)BB*HH*HDIM*TT];  // [bh][d][t] (V^T, fp16)

// ---------------- helpers ---------------------------------------------------
__device__ __forceinline__ uint32_t smem_u32(const void* p) {
    uint32_t a;
    asm("{ .reg .u64 t; cvta.to.shared.u64 t, %1; cvt.u32.u64 %0, t; }"
        : "=r"(a) : "l"(p));
    return a;
}
#define SMEM_SWIZZLE_128B(off) ((off) ^ (((off) >> 3) & 0x70))

#if HAS_TC
__device__ __forceinline__ uint32_t elect_one() {
    uint32_t pred;
    asm volatile("{\n\t.reg .pred p;\n\telect.sync _|p, 0xFFFFFFFF;\n\t"
                 "selp.b32 %0, 1, 0, p;\n\t}" : "=r"(pred));
    return pred;
}
static constexpr uint64_t SMEM_DESC_BASE_SW128 =
    (uint64_t(2) << 61) | (uint64_t(1) << 46) | (uint64_t(64) << 32) | (uint64_t(1) << 16);
#define MAKE_SMEM_DESC(addr) (SMEM_DESC_BASE_SW128 | ((uint64_t)((addr) >> 4) & 0x3FFF))

#define TCGEN05_ALLOC(sa, n) \
    asm volatile("tcgen05.alloc.cta_group::1.sync.aligned.shared::cta.b32 [%0], %1;" \
                 :: "r"((uint32_t)(sa)), "r"((uint32_t)(n)) : "memory")
#define TCGEN05_DEALLOC(t, n) \
    asm volatile("tcgen05.dealloc.cta_group::1.sync.aligned.b32 %0, %1;" :: "r"(t), "r"(n))
#define TCGEN05_RELINQ() \
    asm volatile("tcgen05.relinquish_alloc_permit.cta_group::1.sync.aligned;")
#define TCGEN05_COMMIT(mb) \
    asm volatile("tcgen05.commit.cta_group::1.mbarrier::arrive::one.shared::cluster.b64 [%0];" \
                 :: "r"((uint32_t)(mb)) : "memory")
#define TCGEN05_FENCE_AFTER() \
    asm volatile("tcgen05.fence::after_thread_sync;" ::: "memory")
#define TCGEN05_FENCE_BEFORE() \
    asm volatile("tcgen05.fence::before_thread_sync;" ::: "memory")
#define TCGEN05_WAIT_LD() \
    asm volatile("tcgen05.wait::ld.sync.aligned;" ::: "memory")
#define FENCE_PROXY_ASYNC() \
    asm volatile("fence.proxy.async.shared::cta;" ::: "memory")
#define MBARRIER_INIT(mb, cnt) \
    asm volatile("mbarrier.init.shared.b64 [%0], %1;" \
                 :: "r"((uint32_t)(mb)), "r"((uint32_t)(cnt)) : "memory")
#define MBARRIER_WAIT_PARITY(mb, ph) do {                                   \
    uint32_t _m = (uint32_t)(mb); uint32_t _p = (uint32_t)(ph);             \
    asm volatile("{\n\t.reg .pred P1;\n\t"                                  \
        "WL_%=:\n\t"                                                        \
        "mbarrier.try_wait.parity.acquire.cta.shared::cta.b64 P1, [%0], %1, 0x989680;\n\t" \
        "@P1 bra.uni WD_%=;\n\t"                                            \
        "bra.uni WL_%=;\n\t"                                                \
        "WD_%=:\n\t}" :: "r"(_m), "r"(_p) : "memory");                      \
} while (0)
#define CP_ASYNC16(dst, src) \
    asm volatile("cp.async.cg.shared.global [%0], [%1], 16;" \
                 :: "r"((uint32_t)(dst)), "l"(src) : "memory")
#define CP_COMMIT() asm volatile("cp.async.commit_group;" ::: "memory")
#define CP_WAIT0()  asm volatile("cp.async.wait_group 0;" ::: "memory")

__device__ __forceinline__ void mma_f16_ss_cg1(
    uint32_t d_tmem, uint64_t a_desc, uint64_t b_desc, uint32_t idesc, uint32_t en)
{
    asm volatile(
        "{\n\t.reg .pred p;\n\tsetp.ne.u32 p, %5, 0;\n\t"
        "tcgen05.mma.cta_group::1.kind::f16 [%0], %1, %2, %3, {%4, %4, %4, %4}, p;\n\t}"
        :: "r"(d_tmem), "l"(a_desc), "l"(b_desc), "r"(idesc), "r"(0u), "r"(en)
        : "memory");
}
#define LDTM_X32(r, addr)                                                    \
    asm volatile("tcgen05.ld.sync.aligned.32x32b.x32.b32 "                   \
        "{%0, %1, %2, %3, %4, %5, %6, %7, %8, %9, %10, %11, %12, %13, %14, %15, " \
        " %16, %17, %18, %19, %20, %21, %22, %23, %24, %25, %26, %27, %28, %29, %30, %31}, [%32];" \
        : "=r"((r)[0]),  "=r"((r)[1]),  "=r"((r)[2]),  "=r"((r)[3]),         \
          "=r"((r)[4]),  "=r"((r)[5]),  "=r"((r)[6]),  "=r"((r)[7]),         \
          "=r"((r)[8]),  "=r"((r)[9]),  "=r"((r)[10]), "=r"((r)[11]),        \
          "=r"((r)[12]), "=r"((r)[13]), "=r"((r)[14]), "=r"((r)[15]),        \
          "=r"((r)[16]), "=r"((r)[17]), "=r"((r)[18]), "=r"((r)[19]),        \
          "=r"((r)[20]), "=r"((r)[21]), "=r"((r)[22]), "=r"((r)[23]),        \
          "=r"((r)[24]), "=r"((r)[25]), "=r"((r)[26]), "=r"((r)[27]),        \
          "=r"((r)[28]), "=r"((r)[29]), "=r"((r)[30]), "=r"((r)[31])         \
        : "r"(addr))
#endif  // HAS_TC

// ---------------- prep kernels ---------------------------------------------
__global__ __launch_bounds__(256) void split_hl(
    const float* __restrict__ src, __nv_bfloat16* __restrict__ hi,
    __nv_bfloat16* __restrict__ lo, int n4)
{
    int i = blockIdx.x * 256 + threadIdx.x;
    if (i >= n4) return;
    float4 v = ((const float4*)src)[i];
    float vs[4] = {v.x, v.y, v.z, v.w};
    __nv_bfloat16 h[4], l[4];
#pragma unroll
    for (int j = 0; j < 4; j++) {
        h[j] = __float2bfloat16(vs[j]);
        l[j] = __float2bfloat16(vs[j] - __bfloat162float(h[j]));
    }
    ((__nv_bfloat162*)hi)[2*i]   = __halves2bfloat162(h[0], h[1]);
    ((__nv_bfloat162*)hi)[2*i+1] = __halves2bfloat162(h[2], h[3]);
    ((__nv_bfloat162*)lo)[2*i]   = __halves2bfloat162(l[0], l[1]);
    ((__nv_bfloat162*)lo)[2*i+1] = __halves2bfloat162(l[2], l[3]);
}

__global__ void tsplit_kernel(
    const float* __restrict__ W, __nv_bfloat16* __restrict__ Thi,
    __nv_bfloat16* __restrict__ Tlo, int K, int N)
{
    __shared__ float t[32][33];
    int kb = blockIdx.x * 32, nb = blockIdx.y * 32;
    int tx = threadIdx.x, ty = threadIdx.y;
#pragma unroll
    for (int i = 0; i < 4; i++) {
        int k = ty + i * 8;
        t[k][tx] = W[(size_t)(kb + k) * N + nb + tx];
    }
    __syncthreads();
#pragma unroll
    for (int i = 0; i < 4; i++) {
        int nr = ty + i * 8;
        float v = t[tx][nr];
        __nv_bfloat16 h = __float2bfloat16(v);
        __nv_bfloat16 l = __float2bfloat16(v - __bfloat162float(h));
        size_t o = (size_t)(nb + nr) * K + kb + tx;
        Thi[o] = h; Tlo[o] = l;
    }
}

// g_qkv -> per-head planes (q,k split-bf16 natural; v fp16 transposed)
__global__ __launch_bounds__(256) void prep_split()
{
    const int bh = blockIdx.y;
    const int b = bh / HH, h = bh % HH;
    const int t0 = blockIdx.x * 64;
    const int tid = threadIdx.x;
    const float* base = g_qkv + (size_t)b*TT*QKV3 + h*HDIM;
    __shared__ float vs[64][65];

#pragma unroll
    for (int sel = 0; sel < 2; sel++) {
        const float* src = base + sel * DD;
        __nv_bfloat16* dh = (sel ? g_kh : g_qh) + (size_t)bh*TT*HDIM;
        __nv_bfloat16* dl = (sel ? g_kl : g_ql) + (size_t)bh*TT*HDIM;
#pragma unroll
        for (int p = 0; p < 4; p++) {
            int i = tid + p*256; int r = i >> 4; int c4 = (i & 15) << 2;
            float4 v = *(const float4*)(src + (size_t)(t0 + r)*QKV3 + c4);
            float e[4] = {v.x, v.y, v.z, v.w};
            __nv_bfloat16 hh[4], ll[4];
#pragma unroll
            for (int j = 0; j < 4; j++) {
                hh[j] = __float2bfloat16(e[j]);
                ll[j] = __float2bfloat16(e[j] - __bfloat162float(hh[j]));
            }
            __nv_bfloat162 h01 = __halves2bfloat162(hh[0], hh[1]);
            __nv_bfloat162 h23 = __halves2bfloat162(hh[2], hh[3]);
            __nv_bfloat162 l01 = __halves2bfloat162(ll[0], ll[1]);
            __nv_bfloat162 l23 = __halves2bfloat162(ll[2], ll[3]);
            uint2 hv = make_uint2(*(uint32_t*)&h01, *(uint32_t*)&h23);
            uint2 lv = make_uint2(*(uint32_t*)&l01, *(uint32_t*)&l23);
            *(uint2*)((char*)dh + ((size_t)(t0 + r)*HDIM + c4)*2) = hv;
            *(uint2*)((char*)dl + ((size_t)(t0 + r)*HDIM + c4)*2) = lv;
        }
    }
    // V: load 64x64, transpose, fp16
#pragma unroll
    for (int p = 0; p < 4; p++) {
        int i = tid + p*256; int r = i >> 4; int c4 = (i & 15) << 2;
        float4 v = *(const float4*)(base + 2*DD + (size_t)(t0 + r)*QKV3 + c4);
        vs[r][c4] = v.x; vs[r][c4+1] = v.y; vs[r][c4+2] = v.z; vs[r][c4+3] = v.w;
    }
    __syncthreads();
    {
        int d = tid >> 2;               // 0..63
        int tq = (tid & 3) << 4;        // 0,16,32,48
        uint32_t hp[8];
#pragma unroll
        for (int j2 = 0; j2 < 8; j2++) {
            __half2 hh = __floats2half2_rn(vs[tq + 2*j2][d], vs[tq + 2*j2 + 1][d]);
            hp[j2] = *(uint32_t*)&hh;
        }
        size_t oo = ((size_t)bh*HDIM*TT + (size_t)d*TT + t0 + tq) * 2;
        *(uint4*)((char*)g_vt + oo)      = ((uint4*)hp)[0];
        *(uint4*)((char*)g_vt + oo + 16) = ((uint4*)hp)[1];
    }
}

// ---------------- tcgen05 GEMM (verified) -----------------------------------
#define SM_A   1024
#define SM_AL  (SM_A  + 16384)
#define SM_B   (SM_AL + 16384)
#define SM_BL  (SM_B  + 16384)
#define GEMM_SMEM (SM_BL + 16384)
#define GEMM_IDESC 0x8200490u

#if HAS_TC
__device__ __forceinline__ void load_tile64(
    char* smem, int dst, const __nv_bfloat16* __restrict__ g,
    int ld, int row0, int k0, int tid)
{
    const char* base = (const char*)g;
#pragma unroll
    for (int p = 0; p < 4; p++) {
        int i = tid + p * 256;
        int r = i >> 3;
        int c16 = (i & 7) << 4;
        uint4 v = *(const uint4*)(base + ((size_t)(row0 + r) * ld + k0) * 2 + c16);
        *(uint4*)(smem + dst + SMEM_SWIZZLE_128B(r * 128 + c16)) = v;
    }
}
#endif

__global__ __launch_bounds__(256) void gemm_any(
    const float* __restrict__ A, const float* __restrict__ W,
    const __nv_bfloat16* __restrict__ Ahi, const __nv_bfloat16* __restrict__ Alo,
    const __nv_bfloat16* __restrict__ Bthi, const __nv_bfloat16* __restrict__ Btlo,
    const float* __restrict__ bias, float* __restrict__ C,
    int M, int N, int K)
{
    extern __shared__ char smem[];
#if HAS_TC
    const uint32_t sb = smem_u32(smem);
    const int tid = threadIdx.x;
    const int wid = tid >> 5, lid = tid & 31;
    const int m0 = blockIdx.y * 128, n0 = blockIdx.x * 128;

    if (wid == 0) { TCGEN05_ALLOC(sb, 128); TCGEN05_RELINQ(); }
    if (tid == 0) MBARRIER_INIT(sb + 8, 1);
    __syncthreads();
    uint32_t tmem;
    asm volatile("ld.shared.b32 %0, [%1];" : "=r"(tmem) : "r"(sb));

    const uint64_t dAh = MAKE_SMEM_DESC(sb + SM_A);
    const uint64_t dAl = MAKE_SMEM_DESC(sb + SM_AL);
    const uint64_t dBh = MAKE_SMEM_DESC(sb + SM_B);
    const uint64_t dBl = MAKE_SMEM_DESC(sb + SM_BL);

    const int nchunks = K >> 6;
    for (int c = 0; c < nchunks; c++) {
        const int k0 = c << 6;
        load_tile64(smem, SM_A,  Ahi,  K, m0, k0, tid);
        load_tile64(smem, SM_AL, Alo,  K, m0, k0, tid);
        load_tile64(smem, SM_B,  Bthi, K, n0, k0, tid);
        load_tile64(smem, SM_BL, Btlo, K, n0, k0, tid);
        FENCE_PROXY_ASYNC();
        __syncthreads();

        if (wid == 0 && elect_one()) {
#pragma unroll
            for (int ks = 0; ks < 4; ks++) {
                uint32_t en0 = (c > 0 || ks > 0) ? 1u : 0u;
                mma_f16_ss_cg1(tmem, dAh + ks*2, dBh + ks*2, GEMM_IDESC, en0);
                mma_f16_ss_cg1(tmem, dAh + ks*2, dBl + ks*2, GEMM_IDESC, 1u);
                mma_f16_ss_cg1(tmem, dAl + ks*2, dBh + ks*2, GEMM_IDESC, 1u);
            }
            TCGEN05_COMMIT(sb + 8);
        }
        MBARRIER_WAIT_PARITY(sb + 8, c & 1);
    }

    TCGEN05_FENCE_AFTER();
    if (wid < 4) {
        const int row = m0 + wid * 32 + lid;
#pragma unroll
        for (int base = 0; base < 128; base += 32) {
            uint32_t r[32];
            LDTM_X32(r, tmem + base);
            TCGEN05_WAIT_LD();
            float* crow = C + (size_t)row * N + n0 + base;
            const float* bp = bias + n0 + base;
#pragma unroll
            for (int j = 0; j < 32; j += 4) {
                float4 o = make_float4(__uint_as_float(r[j])   + bp[j],
                                       __uint_as_float(r[j+1]) + bp[j+1],
                                       __uint_as_float(r[j+2]) + bp[j+2],
                                       __uint_as_float(r[j+3]) + bp[j+3]);
                *(float4*)(crow + j) = o;
            }
        }
    }
    __syncthreads();
    if (wid == 0) TCGEN05_DEALLOC(tmem, 128);
#else
    float (*As)[128] = (float(*)[128])(smem);
    float (*Bs)[128] = (float(*)[128])(smem + 8192);
    const int tid  = threadIdx.x;
    const int brow = blockIdx.y, bcol = blockIdx.x;
    const int tr = tid >> 4, tc = tid & 15;
    float acc[8][8];
#pragma unroll
    for (int i = 0; i < 8; i++)
#pragma unroll
        for (int j = 0; j < 8; j++) acc[i][j] = 0.f;
    for (int k0 = 0; k0 < K; k0 += 16) {
#pragma unroll
        for (int p = 0; p < 2; p++) {
            int v  = tid + 256 * p;
            int ra = v >> 2, ca = (v & 3) << 2;
            float4 a4 = *(const float4*)(A + (size_t)(brow*128 + ra)*K + k0 + ca);
            As[ca+0][ra] = a4.x; As[ca+1][ra] = a4.y;
            As[ca+2][ra] = a4.z; As[ca+3][ra] = a4.w;
            int rb = v >> 5, cb = (v & 31) << 2;
            float4 b4 = *(const float4*)(W + (size_t)(k0 + rb)*N + bcol*128 + cb);
            *(float4*)&Bs[rb][cb] = b4;
        }
        __syncthreads();
#pragma unroll
        for (int kk = 0; kk < 16; kk++) {
#pragma unroll
            for (int i = 0; i < 8; i++)
#pragma unroll
                for (int j = 0; j < 8; j++)
                    acc[i][j] = fmaf(As[kk][tr*8+i], Bs[kk][tc*8+j], acc[i][j]);
        }
        __syncthreads();
    }
    const float* bp = bias + bcol*128 + tc*8;
#pragma unroll
    for (int i = 0; i < 8; i++) {
        int row = brow*128 + tr*8 + i;
        float* crow = C + (size_t)row*N + bcol*128 + tc*8;
#pragma unroll
        for (int j = 0; j < 8; j++) crow[j] = acc[i][j] + bp[j];
    }
#endif
}

// ---------------- tcgen05 flash attention (pipelined) -----------------------
#define ASM_TPTR 0
#define ASM_MBS  8
#define ASM_MBPV 16
#define ASM_QH   1024
#define ASM_QL   (ASM_QH + 16384)
#define ASM_K0H  (ASM_QL + 16384)
#define ASM_K0L  (ASM_K0H + 16384)
#define ASM_K1H  (ASM_K0L + 16384)
#define ASM_K1L  (ASM_K1H + 16384)
#define ASM_V0   (ASM_K1L + 16384)
#define ASM_V1   (ASM_V0 + 16384)
#define ASM_P    (ASM_V1 + 16384)     // 32768: 128x128 fp16
#define ASM_LP   (ASM_P + 32768)
#define ATT_SMEM (ASM_LP + 1024)      // 165888 B
#define IDESC_S      0x8200490u       // bf16xbf16 -> f32, M=128 N=128
#define IDESC_PV_F16 0x8100010u       // f16xf16  -> f32, M=128 N=64

__global__ __launch_bounds__(256) void attn_tc()
{
#if HAS_TC
    extern __shared__ char smem[];
    const uint32_t sb = smem_u32(smem);
    const int tid = threadIdx.x;
    const int w = tid >> 5, lid = tid & 31;
    const int bh = blockIdx.y;
    const int qt = gridDim.x - 1 - blockIdx.x;   // big tiles first
    const int q0 = qt * 128;
    const int r  = (w & 3) * 32 + lid;           // owned S/O row
    const int ch = w >> 2;                       // column half (0/1)

    const char* qh = (const char*)(g_qh + (size_t)bh*TT*HDIM);
    const char* ql = (const char*)(g_ql + (size_t)bh*TT*HDIM);
    const char* kh = (const char*)(g_kh + (size_t)bh*TT*HDIM);
    const char* kl = (const char*)(g_kl + (size_t)bh*TT*HDIM);
    const char* vt = (const char*)(g_vt + (size_t)bh*HDIM*TT);

    if (w == 0) { TCGEN05_ALLOC(sb + ASM_TPTR, 256); TCGEN05_RELINQ(); }
    if (tid == 0) { MBARRIER_INIT(sb + ASM_MBS, 1); MBARRIER_INIT(sb + ASM_MBPV, 1); }

    // Q tile (SW128 K-major)
#pragma unroll
    for (int p = 0; p < 4; p++) {
        int i = tid + p*256; int rr = i >> 3; int c16 = (i & 7) << 4;
        uint32_t so = SMEM_SWIZZLE_128B(rr*128 + c16);
        *(uint4*)(smem + ASM_QH + so) = *(const uint4*)(qh + (size_t)(q0+rr)*128 + c16);
        *(uint4*)(smem + ASM_QL + so) = *(const uint4*)(ql + (size_t)(q0+rr)*128 + c16);
    }

    // async load of K/V tile 0 into buf0
    {
        const uint32_t bKH = sb + ASM_K0H, bKL = sb + ASM_K0L, bV = sb + ASM_V0;
#pragma unroll
        for (int p = 0; p < 4; p++) {
            int i = tid + p*256; int rr = i >> 3; int c16 = (i & 7) << 4;
            uint32_t so = SMEM_SWIZZLE_128B(rr*128 + c16);
            CP_ASYNC16(bKH + so, kh + (size_t)rr*128 + c16);
            CP_ASYNC16(bKL + so, kl + (size_t)rr*128 + c16);
        }
#pragma unroll
        for (int p = 0; p < 4; p++) {
            int i = tid + p*256; int d = i >> 4; int j = i & 15;
            uint32_t bo = (uint32_t)((((d>>3) + (j>>3)*8) << 10) + ((d & 7) << 7) + ((j & 7) << 4));
            CP_ASYNC16(bV + SMEM_SWIZZLE_128B(bo), vt + ((size_t)d*TT + j*8)*2);
        }
        CP_COMMIT();
    }
    __syncthreads();
    uint32_t tmem;
    asm volatile("ld.shared.b32 %0, [%1];" : "=r"(tmem) : "r"(sb + ASM_TPTR));

    const uint64_t dQh = MAKE_SMEM_DESC(sb+ASM_QH), dQl = MAKE_SMEM_DESC(sb+ASM_QL);
    const uint64_t dP  = MAKE_SMEM_DESC(sb+ASM_P);

    float lsum = 0.f;
    const uint32_t prow = (uint32_t)((((r>>3) + ch*16) << 10) + ((r & 7) << 7));

    for (int kt = 0; kt <= qt; kt++) {
        const int buf = kt & 1;
        const uint32_t aKH = buf ? ASM_K1H : ASM_K0H;
        const uint32_t aKL = buf ? ASM_K1L : ASM_K0L;
        const uint32_t aV  = buf ? ASM_V1  : ASM_V0;
        const uint64_t dKh = MAKE_SMEM_DESC(sb+aKH), dKl = MAKE_SMEM_DESC(sb+aKL);
        const uint64_t dV  = MAKE_SMEM_DESC(sb+aV);

        // 1) K/V(kt) loads complete
        CP_WAIT0();
        __syncthreads();

        // 2) S = Q K^T (split-bf16, 3 combos)
        if (w == 0 && elect_one()) {
#pragma unroll
            for (int ks = 0; ks < 4; ks++) {
                mma_f16_ss_cg1(tmem, dQh + ks*2, dKh + ks*2, IDESC_S, ks > 0);
                mma_f16_ss_cg1(tmem, dQh + ks*2, dKl + ks*2, IDESC_S, 1u);
                mma_f16_ss_cg1(tmem, dQl + ks*2, dKh + ks*2, IDESC_S, 1u);
            }
            TCGEN05_COMMIT(sb + ASM_MBS);
        }

        // 3) PV(kt-1) retired -> P buffer and V[buf^1] reusable
        if (kt > 0) MBARRIER_WAIT_PARITY(sb + ASM_MBPV, (kt-1) & 1);

        // 4) prefetch K/V(kt+1) into other buffer (overlaps epilogue below)
        if (kt < qt) {
            const int k1 = (kt + 1) * 128;
            const uint32_t nKH = sb + (buf ? ASM_K0H : ASM_K1H);
            const uint32_t nKL = sb + (buf ? ASM_K0L : ASM_K1L);
            const uint32_t nV  = sb + (buf ? ASM_V0  : ASM_V1);
#pragma unroll
            for (int p = 0; p < 4; p++) {
                int i = tid + p*256; int rr = i >> 3; int c16 = (i & 7) << 4;
                uint32_t so = SMEM_SWIZZLE_128B(rr*128 + c16);
                CP_ASYNC16(nKH + so, kh + (size_t)(k1+rr)*128 + c16);
                CP_ASYNC16(nKL + so, kl + (size_t)(k1+rr)*128 + c16);
            }
#pragma unroll
            for (int p = 0; p < 4; p++) {
                int i = tid + p*256; int d = i >> 4; int j = i & 15;
                uint32_t bo = (uint32_t)((((d>>3) + (j>>3)*8) << 10) + ((d & 7) << 7) + ((j & 7) << 4));
                CP_ASYNC16(nV + SMEM_SWIZZLE_128B(bo), vt + ((size_t)d*TT + k1 + j*8)*2);
            }
            CP_COMMIT();
        }

        // 5) S ready
        MBARRIER_WAIT_PARITY(sb + ASM_MBS, kt & 1);
        TCGEN05_FENCE_AFTER();

        // 6) softmax epilogue: exp -> fp16 P
        const bool diag = (kt == qt);
#pragma unroll
        for (int cb = 0; cb < 64; cb += 32) {
            uint32_t sreg[32];
            LDTM_X32(sreg, tmem + ch*64 + cb);
            TCGEN05_WAIT_LD();
            uint32_t hp[16];
#pragma unroll
            for (int j2 = 0; j2 < 16; j2++) {
                float e0 = __expf(__uint_as_float(sreg[2*j2])   * ATT_SCALE);
                float e1 = __expf(__uint_as_float(sreg[2*j2+1]) * ATT_SCALE);
                if (diag) {
                    int c = ch*64 + cb + 2*j2;
                    if (c     > r) e0 = 0.f;
                    if (c + 1 > r) e1 = 0.f;
                }
                lsum += e0 + e1;
                __half2 hh = __floats2half2_rn(e0, e1);
                hp[j2] = *(uint32_t*)&hh;
            }
#pragma unroll
            for (int k4 = 0; k4 < 4; k4++) {
                uint32_t so = SMEM_SWIZZLE_128B(prow + cb*2 + k4*16);
                *(uint4*)(smem + ASM_P + so) = ((uint4*)hp)[k4];
            }
        }
        FENCE_PROXY_ASYNC();
        TCGEN05_FENCE_BEFORE();
        __syncthreads();

        // 7) O += P V   (fp16 x fp16)
        if (w == 0 && elect_one()) {
#pragma unroll
            for (int ks = 0; ks < 8; ks++) {
                uint32_t po = (ks < 4) ? ks*2 : 1024 + (ks-4)*2;
                uint32_t vo = (ks < 4) ? ks*2 : 512  + (ks-4)*2;
                uint32_t en0 = (kt > 0 || ks > 0) ? 1u : 0u;
                mma_f16_ss_cg1(tmem + 128, dP + po, dV + vo, IDESC_PV_F16, en0);
            }
            TCGEN05_COMMIT(sb + ASM_MBPV);
        }
    }
    MBARRIER_WAIT_PARITY(sb + ASM_MBPV, qt & 1);
    TCGEN05_FENCE_AFTER();

    // O epilogue: normalize by row sum, write split bf16
    *(float*)(smem + ASM_LP + (ch*128 + r)*4) = lsum;
    __syncthreads();
    {
        uint32_t oreg[32];
        LDTM_X32(oreg, tmem + 128 + ch*32);
        TCGEN05_WAIT_LD();
        float lt = *(float*)(smem + ASM_LP + r*4)
                 + *(float*)(smem + ASM_LP + (128 + r)*4);
        float inv = 1.f / lt;
        const int b2 = bh / HH, h2 = bh % HH;
        size_t oo = ((size_t)(b2*TT + q0 + r)*DD + h2*HDIM + ch*32) * 2;
        uint32_t hp[16], lp[16];
#pragma unroll
        for (int j2 = 0; j2 < 16; j2++) {
            float e0 = __uint_as_float(oreg[2*j2])   * inv;
            float e1 = __uint_as_float(oreg[2*j2+1]) * inv;
            __nv_bfloat16 h0 = __float2bfloat16(e0), h1 = __float2bfloat16(e1);
            __nv_bfloat16 l0 = __float2bfloat16(e0 - __bfloat162float(h0));
            __nv_bfloat16 l1 = __float2bfloat16(e1 - __bfloat162float(h1));
            __nv_bfloat162 hh = __halves2bfloat162(h0, h1);
            __nv_bfloat162 ll = __halves2bfloat162(l0, l1);
            hp[j2] = *(uint32_t*)&hh; lp[j2] = *(uint32_t*)&ll;
        }
#pragma unroll
        for (int k4 = 0; k4 < 4; k4++) {
            *(uint4*)((char*)g_ahi + oo + k4*16) = ((uint4*)hp)[k4];
            *(uint4*)((char*)g_alo + oo + k4*16) = ((uint4*)lp)[k4];
        }
    }
    __syncthreads();
    if (w == 0) TCGEN05_DEALLOC(tmem, 256);
#endif
}

// ---------------------------------------------------------------------------
extern "C" void kernel_launch(void* const* d_in, const int* in_sizes, int n_in,
                              void* d_out, int out_size)
{
    const float* x     = (const float*)d_in[0];
    const float* W_qkv = (const float*)d_in[1];
    const float* b_qkv = (const float*)d_in[2];
    const float* W_out = (const float*)d_in[3];
    const float* b_out = (const float*)d_in[4];
    float* out = (float*)d_out;

    void* p;
    cudaGetSymbolAddress(&p, g_qkv);    float* qkv = (float*)p;
    cudaGetSymbolAddress(&p, g_xhi);    __nv_bfloat16* xhi = (__nv_bfloat16*)p;
    cudaGetSymbolAddress(&p, g_xlo);    __nv_bfloat16* xlo = (__nv_bfloat16*)p;
    cudaGetSymbolAddress(&p, g_ahi);    __nv_bfloat16* ahi = (__nv_bfloat16*)p;
    cudaGetSymbolAddress(&p, g_alo);    __nv_bfloat16* alo = (__nv_bfloat16*)p;
    cudaGetSymbolAddress(&p, g_wqt_hi); __nv_bfloat16* wqh = (__nv_bfloat16*)p;
    cudaGetSymbolAddress(&p, g_wqt_lo); __nv_bfloat16* wql = (__nv_bfloat16*)p;
    cudaGetSymbolAddress(&p, g_wot_hi); __nv_bfloat16* woh = (__nv_bfloat16*)p;
    cudaGetSymbolAddress(&p, g_wot_lo); __nv_bfloat16* wol = (__nv_bfloat16*)p;

    const int M = BB * TT;  // 8192

    {
        int n4 = M * DD / 4;
        split_hl<<<(n4 + 255) / 256, 256>>>(x, xhi, xlo, n4);
        tsplit_kernel<<<dim3(DD/32, QKV3/32), dim3(32, 8)>>>(W_qkv, wqh, wql, DD, QKV3);
        tsplit_kernel<<<dim3(DD/32, DD/32),   dim3(32, 8)>>>(W_out, woh, wol, DD, DD);
    }

    cudaFuncSetAttribute(gemm_any, cudaFuncAttributeMaxDynamicSharedMemorySize, GEMM_SMEM);

    // 1) QKV projection
    gemm_any<<<dim3(QKV3/128, M/128), 256, GEMM_SMEM>>>(
        x, W_qkv, xhi, xlo, wqh, wql, b_qkv, qkv, M, QKV3, DD);

    // 2) per-head planes (q,k split; v^T fp16)
    prep_split<<<dim3(TT/64, BB*HH), 256>>>();

    // 3) pipelined tcgen05 causal flash attention -> g_ahi/g_alo
    cudaFuncSetAttribute(attn_tc, cudaFuncAttributeMaxDynamicSharedMemorySize, ATT_SMEM);
    attn_tc<<<dim3(TT/128, BB*HH), 256, ATT_SMEM>>>();

    // 4) output projection
    gemm_any<<<dim3(DD/128, M/128), 256, GEMM_SMEM>>>(
        nullptr, nullptr, ahi, alo, woh, wol, b_out, out, M, DD, DD);
}

// round 7
// speedup vs baseline: 11.1316x; 1.0445x over previous
#include <cuda_runtime.h>
#include <cuda_bf16.h>
#include <cuda_fp16.h>
#include <math.h>
#include <cstdint>

#define BB   2
#define TT   4096
#define DD   768
#define HH   12
#define HDIM 64
#define QKV3 (3*DD)       // 2304
#define ATT_SCALE 0.125f  // 1/sqrt(64)

#if !defined(__CUDA_ARCH__)
#define HAS_TC 1
#elif defined(__CUDA_ARCH_FEAT_SM103_ALL)
#define HAS_TC 1
#elif defined(__CUDA_ARCH_SPECIFIC__) && (__CUDA_ARCH_SPECIFIC__ == 1030)
#define HAS_TC 1
#elif defined(__CUDA_ARCH_FAMILY_SPECIFIC__) && (__CUDA_ARCH_FAMILY_SPECIFIC__ >= 1000)
#define HAS_TC 1
#else
#define HAS_TC 0
#endif

// ---------------- scratch ----------------
__device__ float         g_qkv [(size_t)BB*TT*QKV3];
__device__ __nv_bfloat16 g_xhi [(size_t)BB*TT*DD];
__device__ __nv_bfloat16 g_xlo [(size_t)BB*TT*DD];
__device__ __nv_bfloat16 g_ahi [(size_t)BB*TT*DD];
__device__ __nv_bfloat16 g_alo [(size_t)BB*TT*DD];
__device__ __nv_bfloat16 g_wqt_hi[(size_t)QKV3*DD];
__device__ __nv_bfloat16 g_wqt_lo[(size_t)QKV3*DD];
__device__ __nv_bfloat16 g_wot_hi[(size_t)DD*DD];
__device__ __nv_bfloat16 g_wot_lo[(size_t)DD*DD];
__device__ __nv_bfloat16 g_qh [(size_t)BB*HH*TT*HDIM];
__device__ __nv_bfloat16 g_ql [(size_t)BB*HH*TT*HDIM];
__device__ __nv_bfloat16 g_kh [(size_t)BB*HH*TT*HDIM];
__device__ __nv_bfloat16 g_kl [(size_t)BB*HH*TT*HDIM];
__device__ __half        g_vt [(size_t)BB*HH*HDIM*TT];  // [bh][d][t]

// ---------------- helpers ----------------
__device__ __forceinline__ uint32_t smem_u32(const void* p) {
    uint32_t a;
    asm("{ .reg .u64 t; cvta.to.shared.u64 t, %1; cvt.u32.u64 %0, t; }"
        : "=r"(a) : "l"(p));
    return a;
}
#define SMEM_SWIZZLE_128B(off) ((off) ^ (((off) >> 3) & 0x70))

#if HAS_TC
__device__ __forceinline__ uint32_t elect_one() {
    uint32_t pred;
    asm volatile("{\n\t.reg .pred p;\n\telect.sync _|p, 0xFFFFFFFF;\n\t"
                 "selp.b32 %0, 1, 0, p;\n\t}" : "=r"(pred));
    return pred;
}
static constexpr uint64_t SMEM_DESC_BASE_SW128 =
    (uint64_t(2) << 61) | (uint64_t(1) << 46) | (uint64_t(64) << 32) | (uint64_t(1) << 16);
#define MAKE_SMEM_DESC(addr) (SMEM_DESC_BASE_SW128 | ((uint64_t)((addr) >> 4) & 0x3FFF))

#define TCGEN05_ALLOC(sa, n) \
    asm volatile("tcgen05.alloc.cta_group::1.sync.aligned.shared::cta.b32 [%0], %1;" \
                 :: "r"((uint32_t)(sa)), "r"((uint32_t)(n)) : "memory")
#define TCGEN05_DEALLOC(t, n) \
    asm volatile("tcgen05.dealloc.cta_group::1.sync.aligned.b32 %0, %1;" :: "r"(t), "r"(n))
#define TCGEN05_RELINQ() \
    asm volatile("tcgen05.relinquish_alloc_permit.cta_group::1.sync.aligned;")
#define TCGEN05_COMMIT(mb) \
    asm volatile("tcgen05.commit.cta_group::1.mbarrier::arrive::one.shared::cluster.b64 [%0];" \
                 :: "r"((uint32_t)(mb)) : "memory")
#define TCGEN05_FENCE_AFTER() \
    asm volatile("tcgen05.fence::after_thread_sync;" ::: "memory")
#define TCGEN05_FENCE_BEFORE() \
    asm volatile("tcgen05.fence::before_thread_sync;" ::: "memory")
#define TCGEN05_WAIT_LD() \
    asm volatile("tcgen05.wait::ld.sync.aligned;" ::: "memory")
#define FENCE_PROXY_ASYNC() \
    asm volatile("fence.proxy.async.shared::cta;" ::: "memory")
#define MBARRIER_INIT(mb, cnt) \
    asm volatile("mbarrier.init.shared.b64 [%0], %1;" \
                 :: "r"((uint32_t)(mb)), "r"((uint32_t)(cnt)) : "memory")
#define MBARRIER_WAIT_PARITY(mb, ph) do {                                   \
    uint32_t _m = (uint32_t)(mb); uint32_t _p = (uint32_t)(ph);             \
    asm volatile("{\n\t.reg .pred P1;\n\t"                                  \
        "WL_%=:\n\t"                                                        \
        "mbarrier.try_wait.parity.acquire.cta.shared::cta.b64 P1, [%0], %1, 0x989680;\n\t" \
        "@P1 bra.uni WD_%=;\n\t"                                            \
        "bra.uni WL_%=;\n\t"                                                \
        "WD_%=:\n\t}" :: "r"(_m), "r"(_p) : "memory");                      \
} while (0)
#define CP_ASYNC16(dst, src) \
    asm volatile("cp.async.cg.shared.global [%0], [%1], 16;" \
                 :: "r"((uint32_t)(dst)), "l"(src) : "memory")
#define CP_COMMIT() asm volatile("cp.async.commit_group;" ::: "memory")
#define CP_WAIT0()  asm volatile("cp.async.wait_group 0;" ::: "memory")
#define CP_WAIT1()  asm volatile("cp.async.wait_group 1;" ::: "memory")

__device__ __forceinline__ void mma_f16_ss_cg1(
    uint32_t d_tmem, uint64_t a_desc, uint64_t b_desc, uint32_t idesc, uint32_t en)
{
    asm volatile(
        "{\n\t.reg .pred p;\n\tsetp.ne.u32 p, %5, 0;\n\t"
        "tcgen05.mma.cta_group::1.kind::f16 [%0], %1, %2, %3, {%4, %4, %4, %4}, p;\n\t}"
        :: "r"(d_tmem), "l"(a_desc), "l"(b_desc), "r"(idesc), "r"(0u), "r"(en)
        : "memory");
}
#define LDTM_X32(r, addr)                                                    \
    asm volatile("tcgen05.ld.sync.aligned.32x32b.x32.b32 "                   \
        "{%0, %1, %2, %3, %4, %5, %6, %7, %8, %9, %10, %11, %12, %13, %14, %15, " \
        " %16, %17, %18, %19, %20, %21, %22, %23, %24, %25, %26, %27, %28, %29, %30, %31}, [%32];" \
        : "=r"((r)[0]),  "=r"((r)[1]),  "=r"((r)[2]),  "=r"((r)[3]),         \
          "=r"((r)[4]),  "=r"((r)[5]),  "=r"((r)[6]),  "=r"((r)[7]),         \
          "=r"((r)[8]),  "=r"((r)[9]),  "=r"((r)[10]), "=r"((r)[11]),        \
          "=r"((r)[12]), "=r"((r)[13]), "=r"((r)[14]), "=r"((r)[15]),        \
          "=r"((r)[16]), "=r"((r)[17]), "=r"((r)[18]), "=r"((r)[19]),        \
          "=r"((r)[20]), "=r"((r)[21]), "=r"((r)[22]), "=r"((r)[23]),        \
          "=r"((r)[24]), "=r"((r)[25]), "=r"((r)[26]), "=r"((r)[27]),        \
          "=r"((r)[28]), "=r"((r)[29]), "=r"((r)[30]), "=r"((r)[31])         \
        : "r"(addr))
#endif  // HAS_TC

// ---------------- prep kernels ----------------
__global__ __launch_bounds__(256) void split_hl(
    const float* __restrict__ src, __nv_bfloat16* __restrict__ hi,
    __nv_bfloat16* __restrict__ lo, int n4)
{
    int i = blockIdx.x * 256 + threadIdx.x;
    if (i >= n4) return;
    float4 v = ((const float4*)src)[i];
    float vs[4] = {v.x, v.y, v.z, v.w};
    __nv_bfloat16 h[4], l[4];
#pragma unroll
    for (int j = 0; j < 4; j++) {
        h[j] = __float2bfloat16(vs[j]);
        l[j] = __float2bfloat16(vs[j] - __bfloat162float(h[j]));
    }
    ((__nv_bfloat162*)hi)[2*i]   = __halves2bfloat162(h[0], h[1]);
    ((__nv_bfloat162*)hi)[2*i+1] = __halves2bfloat162(h[2], h[3]);
    ((__nv_bfloat162*)lo)[2*i]   = __halves2bfloat162(l[0], l[1]);
    ((__nv_bfloat162*)lo)[2*i+1] = __halves2bfloat162(l[2], l[3]);
}

__global__ void tsplit_kernel(
    const float* __restrict__ W, __nv_bfloat16* __restrict__ Thi,
    __nv_bfloat16* __restrict__ Tlo, int K, int N)
{
    __shared__ float t[32][33];
    int kb = blockIdx.x * 32, nb = blockIdx.y * 32;
    int tx = threadIdx.x, ty = threadIdx.y;
#pragma unroll
    for (int i = 0; i < 4; i++) {
        int k = ty + i * 8;
        t[k][tx] = W[(size_t)(kb + k) * N + nb + tx];
    }
    __syncthreads();
#pragma unroll
    for (int i = 0; i < 4; i++) {
        int nr = ty + i * 8;
        float v = t[tx][nr];
        __nv_bfloat16 h = __float2bfloat16(v);
        __nv_bfloat16 l = __float2bfloat16(v - __bfloat162float(h));
        size_t o = (size_t)(nb + nr) * K + kb + tx;
        Thi[o] = h; Tlo[o] = l;
    }
}

__global__ __launch_bounds__(256) void prep_split()
{
    const int bh = blockIdx.y;
    const int b = bh / HH, h = bh % HH;
    const int t0 = blockIdx.x * 64;
    const int tid = threadIdx.x;
    const float* base = g_qkv + (size_t)b*TT*QKV3 + h*HDIM;
    __shared__ float vs[64][65];

#pragma unroll
    for (int sel = 0; sel < 2; sel++) {
        const float* src = base + sel * DD;
        __nv_bfloat16* dh = (sel ? g_kh : g_qh) + (size_t)bh*TT*HDIM;
        __nv_bfloat16* dl = (sel ? g_kl : g_ql) + (size_t)bh*TT*HDIM;
#pragma unroll
        for (int p = 0; p < 4; p++) {
            int i = tid + p*256; int r = i >> 4; int c4 = (i & 15) << 2;
            float4 v = *(const float4*)(src + (size_t)(t0 + r)*QKV3 + c4);
            float e[4] = {v.x, v.y, v.z, v.w};
            __nv_bfloat16 hh[4], ll[4];
#pragma unroll
            for (int j = 0; j < 4; j++) {
                hh[j] = __float2bfloat16(e[j]);
                ll[j] = __float2bfloat16(e[j] - __bfloat162float(hh[j]));
            }
            __nv_bfloat162 h01 = __halves2bfloat162(hh[0], hh[1]);
            __nv_bfloat162 h23 = __halves2bfloat162(hh[2], hh[3]);
            __nv_bfloat162 l01 = __halves2bfloat162(ll[0], ll[1]);
            __nv_bfloat162 l23 = __halves2bfloat162(ll[2], ll[3]);
            uint2 hv = make_uint2(*(uint32_t*)&h01, *(uint32_t*)&h23);
            uint2 lv = make_uint2(*(uint32_t*)&l01, *(uint32_t*)&l23);
            *(uint2*)((char*)dh + ((size_t)(t0 + r)*HDIM + c4)*2) = hv;
            *(uint2*)((char*)dl + ((size_t)(t0 + r)*HDIM + c4)*2) = lv;
        }
    }
#pragma unroll
    for (int p = 0; p < 4; p++) {
        int i = tid + p*256; int r = i >> 4; int c4 = (i & 15) << 2;
        float4 v = *(const float4*)(base + 2*DD + (size_t)(t0 + r)*QKV3 + c4);
        vs[r][c4] = v.x; vs[r][c4+1] = v.y; vs[r][c4+2] = v.z; vs[r][c4+3] = v.w;
    }
    __syncthreads();
    {
        int d = tid >> 2;
        int tq = (tid & 3) << 4;
        uint32_t hp[8];
#pragma unroll
        for (int j2 = 0; j2 < 8; j2++) {
            __half2 hh = __floats2half2_rn(vs[tq + 2*j2][d], vs[tq + 2*j2 + 1][d]);
            hp[j2] = *(uint32_t*)&hh;
        }
        size_t oo = ((size_t)bh*HDIM*TT + (size_t)d*TT + t0 + tq) * 2;
        *(uint4*)((char*)g_vt + oo)      = ((uint4*)hp)[0];
        *(uint4*)((char*)g_vt + oo + 16) = ((uint4*)hp)[1];
    }
}

// ---------------- tcgen05 GEMM: 128x256 tile, double-buffered chunks -------
#define GB_AH 0
#define GB_AL 16384
#define GB_BH 32768
#define GB_BL 65536
#define GB_SZ 98304
#define GSM_BUF 1024
#define GEMM_SMEM (GSM_BUF + 2*GB_SZ)    // 197632
#define GEMM_IDESC 0x8400490u            // f32 acc, bf16xbf16, M=128, N=256

#if HAS_TC
__device__ __forceinline__ void gemm_prefetch(
    uint32_t sbuf, const char* Ah, const char* Al, const char* Bh, const char* Bl,
    int K, int m0, int n0, int k0, int tid)
{
#pragma unroll
    for (int p = 0; p < 4; p++) {           // A: 128 rows x 128B x 2 planes
        int i = tid + p * 256;
        int r = i >> 3, c16 = (i & 7) << 4;
        uint32_t so = SMEM_SWIZZLE_128B(r * 128 + c16);
        size_t go = ((size_t)(m0 + r) * K + k0) * 2 + c16;
        CP_ASYNC16(sbuf + GB_AH + so, Ah + go);
        CP_ASYNC16(sbuf + GB_AL + so, Al + go);
    }
#pragma unroll
    for (int p = 0; p < 8; p++) {           // B: 256 rows x 128B x 2 planes
        int i = tid + p * 256;
        int r = i >> 3, c16 = (i & 7) << 4;
        uint32_t so = SMEM_SWIZZLE_128B(r * 128 + c16);
        size_t go = ((size_t)(n0 + r) * K + k0) * 2 + c16;
        CP_ASYNC16(sbuf + GB_BH + so, Bh + go);
        CP_ASYNC16(sbuf + GB_BL + so, Bl + go);
    }
}
#endif

__global__ __launch_bounds__(256) void gemm_any(
    const float* __restrict__ A, const float* __restrict__ W,
    const __nv_bfloat16* __restrict__ Ahi, const __nv_bfloat16* __restrict__ Alo,
    const __nv_bfloat16* __restrict__ Bthi, const __nv_bfloat16* __restrict__ Btlo,
    const float* __restrict__ bias, float* __restrict__ C,
    int M, int N, int K)
{
    extern __shared__ char smem[];
#if HAS_TC
    const uint32_t sb = smem_u32(smem);
    const int tid = threadIdx.x;
    const int wid = tid >> 5, lid = tid & 31;
    const int m0 = blockIdx.y * 128, n0 = blockIdx.x * 256;
    const char* Ah = (const char*)Ahi;  const char* Al = (const char*)Alo;
    const char* Bh = (const char*)Bthi; const char* Bl = (const char*)Btlo;

    if (wid == 0) { TCGEN05_ALLOC(sb, 256); TCGEN05_RELINQ(); }
    if (tid == 0) MBARRIER_INIT(sb + 8, 1);

    gemm_prefetch(sb + GSM_BUF,         Ah, Al, Bh, Bl, K, m0, n0, 0,  tid);
    CP_COMMIT();
    gemm_prefetch(sb + GSM_BUF + GB_SZ, Ah, Al, Bh, Bl, K, m0, n0, 64, tid);
    CP_COMMIT();

    __syncthreads();
    uint32_t tmem;
    asm volatile("ld.shared.b32 %0, [%1];" : "=r"(tmem) : "r"(sb));

    const int nchunks = K >> 6;   // 12
    for (int c = 0; c < nchunks; c++) {
        const uint32_t bufb = sb + GSM_BUF + (c & 1) * GB_SZ;
        if (c + 1 < nchunks) { CP_WAIT1(); } else { CP_WAIT0(); }
        __syncthreads();

        if (wid == 0 && elect_one()) {
            const uint64_t dAh = MAKE_SMEM_DESC(bufb + GB_AH);
            const uint64_t dAl = MAKE_SMEM_DESC(bufb + GB_AL);
            const uint64_t dBh = MAKE_SMEM_DESC(bufb + GB_BH);
            const uint64_t dBl = MAKE_SMEM_DESC(bufb + GB_BL);
#pragma unroll
            for (int ks = 0; ks < 4; ks++) {
                uint32_t en0 = (c > 0 || ks > 0) ? 1u : 0u;
                mma_f16_ss_cg1(tmem, dAh + ks*2, dBh + ks*2, GEMM_IDESC, en0);
                mma_f16_ss_cg1(tmem, dAh + ks*2, dBl + ks*2, GEMM_IDESC, 1u);
                mma_f16_ss_cg1(tmem, dAl + ks*2, dBh + ks*2, GEMM_IDESC, 1u);
            }
            TCGEN05_COMMIT(sb + 8);
        }
        MBARRIER_WAIT_PARITY(sb + 8, c & 1);     // lockstep: <=1 phase in flight
        if (c + 2 < nchunks) {
            gemm_prefetch(bufb, Ah, Al, Bh, Bl, K, m0, n0, (c + 2) * 64, tid);
            CP_COMMIT();
        }
    }

    TCGEN05_FENCE_AFTER();
    if (wid < 4) {
        const int row = m0 + wid * 32 + lid;
#pragma unroll
        for (int base = 0; base < 256; base += 32) {
            uint32_t r[32];
            LDTM_X32(r, tmem + base);
            TCGEN05_WAIT_LD();
            float* crow = C + (size_t)row * N + n0 + base;
            const float* bp = bias + n0 + base;
#pragma unroll
            for (int j = 0; j < 32; j += 4) {
                float4 o = make_float4(__uint_as_float(r[j])   + bp[j],
                                       __uint_as_float(r[j+1]) + bp[j+1],
                                       __uint_as_float(r[j+2]) + bp[j+2],
                                       __uint_as_float(r[j+3]) + bp[j+3]);
                *(float4*)(crow + j) = o;
            }
        }
    }
    __syncthreads();
    if (wid == 0) TCGEN05_DEALLOC(tmem, 256);
#else
    const int tid = threadIdx.x;
    for (int idx = blockIdx.x * 256 + blockIdx.y * 256 * gridDim.x + tid;
         idx < M * N; idx += gridDim.x * gridDim.y * 256) {
        int row = idx / N, col = idx % N;
        float acc = bias ? bias[col] : 0.f;
        for (int k = 0; k < K; k++)
            acc += __bfloat162float(Ahi[(size_t)row*K+k]) * __bfloat162float(Bthi[(size_t)col*K+k]);
        C[idx] = acc;
    }
#endif
}

// ---------------- tcgen05 flash attention (S double-buffered) ---------------
#define ASM_TPTR 0
#define ASM_MBS0 8
#define ASM_MBS1 16
#define ASM_MBPV 24
#define ASM_QH   1024
#define ASM_QL   (ASM_QH + 16384)
#define ASM_K0H  (ASM_QL + 16384)
#define ASM_K0L  (ASM_K0H + 16384)
#define ASM_K1H  (ASM_K0L + 16384)
#define ASM_K1L  (ASM_K1H + 16384)
#define ASM_V    (ASM_K1L + 16384)         // 3 x 16KB
#define ASM_P    (ASM_V + 49152)           // 32KB
#define ASM_LP   (ASM_P + 32768)
#define ATT_SMEM (ASM_LP + 1024)           // 182272
#define IDESC_S      0x8200490u            // M=128 N=128 bf16->f32
#define IDESC_PV_F16 0x8100010u            // M=128 N=64  f16->f32
// TMEM: S0 @0, S1 @128, O @256

__global__ __launch_bounds__(256) void attn_tc()
{
#if HAS_TC
    extern __shared__ char smem[];
    const uint32_t sb = smem_u32(smem);
    const int tid = threadIdx.x;
    const int w = tid >> 5, lid = tid & 31;
    const int bh = blockIdx.y;
    const int qt = gridDim.x - 1 - blockIdx.x;
    const int q0 = qt * 128;
    const int r  = (w & 3) * 32 + lid;
    const int ch = w >> 2;

    const char* qh = (const char*)(g_qh + (size_t)bh*TT*HDIM);
    const char* ql = (const char*)(g_ql + (size_t)bh*TT*HDIM);
    const char* kh = (const char*)(g_kh + (size_t)bh*TT*HDIM);
    const char* kl = (const char*)(g_kl + (size_t)bh*TT*HDIM);
    const char* vt = (const char*)(g_vt + (size_t)bh*HDIM*TT);

    if (w == 0) { TCGEN05_ALLOC(sb + ASM_TPTR, 512); TCGEN05_RELINQ(); }
    if (tid == 0) {
        MBARRIER_INIT(sb + ASM_MBS0, 1);
        MBARRIER_INIT(sb + ASM_MBS1, 1);
        MBARRIER_INIT(sb + ASM_MBPV, 1);
    }

    // Q tile
#pragma unroll
    for (int p = 0; p < 4; p++) {
        int i = tid + p*256; int rr = i >> 3; int c16 = (i & 7) << 4;
        uint32_t so = SMEM_SWIZZLE_128B(rr*128 + c16);
        *(uint4*)(smem + ASM_QH + so) = *(const uint4*)(qh + (size_t)(q0+rr)*128 + c16);
        *(uint4*)(smem + ASM_QL + so) = *(const uint4*)(ql + (size_t)(q0+rr)*128 + c16);
    }
    // K/V(0)
    {
#pragma unroll
        for (int p = 0; p < 4; p++) {
            int i = tid + p*256; int rr = i >> 3; int c16 = (i & 7) << 4;
            uint32_t so = SMEM_SWIZZLE_128B(rr*128 + c16);
            CP_ASYNC16(sb + ASM_K0H + so, kh + (size_t)rr*128 + c16);
            CP_ASYNC16(sb + ASM_K0L + so, kl + (size_t)rr*128 + c16);
        }
#pragma unroll
        for (int p = 0; p < 4; p++) {
            int i = tid + p*256; int d = i >> 4; int j = i & 15;
            uint32_t bo = (uint32_t)((((d>>3) + (j>>3)*8) << 10) + ((d & 7) << 7) + ((j & 7) << 4));
            CP_ASYNC16(sb + ASM_V + SMEM_SWIZZLE_128B(bo), vt + ((size_t)d*TT + j*8)*2);
        }
        CP_COMMIT();
    }
    CP_WAIT0();
    FENCE_PROXY_ASYNC();
    __syncthreads();
    uint32_t tmem;
    asm volatile("ld.shared.b32 %0, [%1];" : "=r"(tmem) : "r"(sb + ASM_TPTR));

    const uint64_t dQh = MAKE_SMEM_DESC(sb+ASM_QH), dQl = MAKE_SMEM_DESC(sb+ASM_QL);
    const uint64_t dP  = MAKE_SMEM_DESC(sb+ASM_P);
    const uint64_t dK[2][2] = {
        { MAKE_SMEM_DESC(sb+ASM_K0H), MAKE_SMEM_DESC(sb+ASM_K0L) },
        { MAKE_SMEM_DESC(sb+ASM_K1H), MAKE_SMEM_DESC(sb+ASM_K1L) } };
    const uint32_t mbS[2] = { sb + ASM_MBS0, sb + ASM_MBS1 };

    // S(0) -> commit to MBS0
    if (w == 0 && elect_one()) {
#pragma unroll
        for (int ks = 0; ks < 4; ks++) {
            mma_f16_ss_cg1(tmem, dQh + ks*2, dK[0][0] + ks*2, IDESC_S, ks > 0);
            mma_f16_ss_cg1(tmem, dQh + ks*2, dK[0][1] + ks*2, IDESC_S, 1u);
            mma_f16_ss_cg1(tmem, dQl + ks*2, dK[0][0] + ks*2, IDESC_S, 1u);
        }
        TCGEN05_COMMIT(mbS[0]);
    }
    // prefetch K/V(1)
    if (qt > 0) {
#pragma unroll
        for (int p = 0; p < 4; p++) {
            int i = tid + p*256; int rr = i >> 3; int c16 = (i & 7) << 4;
            uint32_t so = SMEM_SWIZZLE_128B(rr*128 + c16);
            CP_ASYNC16(sb + ASM_K1H + so, kh + (size_t)(128+rr)*128 + c16);
            CP_ASYNC16(sb + ASM_K1L + so, kl + (size_t)(128+rr)*128 + c16);
        }
#pragma unroll
        for (int p = 0; p < 4; p++) {
            int i = tid + p*256; int d = i >> 4; int j = i & 15;
            uint32_t bo = (uint32_t)((((d>>3) + (j>>3)*8) << 10) + ((d & 7) << 7) + ((j & 7) << 4));
            CP_ASYNC16(sb + ASM_V + 16384 + SMEM_SWIZZLE_128B(bo),
                       vt + ((size_t)d*TT + 128 + j*8)*2);
        }
        CP_COMMIT();
    }

    float lsum = 0.f;
    const uint32_t prow = (uint32_t)((((r>>3) + ch*16) << 10) + ((r & 7) << 7));

    for (int kt = 0; kt <= qt; kt++) {
        const int buf = kt & 1;

        // 1-2) K/V(kt+1) ready -> issue S(kt+1) into the other TMEM buffer
        if (kt < qt) {
            CP_WAIT0();
            FENCE_PROXY_ASYNC();
            __syncthreads();
            if (w == 0 && elect_one()) {
                const int nb = (kt + 1) & 1;
#pragma unroll
                for (int ks = 0; ks < 4; ks++) {
                    mma_f16_ss_cg1(tmem + nb*128, dQh + ks*2, dK[nb][0] + ks*2, IDESC_S, ks > 0);
                    mma_f16_ss_cg1(tmem + nb*128, dQh + ks*2, dK[nb][1] + ks*2, IDESC_S, 1u);
                    mma_f16_ss_cg1(tmem + nb*128, dQl + ks*2, dK[nb][0] + ks*2, IDESC_S, 1u);
                }
                TCGEN05_COMMIT(mbS[nb]);   // per-buffer barrier: <=1 phase in flight
            }
        }

        // 3) P buffer free (PV(kt-1) retired)
        if (kt > 0) MBARRIER_WAIT_PARITY(sb + ASM_MBPV, (kt-1) & 1);

        // 4) S(kt) ready — wait on buffer-kt&1 barrier, phase kt>>1
        MBARRIER_WAIT_PARITY(mbS[buf], (kt >> 1) & 1);
        TCGEN05_FENCE_AFTER();

        // 5) softmax epilogue -> fp16 P
        const bool diag = (kt == qt);
#pragma unroll
        for (int cb = 0; cb < 64; cb += 32) {
            uint32_t sreg[32];
            LDTM_X32(sreg, tmem + buf*128 + ch*64 + cb);
            TCGEN05_WAIT_LD();
            uint32_t hp[16];
#pragma unroll
            for (int j2 = 0; j2 < 16; j2++) {
                float e0 = __expf(__uint_as_float(sreg[2*j2])   * ATT_SCALE);
                float e1 = __expf(__uint_as_float(sreg[2*j2+1]) * ATT_SCALE);
                if (diag) {
                    int c = ch*64 + cb + 2*j2;
                    if (c     > r) e0 = 0.f;
                    if (c + 1 > r) e1 = 0.f;
                }
                lsum += e0 + e1;
                __half2 hh = __floats2half2_rn(e0, e1);
                hp[j2] = *(uint32_t*)&hh;
            }
#pragma unroll
            for (int k4 = 0; k4 < 4; k4++) {
                uint32_t so = SMEM_SWIZZLE_128B(prow + cb*2 + k4*16);
                *(uint4*)(smem + ASM_P + so) = ((uint4*)hp)[k4];
            }
        }

        // 6) prefetch K/V(kt+2): K buf (kt&1) free (S(kt) done), V slot (kt+2)%3
        if (kt + 2 <= qt) {
            const int k2 = (kt + 2) * 128;
            const uint32_t nKH = sb + (buf ? ASM_K1H : ASM_K0H);
            const uint32_t nKL = sb + (buf ? ASM_K1L : ASM_K0L);
            const uint32_t nV  = sb + ASM_V + ((kt + 2) % 3) * 16384;
#pragma unroll
            for (int p = 0; p < 4; p++) {
                int i = tid + p*256; int rr = i >> 3; int c16 = (i & 7) << 4;
                uint32_t so = SMEM_SWIZZLE_128B(rr*128 + c16);
                CP_ASYNC16(nKH + so, kh + (size_t)(k2+rr)*128 + c16);
                CP_ASYNC16(nKL + so, kl + (size_t)(k2+rr)*128 + c16);
            }
#pragma unroll
            for (int p = 0; p < 4; p++) {
                int i = tid + p*256; int d = i >> 4; int j = i & 15;
                uint32_t bo = (uint32_t)((((d>>3) + (j>>3)*8) << 10) + ((d & 7) << 7) + ((j & 7) << 4));
                CP_ASYNC16(nV + SMEM_SWIZZLE_128B(bo), vt + ((size_t)d*TT + k2 + j*8)*2);
            }
            CP_COMMIT();
        }

        // 7) P visible to MMA
        FENCE_PROXY_ASYNC();
        TCGEN05_FENCE_BEFORE();
        __syncthreads();

        // 8) O += P V
        if (w == 0 && elect_one()) {
            const uint64_t dV = MAKE_SMEM_DESC(sb + ASM_V + (kt % 3) * 16384);
#pragma unroll
            for (int ks = 0; ks < 8; ks++) {
                uint32_t po = (ks < 4) ? ks*2 : 1024 + (ks-4)*2;
                uint32_t vo = (ks < 4) ? ks*2 : 512  + (ks-4)*2;
                uint32_t en0 = (kt > 0 || ks > 0) ? 1u : 0u;
                mma_f16_ss_cg1(tmem + 256, dP + po, dV + vo, IDESC_PV_F16, en0);
            }
            TCGEN05_COMMIT(sb + ASM_MBPV);
        }
    }
    CP_WAIT0();
    MBARRIER_WAIT_PARITY(sb + ASM_MBPV, qt & 1);
    TCGEN05_FENCE_AFTER();

    // O epilogue
    *(float*)(smem + ASM_LP + (ch*128 + r)*4) = lsum;
    __syncthreads();
    {
        uint32_t oreg[32];
        LDTM_X32(oreg, tmem + 256 + ch*32);
        TCGEN05_WAIT_LD();
        float lt = *(float*)(smem + ASM_LP + r*4)
                 + *(float*)(smem + ASM_LP + (128 + r)*4);
        float inv = 1.f / lt;
        const int b2 = bh / HH, h2 = bh % HH;
        size_t oo = ((size_t)(b2*TT + q0 + r)*DD + h2*HDIM + ch*32) * 2;
        uint32_t hp[16], lp[16];
#pragma unroll
        for (int j2 = 0; j2 < 16; j2++) {
            float e0 = __uint_as_float(oreg[2*j2])   * inv;
            float e1 = __uint_as_float(oreg[2*j2+1]) * inv;
            __nv_bfloat16 h0 = __float2bfloat16(e0), h1 = __float2bfloat16(e1);
            __nv_bfloat16 l0 = __float2bfloat16(e0 - __bfloat162float(h0));
            __nv_bfloat16 l1 = __float2bfloat16(e1 - __bfloat162float(h1));
            __nv_bfloat162 hh = __halves2bfloat162(h0, h1);
            __nv_bfloat162 ll = __halves2bfloat162(l0, l1);
            hp[j2] = *(uint32_t*)&hh; lp[j2] = *(uint32_t*)&ll;
        }
#pragma unroll
        for (int k4 = 0; k4 < 4; k4++) {
            *(uint4*)((char*)g_ahi + oo + k4*16) = ((uint4*)hp)[k4];
            *(uint4*)((char*)g_alo + oo + k4*16) = ((uint4*)lp)[k4];
        }
    }
    __syncthreads();
    if (w == 0) TCGEN05_DEALLOC(tmem, 512);
#endif
}

// ---------------------------------------------------------------------------
extern "C" void kernel_launch(void* const* d_in, const int* in_sizes, int n_in,
                              void* d_out, int out_size)
{
    const float* x     = (const float*)d_in[0];
    const float* W_qkv = (const float*)d_in[1];
    const float* b_qkv = (const float*)d_in[2];
    const float* W_out = (const float*)d_in[3];
    const float* b_out = (const float*)d_in[4];
    float* out = (float*)d_out;

    void* p;
    cudaGetSymbolAddress(&p, g_qkv);    float* qkv = (float*)p;
    cudaGetSymbolAddress(&p, g_xhi);    __nv_bfloat16* xhi = (__nv_bfloat16*)p;
    cudaGetSymbolAddress(&p, g_xlo);    __nv_bfloat16* xlo = (__nv_bfloat16*)p;
    cudaGetSymbolAddress(&p, g_ahi);    __nv_bfloat16* ahi = (__nv_bfloat16*)p;
    cudaGetSymbolAddress(&p, g_alo);    __nv_bfloat16* alo = (__nv_bfloat16*)p;
    cudaGetSymbolAddress(&p, g_wqt_hi); __nv_bfloat16* wqh = (__nv_bfloat16*)p;
    cudaGetSymbolAddress(&p, g_wqt_lo); __nv_bfloat16* wql = (__nv_bfloat16*)p;
    cudaGetSymbolAddress(&p, g_wot_hi); __nv_bfloat16* woh = (__nv_bfloat16*)p;
    cudaGetSymbolAddress(&p, g_wot_lo); __nv_bfloat16* wol = (__nv_bfloat16*)p;

    const int M = BB * TT;  // 8192

    {
        int n4 = M * DD / 4;
        split_hl<<<(n4 + 255) / 256, 256>>>(x, xhi, xlo, n4);
        tsplit_kernel<<<dim3(DD/32, QKV3/32), dim3(32, 8)>>>(W_qkv, wqh, wql, DD, QKV3);
        tsplit_kernel<<<dim3(DD/32, DD/32),   dim3(32, 8)>>>(W_out, woh, wol, DD, DD);
    }

    cudaFuncSetAttribute(gemm_any, cudaFuncAttributeMaxDynamicSharedMemorySize, GEMM_SMEM);

    // 1) QKV projection: N = 2304 = 9 x 256
    gemm_any<<<dim3(QKV3/256, M/128), 256, GEMM_SMEM>>>(
        x, W_qkv, xhi, xlo, wqh, wql, b_qkv, qkv, M, QKV3, DD);

    // 2) per-head planes
    prep_split<<<dim3(TT/64, BB*HH), 256>>>();

    // 3) attention
    cudaFuncSetAttribute(attn_tc, cudaFuncAttributeMaxDynamicSharedMemorySize, ATT_SMEM);
    attn_tc<<<dim3(TT/128, BB*HH), 256, ATT_SMEM>>>();

    // 4) output projection: N = 768 = 3 x 256
    gemm_any<<<dim3(DD/256, M/128), 256, GEMM_SMEM>>>(
        nullptr, nullptr, ahi, alo, woh, wol, b_out, out, M, DD, DD);
}

// round 8
// speedup vs baseline: 13.6214x; 1.2237x over previous
#include <cuda_runtime.h>
#include <cuda_bf16.h>
#include <cuda_fp16.h>
#include <math.h>
#include <cstdint>

#define BB   2
#define TT   4096
#define DD   768
#define HH   12
#define HDIM 64
#define QKV3 (3*DD)       // 2304
#define ATT_SCALE 0.125f  // 1/sqrt(64)

#if !defined(__CUDA_ARCH__)
#define HAS_TC 1
#elif defined(__CUDA_ARCH_FEAT_SM103_ALL)
#define HAS_TC 1
#elif defined(__CUDA_ARCH_SPECIFIC__) && (__CUDA_ARCH_SPECIFIC__ == 1030)
#define HAS_TC 1
#elif defined(__CUDA_ARCH_FAMILY_SPECIFIC__) && (__CUDA_ARCH_FAMILY_SPECIFIC__ >= 1000)
#define HAS_TC 1
#else
#define HAS_TC 0
#endif

// ---------------- scratch ----------------
__device__ __nv_bfloat16 g_xhi [(size_t)BB*TT*DD];
__device__ __nv_bfloat16 g_xlo [(size_t)BB*TT*DD];
__device__ __nv_bfloat16 g_ahi [(size_t)BB*TT*DD];
__device__ __nv_bfloat16 g_alo [(size_t)BB*TT*DD];
__device__ __nv_bfloat16 g_wqt_hi[(size_t)QKV3*DD];
__device__ __nv_bfloat16 g_wqt_lo[(size_t)QKV3*DD];
__device__ __nv_bfloat16 g_wot_hi[(size_t)DD*DD];
__device__ __nv_bfloat16 g_wot_lo[(size_t)DD*DD];
__device__ __nv_bfloat16 g_qh [(size_t)BB*HH*TT*HDIM];   // [bh][t][d]
__device__ __nv_bfloat16 g_ql [(size_t)BB*HH*TT*HDIM];
__device__ __nv_bfloat16 g_kh [(size_t)BB*HH*TT*HDIM];
__device__ __nv_bfloat16 g_kl [(size_t)BB*HH*TT*HDIM];
__device__ __half        g_vt [(size_t)BB*HH*HDIM*TT];   // [bh][d][t]

// ---------------- helpers ----------------
__device__ __forceinline__ uint32_t smem_u32(const void* p) {
    uint32_t a;
    asm("{ .reg .u64 t; cvta.to.shared.u64 t, %1; cvt.u32.u64 %0, t; }"
        : "=r"(a) : "l"(p));
    return a;
}
#define SMEM_SWIZZLE_128B(off) ((off) ^ (((off) >> 3) & 0x70))

#if HAS_TC
__device__ __forceinline__ uint32_t elect_one() {
    uint32_t pred;
    asm volatile("{\n\t.reg .pred p;\n\telect.sync _|p, 0xFFFFFFFF;\n\t"
                 "selp.b32 %0, 1, 0, p;\n\t}" : "=r"(pred));
    return pred;
}
static constexpr uint64_t SMEM_DESC_BASE_SW128 =
    (uint64_t(2) << 61) | (uint64_t(1) << 46) | (uint64_t(64) << 32) | (uint64_t(1) << 16);
#define MAKE_SMEM_DESC(addr) (SMEM_DESC_BASE_SW128 | ((uint64_t)((addr) >> 4) & 0x3FFF))

#define TCGEN05_ALLOC(sa, n) \
    asm volatile("tcgen05.alloc.cta_group::1.sync.aligned.shared::cta.b32 [%0], %1;" \
                 :: "r"((uint32_t)(sa)), "r"((uint32_t)(n)) : "memory")
#define TCGEN05_DEALLOC(t, n) \
    asm volatile("tcgen05.dealloc.cta_group::1.sync.aligned.b32 %0, %1;" :: "r"(t), "r"(n))
#define TCGEN05_RELINQ() \
    asm volatile("tcgen05.relinquish_alloc_permit.cta_group::1.sync.aligned;")
#define TCGEN05_COMMIT(mb) \
    asm volatile("tcgen05.commit.cta_group::1.mbarrier::arrive::one.shared::cluster.b64 [%0];" \
                 :: "r"((uint32_t)(mb)) : "memory")
#define TCGEN05_FENCE_AFTER() \
    asm volatile("tcgen05.fence::after_thread_sync;" ::: "memory")
#define TCGEN05_FENCE_BEFORE() \
    asm volatile("tcgen05.fence::before_thread_sync;" ::: "memory")
#define TCGEN05_WAIT_LD() \
    asm volatile("tcgen05.wait::ld.sync.aligned;" ::: "memory")
#define FENCE_PROXY_ASYNC() \
    asm volatile("fence.proxy.async.shared::cta;" ::: "memory")
#define MBARRIER_INIT(mb, cnt) \
    asm volatile("mbarrier.init.shared.b64 [%0], %1;" \
                 :: "r"((uint32_t)(mb)), "r"((uint32_t)(cnt)) : "memory")
#define MBARRIER_WAIT_PARITY(mb, ph) do {                                   \
    uint32_t _m = (uint32_t)(mb); uint32_t _p = (uint32_t)(ph);             \
    asm volatile("{\n\t.reg .pred P1;\n\t"                                  \
        "WL_%=:\n\t"                                                        \
        "mbarrier.try_wait.parity.acquire.cta.shared::cta.b64 P1, [%0], %1, 0x989680;\n\t" \
        "@P1 bra.uni WD_%=;\n\t"                                            \
        "bra.uni WL_%=;\n\t"                                                \
        "WD_%=:\n\t}" :: "r"(_m), "r"(_p) : "memory");                      \
} while (0)
#define CP_ASYNC16(dst, src) \
    asm volatile("cp.async.cg.shared.global [%0], [%1], 16;" \
                 :: "r"((uint32_t)(dst)), "l"(src) : "memory")
#define CP_COMMIT() asm volatile("cp.async.commit_group;" ::: "memory")
#define CP_WAIT0()  asm volatile("cp.async.wait_group 0;" ::: "memory")

__device__ __forceinline__ void mma_f16_ss_cg1(
    uint32_t d_tmem, uint64_t a_desc, uint64_t b_desc, uint32_t idesc, uint32_t en)
{
    asm volatile(
        "{\n\t.reg .pred p;\n\tsetp.ne.u32 p, %5, 0;\n\t"
        "tcgen05.mma.cta_group::1.kind::f16 [%0], %1, %2, %3, {%4, %4, %4, %4}, p;\n\t}"
        :: "r"(d_tmem), "l"(a_desc), "l"(b_desc), "r"(idesc), "r"(0u), "r"(en)
        : "memory");
}
#define LDTM_X32(r, addr)                                                    \
    asm volatile("tcgen05.ld.sync.aligned.32x32b.x32.b32 "                   \
        "{%0, %1, %2, %3, %4, %5, %6, %7, %8, %9, %10, %11, %12, %13, %14, %15, " \
        " %16, %17, %18, %19, %20, %21, %22, %23, %24, %25, %26, %27, %28, %29, %30, %31}, [%32];" \
        : "=r"((r)[0]),  "=r"((r)[1]),  "=r"((r)[2]),  "=r"((r)[3]),         \
          "=r"((r)[4]),  "=r"((r)[5]),  "=r"((r)[6]),  "=r"((r)[7]),         \
          "=r"((r)[8]),  "=r"((r)[9]),  "=r"((r)[10]), "=r"((r)[11]),        \
          "=r"((r)[12]), "=r"((r)[13]), "=r"((r)[14]), "=r"((r)[15]),        \
          "=r"((r)[16]), "=r"((r)[17]), "=r"((r)[18]), "=r"((r)[19]),        \
          "=r"((r)[20]), "=r"((r)[21]), "=r"((r)[22]), "=r"((r)[23]),        \
          "=r"((r)[24]), "=r"((r)[25]), "=r"((r)[26]), "=r"((r)[27]),        \
          "=r"((r)[28]), "=r"((r)[29]), "=r"((r)[30]), "=r"((r)[31])         \
        : "r"(addr))
#endif  // HAS_TC

// ---------------- prep kernels ----------------
__global__ __launch_bounds__(256) void split_hl(
    const float* __restrict__ src, __nv_bfloat16* __restrict__ hi,
    __nv_bfloat16* __restrict__ lo, int n4)
{
    int i = blockIdx.x * 256 + threadIdx.x;
    if (i >= n4) return;
    float4 v = ((const float4*)src)[i];
    float vs[4] = {v.x, v.y, v.z, v.w};
    __nv_bfloat16 h[4], l[4];
#pragma unroll
    for (int j = 0; j < 4; j++) {
        h[j] = __float2bfloat16(vs[j]);
        l[j] = __float2bfloat16(vs[j] - __bfloat162float(h[j]));
    }
    ((__nv_bfloat162*)hi)[2*i]   = __halves2bfloat162(h[0], h[1]);
    ((__nv_bfloat162*)hi)[2*i+1] = __halves2bfloat162(h[2], h[3]);
    ((__nv_bfloat162*)lo)[2*i]   = __halves2bfloat162(l[0], l[1]);
    ((__nv_bfloat162*)lo)[2*i+1] = __halves2bfloat162(l[2], l[3]);
}

__global__ void tsplit_kernel(
    const float* __restrict__ W, __nv_bfloat16* __restrict__ Thi,
    __nv_bfloat16* __restrict__ Tlo, int K, int N)
{
    __shared__ float t[32][33];
    int kb = blockIdx.x * 32, nb = blockIdx.y * 32;
    int tx = threadIdx.x, ty = threadIdx.y;
#pragma unroll
    for (int i = 0; i < 4; i++) {
        int k = ty + i * 8;
        t[k][tx] = W[(size_t)(kb + k) * N + nb + tx];
    }
    __syncthreads();
#pragma unroll
    for (int i = 0; i < 4; i++) {
        int nr = ty + i * 8;
        float v = t[tx][nr];
        __nv_bfloat16 h = __float2bfloat16(v);
        __nv_bfloat16 l = __float2bfloat16(v - __bfloat162float(h));
        size_t o = (size_t)(nb + nr) * K + kb + tx;
        Thi[o] = h; Tlo[o] = l;
    }
}

// ---------------- tcgen05 GEMM: 128x256 tile, single buffer, 2 CTA/SM ------
// mode 0: C fp32 + bias.  mode 1: fused qkv epilogue -> split planes + g_vt.
#define GB_AH 0
#define GB_AL 16384
#define GB_BH 32768
#define GB_BL 65536
#define GB_SZ 98304
#define GSM_BUF 1024
#define GEMM_SMEM (GSM_BUF + GB_SZ)      // 99328 -> 2 CTAs/SM
#define GEMM_IDESC 0x8400490u            // f32 acc, bf16xbf16, M=128, N=256

#if HAS_TC
__device__ __forceinline__ void gemm_prefetch(
    uint32_t sbuf, const char* Ah, const char* Al, const char* Bh, const char* Bl,
    int K, int m0, int n0, int k0, int tid)
{
#pragma unroll
    for (int p = 0; p < 4; p++) {           // A: 128 rows x 128B x 2 planes
        int i = tid + p * 256;
        int r = i >> 3, c16 = (i & 7) << 4;
        uint32_t so = SMEM_SWIZZLE_128B(r * 128 + c16);
        size_t go = ((size_t)(m0 + r) * K + k0) * 2 + c16;
        CP_ASYNC16(sbuf + GB_AH + so, Ah + go);
        CP_ASYNC16(sbuf + GB_AL + so, Al + go);
    }
#pragma unroll
    for (int p = 0; p < 8; p++) {           // B: 256 rows x 128B x 2 planes
        int i = tid + p * 256;
        int r = i >> 3, c16 = (i & 7) << 4;
        uint32_t so = SMEM_SWIZZLE_128B(r * 128 + c16);
        size_t go = ((size_t)(n0 + r) * K + k0) * 2 + c16;
        CP_ASYNC16(sbuf + GB_BH + so, Bh + go);
        CP_ASYNC16(sbuf + GB_BL + so, Bl + go);
    }
}
#endif

__global__ __launch_bounds__(256) void gemm_any(
    const __nv_bfloat16* __restrict__ Ahi, const __nv_bfloat16* __restrict__ Alo,
    const __nv_bfloat16* __restrict__ Bthi, const __nv_bfloat16* __restrict__ Btlo,
    const float* __restrict__ bias, float* __restrict__ C,
    int M, int N, int K, int mode)
{
    extern __shared__ char smem[];
#if HAS_TC
    const uint32_t sb = smem_u32(smem);
    const int tid = threadIdx.x;
    const int wid = tid >> 5, lid = tid & 31;
    const int m0 = blockIdx.y * 128, n0 = blockIdx.x * 256;
    const char* Ah = (const char*)Ahi;  const char* Al = (const char*)Alo;
    const char* Bh = (const char*)Bthi; const char* Bl = (const char*)Btlo;

    if (wid == 0) { TCGEN05_ALLOC(sb, 256); TCGEN05_RELINQ(); }
    if (tid == 0) MBARRIER_INIT(sb + 8, 1);
    __syncthreads();
    uint32_t tmem;
    asm volatile("ld.shared.b32 %0, [%1];" : "=r"(tmem) : "r"(sb));

    const uint64_t dAh = MAKE_SMEM_DESC(sb + GSM_BUF + GB_AH);
    const uint64_t dAl = MAKE_SMEM_DESC(sb + GSM_BUF + GB_AL);
    const uint64_t dBh = MAKE_SMEM_DESC(sb + GSM_BUF + GB_BH);
    const uint64_t dBl = MAKE_SMEM_DESC(sb + GSM_BUF + GB_BL);

    const int nchunks = K >> 6;   // 12
    for (int c = 0; c < nchunks; c++) {
        gemm_prefetch(sb + GSM_BUF, Ah, Al, Bh, Bl, K, m0, n0, c * 64, tid);
        CP_COMMIT();
        CP_WAIT0();
        __syncthreads();

        if (wid == 0 && elect_one()) {
#pragma unroll
            for (int ks = 0; ks < 4; ks++) {
                uint32_t en0 = (c > 0 || ks > 0) ? 1u : 0u;
                mma_f16_ss_cg1(tmem, dAh + ks*2, dBh + ks*2, GEMM_IDESC, en0);
                mma_f16_ss_cg1(tmem, dAh + ks*2, dBl + ks*2, GEMM_IDESC, 1u);
                mma_f16_ss_cg1(tmem, dAl + ks*2, dBh + ks*2, GEMM_IDESC, 1u);
            }
            TCGEN05_COMMIT(sb + 8);
        }
        MBARRIER_WAIT_PARITY(sb + 8, c & 1);   // buffer reusable next chunk
    }

    TCGEN05_FENCE_AFTER();
    if (wid < 4) {
        const int row = m0 + wid * 32 + lid;
        const int b  = row >> 12;           // row / 4096
        const int t  = row & 4095;
#pragma unroll
        for (int base = 0; base < 256; base += 32) {
            uint32_t rg[32];
            LDTM_X32(rg, tmem + base);
            TCGEN05_WAIT_LD();
            const int col0 = n0 + base;
            const float* bp = bias + col0;
            if (mode == 0) {
                float* crow = C + (size_t)row * N + col0;
#pragma unroll
                for (int j = 0; j < 32; j += 4) {
                    float4 o = make_float4(__uint_as_float(rg[j])   + bp[j],
                                           __uint_as_float(rg[j+1]) + bp[j+1],
                                           __uint_as_float(rg[j+2]) + bp[j+2],
                                           __uint_as_float(rg[j+3]) + bp[j+3]);
                    *(float4*)(crow + j) = o;
                }
            } else {
                const int sec  = col0 / DD;          // 0=q 1=k 2=v
                const int rcol = col0 - sec * DD;
                const int h    = rcol >> 6;
                const int d0   = rcol & 63;          // 0 or 32
                const int bh   = b * HH + h;
                if (sec < 2) {
                    __nv_bfloat16* dh = (sec ? g_kh : g_qh);
                    __nv_bfloat16* dl = (sec ? g_kl : g_ql);
                    size_t off = (((size_t)bh * TT + t) << 6) + d0;
                    uint32_t hp[16], lp[16];
#pragma unroll
                    for (int j2 = 0; j2 < 16; j2++) {
                        float v0 = __uint_as_float(rg[2*j2])   + bp[2*j2];
                        float v1 = __uint_as_float(rg[2*j2+1]) + bp[2*j2+1];
                        __nv_bfloat16 h0 = __float2bfloat16(v0), h1 = __float2bfloat16(v1);
                        __nv_bfloat16 l0 = __float2bfloat16(v0 - __bfloat162float(h0));
                        __nv_bfloat16 l1 = __float2bfloat16(v1 - __bfloat162float(h1));
                        __nv_bfloat162 hh = __halves2bfloat162(h0, h1);
                        __nv_bfloat162 ll = __halves2bfloat162(l0, l1);
                        hp[j2] = *(uint32_t*)&hh; lp[j2] = *(uint32_t*)&ll;
                    }
#pragma unroll
                    for (int k4 = 0; k4 < 4; k4++) {
                        *(uint4*)((char*)dh + off*2 + k4*16) = ((uint4*)hp)[k4];
                        *(uint4*)((char*)dl + off*2 + k4*16) = ((uint4*)lp)[k4];
                    }
                } else {
                    __half* dst = g_vt + (((size_t)bh << 6) + d0) * TT + t;
#pragma unroll
                    for (int j = 0; j < 32; j++)
                        dst[(size_t)j * TT] = __float2half(__uint_as_float(rg[j]) + bp[j]);
                }
            }
        }
    }
    __syncthreads();
    if (wid == 0) TCGEN05_DEALLOC(tmem, 256);
#else
    // non-'a' PTX fallback (never executes on sm_103a SASS)
    const int tid = threadIdx.x;
    for (int idx = (blockIdx.y * gridDim.x + blockIdx.x) * 256 + tid;
         idx < M * N; idx += gridDim.x * gridDim.y * 256) {
        int row = idx / N, col = idx % N;
        float acc = bias[col];
        for (int k = 0; k < K; k++)
            acc += __bfloat162float(Ahi[(size_t)row*K+k]) * __bfloat162float(Bthi[(size_t)col*K+k])
                 + __bfloat162float(Alo[(size_t)row*K+k]) * __bfloat162float(Bthi[(size_t)col*K+k])
                 + __bfloat162float(Ahi[(size_t)row*K+k]) * __bfloat162float(Btlo[(size_t)col*K+k]);
        if (mode == 0) {
            C[idx] = acc;
        } else {
            int b = row >> 12, t = row & 4095;
            int sec = col / DD, rcol = col - sec * DD;
            int h = rcol >> 6, d = rcol & 63, bh = b * HH + h;
            if (sec < 2) {
                __nv_bfloat16 hv = __float2bfloat16(acc);
                __nv_bfloat16 lv = __float2bfloat16(acc - __bfloat162float(hv));
                size_t off = (((size_t)bh * TT + t) << 6) + d;
                (sec ? g_kh : g_qh)[off] = hv;
                (sec ? g_kl : g_ql)[off] = lv;
            } else {
                g_vt[(((size_t)bh << 6) + d) * TT + t] = __float2half(acc);
            }
        }
    }
#endif
}

// ---------------- tcgen05 flash attention (S double-buffered) ---------------
#define ASM_TPTR 0
#define ASM_MBS0 8
#define ASM_MBS1 16
#define ASM_MBPV 24
#define ASM_QH   1024
#define ASM_QL   (ASM_QH + 16384)
#define ASM_K0H  (ASM_QL + 16384)
#define ASM_K0L  (ASM_K0H + 16384)
#define ASM_K1H  (ASM_K0L + 16384)
#define ASM_K1L  (ASM_K1H + 16384)
#define ASM_V    (ASM_K1L + 16384)         // 3 x 16KB
#define ASM_P    (ASM_V + 49152)           // 32KB
#define ASM_LP   (ASM_P + 32768)
#define ATT_SMEM (ASM_LP + 1024)           // 182272
#define IDESC_S      0x8200490u            // M=128 N=128 bf16->f32
#define IDESC_PV_F16 0x8100010u            // M=128 N=64  f16->f32
// TMEM: S0 @0, S1 @128, O @256

__global__ __launch_bounds__(256) void attn_tc()
{
#if HAS_TC
    extern __shared__ char smem[];
    const uint32_t sb = smem_u32(smem);
    const int tid = threadIdx.x;
    const int w = tid >> 5, lid = tid & 31;
    const int bh = blockIdx.y;
    const int qt = gridDim.x - 1 - blockIdx.x;
    const int q0 = qt * 128;
    const int r  = (w & 3) * 32 + lid;
    const int ch = w >> 2;

    const char* qh = (const char*)(g_qh + (size_t)bh*TT*HDIM);
    const char* ql = (const char*)(g_ql + (size_t)bh*TT*HDIM);
    const char* kh = (const char*)(g_kh + (size_t)bh*TT*HDIM);
    const char* kl = (const char*)(g_kl + (size_t)bh*TT*HDIM);
    const char* vt = (const char*)(g_vt + (size_t)bh*HDIM*TT);

    if (w == 0) { TCGEN05_ALLOC(sb + ASM_TPTR, 512); TCGEN05_RELINQ(); }
    if (tid == 0) {
        MBARRIER_INIT(sb + ASM_MBS0, 1);
        MBARRIER_INIT(sb + ASM_MBS1, 1);
        MBARRIER_INIT(sb + ASM_MBPV, 1);
    }

    // Q tile
#pragma unroll
    for (int p = 0; p < 4; p++) {
        int i = tid + p*256; int rr = i >> 3; int c16 = (i & 7) << 4;
        uint32_t so = SMEM_SWIZZLE_128B(rr*128 + c16);
        *(uint4*)(smem + ASM_QH + so) = *(const uint4*)(qh + (size_t)(q0+rr)*128 + c16);
        *(uint4*)(smem + ASM_QL + so) = *(const uint4*)(ql + (size_t)(q0+rr)*128 + c16);
    }
    // K/V(0)
    {
#pragma unroll
        for (int p = 0; p < 4; p++) {
            int i = tid + p*256; int rr = i >> 3; int c16 = (i & 7) << 4;
            uint32_t so = SMEM_SWIZZLE_128B(rr*128 + c16);
            CP_ASYNC16(sb + ASM_K0H + so, kh + (size_t)rr*128 + c16);
            CP_ASYNC16(sb + ASM_K0L + so, kl + (size_t)rr*128 + c16);
        }
#pragma unroll
        for (int p = 0; p < 4; p++) {
            int i = tid + p*256; int d = i >> 4; int j = i & 15;
            uint32_t bo = (uint32_t)((((d>>3) + (j>>3)*8) << 10) + ((d & 7) << 7) + ((j & 7) << 4));
            CP_ASYNC16(sb + ASM_V + SMEM_SWIZZLE_128B(bo), vt + ((size_t)d*TT + j*8)*2);
        }
        CP_COMMIT();
    }
    CP_WAIT0();
    FENCE_PROXY_ASYNC();
    __syncthreads();
    uint32_t tmem;
    asm volatile("ld.shared.b32 %0, [%1];" : "=r"(tmem) : "r"(sb + ASM_TPTR));

    const uint64_t dQh = MAKE_SMEM_DESC(sb+ASM_QH), dQl = MAKE_SMEM_DESC(sb+ASM_QL);
    const uint64_t dP  = MAKE_SMEM_DESC(sb+ASM_P);
    const uint64_t dK[2][2] = {
        { MAKE_SMEM_DESC(sb+ASM_K0H), MAKE_SMEM_DESC(sb+ASM_K0L) },
        { MAKE_SMEM_DESC(sb+ASM_K1H), MAKE_SMEM_DESC(sb+ASM_K1L) } };
    const uint32_t mbS[2] = { sb + ASM_MBS0, sb + ASM_MBS1 };

    // S(0)
    if (w == 0 && elect_one()) {
#pragma unroll
        for (int ks = 0; ks < 4; ks++) {
            mma_f16_ss_cg1(tmem, dQh + ks*2, dK[0][0] + ks*2, IDESC_S, ks > 0);
            mma_f16_ss_cg1(tmem, dQh + ks*2, dK[0][1] + ks*2, IDESC_S, 1u);
            mma_f16_ss_cg1(tmem, dQl + ks*2, dK[0][0] + ks*2, IDESC_S, 1u);
        }
        TCGEN05_COMMIT(mbS[0]);
    }
    // prefetch K/V(1)
    if (qt > 0) {
#pragma unroll
        for (int p = 0; p < 4; p++) {
            int i = tid + p*256; int rr = i >> 3; int c16 = (i & 7) << 4;
            uint32_t so = SMEM_SWIZZLE_128B(rr*128 + c16);
            CP_ASYNC16(sb + ASM_K1H + so, kh + (size_t)(128+rr)*128 + c16);
            CP_ASYNC16(sb + ASM_K1L + so, kl + (size_t)(128+rr)*128 + c16);
        }
#pragma unroll
        for (int p = 0; p < 4; p++) {
            int i = tid + p*256; int d = i >> 4; int j = i & 15;
            uint32_t bo = (uint32_t)((((d>>3) + (j>>3)*8) << 10) + ((d & 7) << 7) + ((j & 7) << 4));
            CP_ASYNC16(sb + ASM_V + 16384 + SMEM_SWIZZLE_128B(bo),
                       vt + ((size_t)d*TT + 128 + j*8)*2);
        }
        CP_COMMIT();
    }

    float lsum = 0.f;
    const uint32_t prow = (uint32_t)((((r>>3) + ch*16) << 10) + ((r & 7) << 7));

    for (int kt = 0; kt <= qt; kt++) {
        const int buf = kt & 1;

        if (kt < qt) {
            CP_WAIT0();
            FENCE_PROXY_ASYNC();
            __syncthreads();
            if (w == 0 && elect_one()) {
                const int nb = (kt + 1) & 1;
#pragma unroll
                for (int ks = 0; ks < 4; ks++) {
                    mma_f16_ss_cg1(tmem + nb*128, dQh + ks*2, dK[nb][0] + ks*2, IDESC_S, ks > 0);
                    mma_f16_ss_cg1(tmem + nb*128, dQh + ks*2, dK[nb][1] + ks*2, IDESC_S, 1u);
                    mma_f16_ss_cg1(tmem + nb*128, dQl + ks*2, dK[nb][0] + ks*2, IDESC_S, 1u);
                }
                TCGEN05_COMMIT(mbS[nb]);
            }
        }

        if (kt > 0) MBARRIER_WAIT_PARITY(sb + ASM_MBPV, (kt-1) & 1);
        MBARRIER_WAIT_PARITY(mbS[buf], (kt >> 1) & 1);
        TCGEN05_FENCE_AFTER();

        const bool diag = (kt == qt);
#pragma unroll
        for (int cb = 0; cb < 64; cb += 32) {
            uint32_t sreg[32];
            LDTM_X32(sreg, tmem + buf*128 + ch*64 + cb);
            TCGEN05_WAIT_LD();
            uint32_t hp[16];
#pragma unroll
            for (int j2 = 0; j2 < 16; j2++) {
                float e0 = __expf(__uint_as_float(sreg[2*j2])   * ATT_SCALE);
                float e1 = __expf(__uint_as_float(sreg[2*j2+1]) * ATT_SCALE);
                if (diag) {
                    int c = ch*64 + cb + 2*j2;
                    if (c     > r) e0 = 0.f;
                    if (c + 1 > r) e1 = 0.f;
                }
                lsum += e0 + e1;
                __half2 hh = __floats2half2_rn(e0, e1);
                hp[j2] = *(uint32_t*)&hh;
            }
#pragma unroll
            for (int k4 = 0; k4 < 4; k4++) {
                uint32_t so = SMEM_SWIZZLE_128B(prow + cb*2 + k4*16);
                *(uint4*)(smem + ASM_P + so) = ((uint4*)hp)[k4];
            }
        }

        if (kt + 2 <= qt) {
            const int k2 = (kt + 2) * 128;
            const uint32_t nKH = sb + (buf ? ASM_K1H : ASM_K0H);
            const uint32_t nKL = sb + (buf ? ASM_K1L : ASM_K0L);
            const uint32_t nV  = sb + ASM_V + ((kt + 2) % 3) * 16384;
#pragma unroll
            for (int p = 0; p < 4; p++) {
                int i = tid + p*256; int rr = i >> 3; int c16 = (i & 7) << 4;
                uint32_t so = SMEM_SWIZZLE_128B(rr*128 + c16);
                CP_ASYNC16(nKH + so, kh + (size_t)(k2+rr)*128 + c16);
                CP_ASYNC16(nKL + so, kl + (size_t)(k2+rr)*128 + c16);
            }
#pragma unroll
            for (int p = 0; p < 4; p++) {
                int i = tid + p*256; int d = i >> 4; int j = i & 15;
                uint32_t bo = (uint32_t)((((d>>3) + (j>>3)*8) << 10) + ((d & 7) << 7) + ((j & 7) << 4));
                CP_ASYNC16(nV + SMEM_SWIZZLE_128B(bo), vt + ((size_t)d*TT + k2 + j*8)*2);
            }
            CP_COMMIT();
        }

        FENCE_PROXY_ASYNC();
        TCGEN05_FENCE_BEFORE();
        __syncthreads();

        if (w == 0 && elect_one()) {
            const uint64_t dV = MAKE_SMEM_DESC(sb + ASM_V + (kt % 3) * 16384);
#pragma unroll
            for (int ks = 0; ks < 8; ks++) {
                uint32_t po = (ks < 4) ? ks*2 : 1024 + (ks-4)*2;
                uint32_t vo = (ks < 4) ? ks*2 : 512  + (ks-4)*2;
                uint32_t en0 = (kt > 0 || ks > 0) ? 1u : 0u;
                mma_f16_ss_cg1(tmem + 256, dP + po, dV + vo, IDESC_PV_F16, en0);
            }
            TCGEN05_COMMIT(sb + ASM_MBPV);
        }
    }
    CP_WAIT0();
    MBARRIER_WAIT_PARITY(sb + ASM_MBPV, qt & 1);
    TCGEN05_FENCE_AFTER();

    *(float*)(smem + ASM_LP + (ch*128 + r)*4) = lsum;
    __syncthreads();
    {
        uint32_t oreg[32];
        LDTM_X32(oreg, tmem + 256 + ch*32);
        TCGEN05_WAIT_LD();
        float lt = *(float*)(smem + ASM_LP + r*4)
                 + *(float*)(smem + ASM_LP + (128 + r)*4);
        float inv = 1.f / lt;
        const int b2 = bh / HH, h2 = bh % HH;
        size_t oo = ((size_t)(b2*TT + q0 + r)*DD + h2*HDIM + ch*32) * 2;
        uint32_t hp[16], lp[16];
#pragma unroll
        for (int j2 = 0; j2 < 16; j2++) {
            float e0 = __uint_as_float(oreg[2*j2])   * inv;
            float e1 = __uint_as_float(oreg[2*j2+1]) * inv;
            __nv_bfloat16 h0 = __float2bfloat16(e0), h1 = __float2bfloat16(e1);
            __nv_bfloat16 l0 = __float2bfloat16(e0 - __bfloat162float(h0));
            __nv_bfloat16 l1 = __float2bfloat16(e1 - __bfloat162float(h1));
            __nv_bfloat162 hh = __halves2bfloat162(h0, h1);
            __nv_bfloat162 ll = __halves2bfloat162(l0, l1);
            hp[j2] = *(uint32_t*)&hh; lp[j2] = *(uint32_t*)&ll;
        }
#pragma unroll
        for (int k4 = 0; k4 < 4; k4++) {
            *(uint4*)((char*)g_ahi + oo + k4*16) = ((uint4*)hp)[k4];
            *(uint4*)((char*)g_alo + oo + k4*16) = ((uint4*)lp)[k4];
        }
    }
    __syncthreads();
    if (w == 0) TCGEN05_DEALLOC(tmem, 512);
#endif
}

// ---------------------------------------------------------------------------
extern "C" void kernel_launch(void* const* d_in, const int* in_sizes, int n_in,
                              void* d_out, int out_size)
{
    const float* x     = (const float*)d_in[0];
    const float* W_qkv = (const float*)d_in[1];
    const float* b_qkv = (const float*)d_in[2];
    const float* W_out = (const float*)d_in[3];
    const float* b_out = (const float*)d_in[4];
    float* out = (float*)d_out;

    void* p;
    cudaGetSymbolAddress(&p, g_xhi);    __nv_bfloat16* xhi = (__nv_bfloat16*)p;
    cudaGetSymbolAddress(&p, g_xlo);    __nv_bfloat16* xlo = (__nv_bfloat16*)p;
    cudaGetSymbolAddress(&p, g_ahi);    __nv_bfloat16* ahi = (__nv_bfloat16*)p;
    cudaGetSymbolAddress(&p, g_alo);    __nv_bfloat16* alo = (__nv_bfloat16*)p;
    cudaGetSymbolAddress(&p, g_wqt_hi); __nv_bfloat16* wqh = (__nv_bfloat16*)p;
    cudaGetSymbolAddress(&p, g_wqt_lo); __nv_bfloat16* wql = (__nv_bfloat16*)p;
    cudaGetSymbolAddress(&p, g_wot_hi); __nv_bfloat16* woh = (__nv_bfloat16*)p;
    cudaGetSymbolAddress(&p, g_wot_lo); __nv_bfloat16* wol = (__nv_bfloat16*)p;

    const int M = BB * TT;  // 8192

    {
        int n4 = M * DD / 4;
        split_hl<<<(n4 + 255) / 256, 256>>>(x, xhi, xlo, n4);
        tsplit_kernel<<<dim3(DD/32, QKV3/32), dim3(32, 8)>>>(W_qkv, wqh, wql, DD, QKV3);
        tsplit_kernel<<<dim3(DD/32, DD/32),   dim3(32, 8)>>>(W_out, woh, wol, DD, DD);
    }

    cudaFuncSetAttribute(gemm_any, cudaFuncAttributeMaxDynamicSharedMemorySize, GEMM_SMEM);

    // 1) QKV projection with fused split/transpose epilogue (mode 1)
    gemm_any<<<dim3(QKV3/256, M/128), 256, GEMM_SMEM>>>(
        xhi, xlo, wqh, wql, b_qkv, nullptr, M, QKV3, DD, 1);

    // 2) attention -> g_ahi/g_alo
    cudaFuncSetAttribute(attn_tc, cudaFuncAttributeMaxDynamicSharedMemorySize, ATT_SMEM);
    attn_tc<<<dim3(TT/128, BB*HH), 256, ATT_SMEM>>>();

    // 3) output projection (mode 0)
    gemm_any<<<dim3(DD/256, M/128), 256, GEMM_SMEM>>>(
        ahi, alo, woh, wol, b_out, out, M, DD, DD, 0);
}

// round 9
// speedup vs baseline: 14.1335x; 1.0376x over previous
#include <cuda_runtime.h>
#include <cuda_bf16.h>
#include <cuda_fp16.h>
#include <math.h>
#include <cstdint>

#define BB   2
#define TT   4096
#define DD   768
#define HH   12
#define HDIM 64
#define QKV3 (3*DD)       // 2304
#define ATT_SCALE 0.125f  // 1/sqrt(64)

#if !defined(__CUDA_ARCH__)
#define HAS_TC 1
#elif defined(__CUDA_ARCH_FEAT_SM103_ALL)
#define HAS_TC 1
#elif defined(__CUDA_ARCH_SPECIFIC__) && (__CUDA_ARCH_SPECIFIC__ == 1030)
#define HAS_TC 1
#elif defined(__CUDA_ARCH_FAMILY_SPECIFIC__) && (__CUDA_ARCH_FAMILY_SPECIFIC__ >= 1000)
#define HAS_TC 1
#else
#define HAS_TC 0
#endif

// ---------------- scratch ----------------
__device__ __nv_bfloat16 g_xhi [(size_t)BB*TT*DD];
__device__ __nv_bfloat16 g_xlo [(size_t)BB*TT*DD];
__device__ __nv_bfloat16 g_ahi [(size_t)BB*TT*DD];
__device__ __nv_bfloat16 g_alo [(size_t)BB*TT*DD];
__device__ __nv_bfloat16 g_wqt_hi[(size_t)QKV3*DD];
__device__ __nv_bfloat16 g_wqt_lo[(size_t)QKV3*DD];
__device__ __nv_bfloat16 g_wot_hi[(size_t)DD*DD];
__device__ __nv_bfloat16 g_wot_lo[(size_t)DD*DD];
__device__ __nv_bfloat16 g_qh [(size_t)BB*HH*TT*HDIM];   // [bh][t][d]
__device__ __nv_bfloat16 g_ql [(size_t)BB*HH*TT*HDIM];
__device__ __nv_bfloat16 g_kh [(size_t)BB*HH*TT*HDIM];
__device__ __nv_bfloat16 g_kl [(size_t)BB*HH*TT*HDIM];
__device__ __half        g_vt [(size_t)BB*HH*HDIM*TT];   // [bh][d][t]

// ---------------- helpers ----------------
__device__ __forceinline__ uint32_t smem_u32(const void* p) {
    uint32_t a;
    asm("{ .reg .u64 t; cvta.to.shared.u64 t, %1; cvt.u32.u64 %0, t; }"
        : "=r"(a) : "l"(p));
    return a;
}
#define SMEM_SWIZZLE_128B(off) ((off) ^ (((off) >> 3) & 0x70))

#if HAS_TC
__device__ __forceinline__ uint32_t elect_one() {
    uint32_t pred;
    asm volatile("{\n\t.reg .pred p;\n\telect.sync _|p, 0xFFFFFFFF;\n\t"
                 "selp.b32 %0, 1, 0, p;\n\t}" : "=r"(pred));
    return pred;
}
static constexpr uint64_t SMEM_DESC_BASE_SW128 =
    (uint64_t(2) << 61) | (uint64_t(1) << 46) | (uint64_t(64) << 32) | (uint64_t(1) << 16);
#define MAKE_SMEM_DESC(addr) (SMEM_DESC_BASE_SW128 | ((uint64_t)((addr) >> 4) & 0x3FFF))

#define TCGEN05_ALLOC(sa, n) \
    asm volatile("tcgen05.alloc.cta_group::1.sync.aligned.shared::cta.b32 [%0], %1;" \
                 :: "r"((uint32_t)(sa)), "r"((uint32_t)(n)) : "memory")
#define TCGEN05_DEALLOC(t, n) \
    asm volatile("tcgen05.dealloc.cta_group::1.sync.aligned.b32 %0, %1;" :: "r"(t), "r"(n))
#define TCGEN05_RELINQ() \
    asm volatile("tcgen05.relinquish_alloc_permit.cta_group::1.sync.aligned;")
#define TCGEN05_COMMIT(mb) \
    asm volatile("tcgen05.commit.cta_group::1.mbarrier::arrive::one.shared::cluster.b64 [%0];" \
                 :: "r"((uint32_t)(mb)) : "memory")
#define TCGEN05_FENCE_AFTER() \
    asm volatile("tcgen05.fence::after_thread_sync;" ::: "memory")
#define TCGEN05_FENCE_BEFORE() \
    asm volatile("tcgen05.fence::before_thread_sync;" ::: "memory")
#define TCGEN05_WAIT_LD() \
    asm volatile("tcgen05.wait::ld.sync.aligned;" ::: "memory")
#define FENCE_PROXY_ASYNC() \
    asm volatile("fence.proxy.async.shared::cta;" ::: "memory")
#define MBARRIER_INIT(mb, cnt) \
    asm volatile("mbarrier.init.shared.b64 [%0], %1;" \
                 :: "r"((uint32_t)(mb)), "r"((uint32_t)(cnt)) : "memory")
#define MBARRIER_WAIT_PARITY(mb, ph) do {                                   \
    uint32_t _m = (uint32_t)(mb); uint32_t _p = (uint32_t)(ph);             \
    asm volatile("{\n\t.reg .pred P1;\n\t"                                  \
        "WL_%=:\n\t"                                                        \
        "mbarrier.try_wait.parity.acquire.cta.shared::cta.b64 P1, [%0], %1, 0x989680;\n\t" \
        "@P1 bra.uni WD_%=;\n\t"                                            \
        "bra.uni WL_%=;\n\t"                                                \
        "WD_%=:\n\t}" :: "r"(_m), "r"(_p) : "memory");                      \
} while (0)
#define CP_ASYNC16(dst, src) \
    asm volatile("cp.async.cg.shared.global [%0], [%1], 16;" \
                 :: "r"((uint32_t)(dst)), "l"(src) : "memory")
#define CP_COMMIT() asm volatile("cp.async.commit_group;" ::: "memory")
#define CP_WAIT0()  asm volatile("cp.async.wait_group 0;" ::: "memory")

__device__ __forceinline__ void mma_f16_ss_cg1(
    uint32_t d_tmem, uint64_t a_desc, uint64_t b_desc, uint32_t idesc, uint32_t en)
{
    asm volatile(
        "{\n\t.reg .pred p;\n\tsetp.ne.u32 p, %5, 0;\n\t"
        "tcgen05.mma.cta_group::1.kind::f16 [%0], %1, %2, %3, {%4, %4, %4, %4}, p;\n\t}"
        :: "r"(d_tmem), "l"(a_desc), "l"(b_desc), "r"(idesc), "r"(0u), "r"(en)
        : "memory");
}
#define LDTM_X32(r, addr)                                                    \
    asm volatile("tcgen05.ld.sync.aligned.32x32b.x32.b32 "                   \
        "{%0, %1, %2, %3, %4, %5, %6, %7, %8, %9, %10, %11, %12, %13, %14, %15, " \
        " %16, %17, %18, %19, %20, %21, %22, %23, %24, %25, %26, %27, %28, %29, %30, %31}, [%32];" \
        : "=r"((r)[0]),  "=r"((r)[1]),  "=r"((r)[2]),  "=r"((r)[3]),         \
          "=r"((r)[4]),  "=r"((r)[5]),  "=r"((r)[6]),  "=r"((r)[7]),         \
          "=r"((r)[8]),  "=r"((r)[9]),  "=r"((r)[10]), "=r"((r)[11]),        \
          "=r"((r)[12]), "=r"((r)[13]), "=r"((r)[14]), "=r"((r)[15]),        \
          "=r"((r)[16]), "=r"((r)[17]), "=r"((r)[18]), "=r"((r)[19]),        \
          "=r"((r)[20]), "=r"((r)[21]), "=r"((r)[22]), "=r"((r)[23]),        \
          "=r"((r)[24]), "=r"((r)[25]), "=r"((r)[26]), "=r"((r)[27]),        \
          "=r"((r)[28]), "=r"((r)[29]), "=r"((r)[30]), "=r"((r)[31])         \
        : "r"(addr))
#endif  // HAS_TC

// ---------------- prep kernels ----------------
__global__ __launch_bounds__(256) void split_hl(
    const float* __restrict__ src, __nv_bfloat16* __restrict__ hi,
    __nv_bfloat16* __restrict__ lo, int n4)
{
    int i = blockIdx.x * 256 + threadIdx.x;
    if (i >= n4) return;
    float4 v = ((const float4*)src)[i];
    float vs[4] = {v.x, v.y, v.z, v.w};
    __nv_bfloat16 h[4], l[4];
#pragma unroll
    for (int j = 0; j < 4; j++) {
        h[j] = __float2bfloat16(vs[j]);
        l[j] = __float2bfloat16(vs[j] - __bfloat162float(h[j]));
    }
    ((__nv_bfloat162*)hi)[2*i]   = __halves2bfloat162(h[0], h[1]);
    ((__nv_bfloat162*)hi)[2*i+1] = __halves2bfloat162(h[2], h[3]);
    ((__nv_bfloat162*)lo)[2*i]   = __halves2bfloat162(l[0], l[1]);
    ((__nv_bfloat162*)lo)[2*i+1] = __halves2bfloat162(l[2], l[3]);
}

__global__ void tsplit_kernel(
    const float* __restrict__ W, __nv_bfloat16* __restrict__ Thi,
    __nv_bfloat16* __restrict__ Tlo, int K, int N)
{
    __shared__ float t[32][33];
    int kb = blockIdx.x * 32, nb = blockIdx.y * 32;
    int tx = threadIdx.x, ty = threadIdx.y;
#pragma unroll
    for (int i = 0; i < 4; i++) {
        int k = ty + i * 8;
        t[k][tx] = W[(size_t)(kb + k) * N + nb + tx];
    }
    __syncthreads();
#pragma unroll
    for (int i = 0; i < 4; i++) {
        int nr = ty + i * 8;
        float v = t[tx][nr];
        __nv_bfloat16 h = __float2bfloat16(v);
        __nv_bfloat16 l = __float2bfloat16(v - __bfloat162float(h));
        size_t o = (size_t)(nb + nr) * K + kb + tx;
        Thi[o] = h; Tlo[o] = l;
    }
}

// ---------------- tcgen05 GEMM: 128x256 tile, single buffer, 2 CTA/SM ------
#define GB_AH 0
#define GB_AL 16384
#define GB_BH 32768
#define GB_BL 65536
#define GB_SZ 98304
#define GSM_BUF 1024
#define GEMM_SMEM (GSM_BUF + GB_SZ)      // 99328 -> 2 CTAs/SM
#define GEMM_IDESC 0x8400490u            // f32 acc, bf16xbf16, M=128, N=256

#if HAS_TC
__device__ __forceinline__ void gemm_prefetch(
    uint32_t sbuf, const char* Ah, const char* Al, const char* Bh, const char* Bl,
    int K, int m0, int n0, int k0, int tid)
{
#pragma unroll
    for (int p = 0; p < 4; p++) {           // A: 128 rows x 128B x 2 planes
        int i = tid + p * 256;
        int r = i >> 3, c16 = (i & 7) << 4;
        uint32_t so = SMEM_SWIZZLE_128B(r * 128 + c16);
        size_t go = ((size_t)(m0 + r) * K + k0) * 2 + c16;
        CP_ASYNC16(sbuf + GB_AH + so, Ah + go);
        CP_ASYNC16(sbuf + GB_AL + so, Al + go);
    }
#pragma unroll
    for (int p = 0; p < 8; p++) {           // B: 256 rows x 128B x 2 planes
        int i = tid + p * 256;
        int r = i >> 3, c16 = (i & 7) << 4;
        uint32_t so = SMEM_SWIZZLE_128B(r * 128 + c16);
        size_t go = ((size_t)(n0 + r) * K + k0) * 2 + c16;
        CP_ASYNC16(sbuf + GB_BH + so, Bh + go);
        CP_ASYNC16(sbuf + GB_BL + so, Bl + go);
    }
}
#endif

__global__ __launch_bounds__(256) void gemm_any(
    const __nv_bfloat16* __restrict__ Ahi, const __nv_bfloat16* __restrict__ Alo,
    const __nv_bfloat16* __restrict__ Bthi, const __nv_bfloat16* __restrict__ Btlo,
    const float* __restrict__ bias, float* __restrict__ C,
    int M, int N, int K, int mode)
{
    extern __shared__ char smem[];
#if HAS_TC
    const uint32_t sb = smem_u32(smem);
    const int tid = threadIdx.x;
    const int wid = tid >> 5, lid = tid & 31;
    const int m0 = blockIdx.y * 128, n0 = blockIdx.x * 256;
    const char* Ah = (const char*)Ahi;  const char* Al = (const char*)Alo;
    const char* Bh = (const char*)Bthi; const char* Bl = (const char*)Btlo;

    if (wid == 0) { TCGEN05_ALLOC(sb, 256); TCGEN05_RELINQ(); }
    if (tid == 0) MBARRIER_INIT(sb + 8, 1);
    __syncthreads();
    uint32_t tmem;
    asm volatile("ld.shared.b32 %0, [%1];" : "=r"(tmem) : "r"(sb));

    const uint64_t dAh = MAKE_SMEM_DESC(sb + GSM_BUF + GB_AH);
    const uint64_t dAl = MAKE_SMEM_DESC(sb + GSM_BUF + GB_AL);
    const uint64_t dBh = MAKE_SMEM_DESC(sb + GSM_BUF + GB_BH);
    const uint64_t dBl = MAKE_SMEM_DESC(sb + GSM_BUF + GB_BL);

    const int nchunks = K >> 6;   // 12
    for (int c = 0; c < nchunks; c++) {
        gemm_prefetch(sb + GSM_BUF, Ah, Al, Bh, Bl, K, m0, n0, c * 64, tid);
        CP_COMMIT();
        CP_WAIT0();
        __syncthreads();

        if (wid == 0 && elect_one()) {
#pragma unroll
            for (int ks = 0; ks < 4; ks++) {
                uint32_t en0 = (c > 0 || ks > 0) ? 1u : 0u;
                mma_f16_ss_cg1(tmem, dAh + ks*2, dBh + ks*2, GEMM_IDESC, en0);
                mma_f16_ss_cg1(tmem, dAh + ks*2, dBl + ks*2, GEMM_IDESC, 1u);
                mma_f16_ss_cg1(tmem, dAl + ks*2, dBh + ks*2, GEMM_IDESC, 1u);
            }
            TCGEN05_COMMIT(sb + 8);
        }
        MBARRIER_WAIT_PARITY(sb + 8, c & 1);
    }

    TCGEN05_FENCE_AFTER();
    {   // 8-warp epilogue: warps split 256 cols into 2 halves
        const int row = m0 + (wid & 3) * 32 + lid;
        const int cbase = (wid >> 2) * 128;
        const int b  = row >> 12;
        const int t  = row & 4095;
#pragma unroll
        for (int base = 0; base < 128; base += 32) {
            uint32_t rg[32];
            LDTM_X32(rg, tmem + cbase + base);
            TCGEN05_WAIT_LD();
            const int col0 = n0 + cbase + base;
            const float* bp = bias + col0;
            if (mode == 0) {
                float* crow = C + (size_t)row * N + col0;
#pragma unroll
                for (int j = 0; j < 32; j += 4) {
                    float4 o = make_float4(__uint_as_float(rg[j])   + bp[j],
                                           __uint_as_float(rg[j+1]) + bp[j+1],
                                           __uint_as_float(rg[j+2]) + bp[j+2],
                                           __uint_as_float(rg[j+3]) + bp[j+3]);
                    *(float4*)(crow + j) = o;
                }
            } else {
                const int sec  = col0 / DD;          // 0=q 1=k 2=v
                const int rcol = col0 - sec * DD;
                const int h    = rcol >> 6;
                const int d0   = rcol & 63;          // 0 or 32
                const int bh   = b * HH + h;
                if (sec < 2) {
                    __nv_bfloat16* dh = (sec ? g_kh : g_qh);
                    __nv_bfloat16* dl = (sec ? g_kl : g_ql);
                    size_t off = (((size_t)bh * TT + t) << 6) + d0;
                    uint32_t hp[16], lp[16];
#pragma unroll
                    for (int j2 = 0; j2 < 16; j2++) {
                        float v0 = __uint_as_float(rg[2*j2])   + bp[2*j2];
                        float v1 = __uint_as_float(rg[2*j2+1]) + bp[2*j2+1];
                        __nv_bfloat16 h0 = __float2bfloat16(v0), h1 = __float2bfloat16(v1);
                        __nv_bfloat16 l0 = __float2bfloat16(v0 - __bfloat162float(h0));
                        __nv_bfloat16 l1 = __float2bfloat16(v1 - __bfloat162float(h1));
                        __nv_bfloat162 hh = __halves2bfloat162(h0, h1);
                        __nv_bfloat162 ll = __halves2bfloat162(l0, l1);
                        hp[j2] = *(uint32_t*)&hh; lp[j2] = *(uint32_t*)&ll;
                    }
#pragma unroll
                    for (int k4 = 0; k4 < 4; k4++) {
                        *(uint4*)((char*)dh + off*2 + k4*16) = ((uint4*)hp)[k4];
                        *(uint4*)((char*)dl + off*2 + k4*16) = ((uint4*)lp)[k4];
                    }
                } else {
                    __half* dst = g_vt + (((size_t)bh << 6) + d0) * TT + t;
#pragma unroll
                    for (int j = 0; j < 32; j++)
                        dst[(size_t)j * TT] = __float2half(__uint_as_float(rg[j]) + bp[j]);
                }
            }
        }
    }
    __syncthreads();
    if (wid == 0) TCGEN05_DEALLOC(tmem, 256);
#else
    const int tid = threadIdx.x;
    for (int idx = (blockIdx.y * gridDim.x + blockIdx.x) * 256 + tid;
         idx < M * N; idx += gridDim.x * gridDim.y * 256) {
        int row = idx / N, col = idx % N;
        float acc = bias[col];
        for (int k = 0; k < K; k++)
            acc += __bfloat162float(Ahi[(size_t)row*K+k]) * __bfloat162float(Bthi[(size_t)col*K+k])
                 + __bfloat162float(Alo[(size_t)row*K+k]) * __bfloat162float(Bthi[(size_t)col*K+k])
                 + __bfloat162float(Ahi[(size_t)row*K+k]) * __bfloat162float(Btlo[(size_t)col*K+k]);
        if (mode == 0) {
            C[idx] = acc;
        } else {
            int b = row >> 12, t = row & 4095;
            int sec = col / DD, rcol = col - sec * DD;
            int h = rcol >> 6, d = rcol & 63, bh = b * HH + h;
            if (sec < 2) {
                __nv_bfloat16 hv = __float2bfloat16(acc);
                __nv_bfloat16 lv = __float2bfloat16(acc - __bfloat162float(hv));
                size_t off = (((size_t)bh * TT + t) << 6) + d;
                (sec ? g_kh : g_qh)[off] = hv;
                (sec ? g_kl : g_ql)[off] = lv;
            } else {
                g_vt[(((size_t)bh << 6) + d) * TT + t] = __float2half(acc);
            }
        }
    }
#endif
}

// ---------------- tcgen05 flash attention (512 threads, S double-buffered) --
#define ASM_TPTR 0
#define ASM_MBS0 8
#define ASM_MBS1 16
#define ASM_MBPV 24
#define ASM_QH   1024
#define ASM_QL   (ASM_QH + 16384)
#define ASM_K0H  (ASM_QL + 16384)
#define ASM_K0L  (ASM_K0H + 16384)
#define ASM_K1H  (ASM_K0L + 16384)
#define ASM_K1L  (ASM_K1H + 16384)
#define ASM_V    (ASM_K1L + 16384)         // 3 x 16KB
#define ASM_P    (ASM_V + 49152)           // 32KB
#define ASM_LP   (ASM_P + 32768)           // 4 x 128 floats
#define ATT_SMEM (ASM_LP + 2048)           // 183296
#define IDESC_S      0x8200490u            // M=128 N=128 bf16->f32
#define IDESC_PV_F16 0x8100010u            // M=128 N=64  f16->f32
// TMEM: S0 @0, S1 @128, O @256

__global__ __launch_bounds__(512) void attn_tc()
{
#if HAS_TC
    extern __shared__ char smem[];
    const uint32_t sb = smem_u32(smem);
    const int tid = threadIdx.x;
    const int w = tid >> 5, lid = tid & 31;
    const int bh = blockIdx.y;
    const int qt = gridDim.x - 1 - blockIdx.x;
    const int q0 = qt * 128;
    const int r  = (w & 3) * 32 + lid;     // owned row
    const int cq = w >> 2;                 // col quarter 0..3

    const char* qh = (const char*)(g_qh + (size_t)bh*TT*HDIM);
    const char* ql = (const char*)(g_ql + (size_t)bh*TT*HDIM);
    const char* kh = (const char*)(g_kh + (size_t)bh*TT*HDIM);
    const char* kl = (const char*)(g_kl + (size_t)bh*TT*HDIM);
    const char* vt = (const char*)(g_vt + (size_t)bh*HDIM*TT);

    if (w == 0) { TCGEN05_ALLOC(sb + ASM_TPTR, 512); TCGEN05_RELINQ(); }
    if (tid == 0) {
        MBARRIER_INIT(sb + ASM_MBS0, 1);
        MBARRIER_INIT(sb + ASM_MBS1, 1);
        MBARRIER_INIT(sb + ASM_MBPV, 1);
    }

    // Q tile (2 planes, 1024 uint4 slots each)
#pragma unroll
    for (int p = 0; p < 2; p++) {
        int i = tid + p*512; int rr = i >> 3; int c16 = (i & 7) << 4;
        uint32_t so = SMEM_SWIZZLE_128B(rr*128 + c16);
        *(uint4*)(smem + ASM_QH + so) = *(const uint4*)(qh + (size_t)(q0+rr)*128 + c16);
        *(uint4*)(smem + ASM_QL + so) = *(const uint4*)(ql + (size_t)(q0+rr)*128 + c16);
    }
    // K/V(0)
    {
#pragma unroll
        for (int p = 0; p < 2; p++) {
            int i = tid + p*512; int rr = i >> 3; int c16 = (i & 7) << 4;
            uint32_t so = SMEM_SWIZZLE_128B(rr*128 + c16);
            CP_ASYNC16(sb + ASM_K0H + so, kh + (size_t)rr*128 + c16);
            CP_ASYNC16(sb + ASM_K0L + so, kl + (size_t)rr*128 + c16);
        }
#pragma unroll
        for (int p = 0; p < 2; p++) {
            int i = tid + p*512; int d = i >> 4; int j = i & 15;
            uint32_t bo = (uint32_t)((((d>>3) + (j>>3)*8) << 10) + ((d & 7) << 7) + ((j & 7) << 4));
            CP_ASYNC16(sb + ASM_V + SMEM_SWIZZLE_128B(bo), vt + ((size_t)d*TT + j*8)*2);
        }
        CP_COMMIT();
    }
    CP_WAIT0();
    FENCE_PROXY_ASYNC();
    __syncthreads();
    uint32_t tmem;
    asm volatile("ld.shared.b32 %0, [%1];" : "=r"(tmem) : "r"(sb + ASM_TPTR));

    const uint64_t dQh = MAKE_SMEM_DESC(sb+ASM_QH), dQl = MAKE_SMEM_DESC(sb+ASM_QL);
    const uint64_t dP  = MAKE_SMEM_DESC(sb+ASM_P);
    const uint64_t dK[2][2] = {
        { MAKE_SMEM_DESC(sb+ASM_K0H), MAKE_SMEM_DESC(sb+ASM_K0L) },
        { MAKE_SMEM_DESC(sb+ASM_K1H), MAKE_SMEM_DESC(sb+ASM_K1L) } };
    const uint32_t mbS[2] = { sb + ASM_MBS0, sb + ASM_MBS1 };

    // S(0)
    if (w == 0 && elect_one()) {
#pragma unroll
        for (int ks = 0; ks < 4; ks++) {
            mma_f16_ss_cg1(tmem, dQh + ks*2, dK[0][0] + ks*2, IDESC_S, ks > 0);
            mma_f16_ss_cg1(tmem, dQh + ks*2, dK[0][1] + ks*2, IDESC_S, 1u);
            mma_f16_ss_cg1(tmem, dQl + ks*2, dK[0][0] + ks*2, IDESC_S, 1u);
        }
        TCGEN05_COMMIT(mbS[0]);
    }
    // prefetch K/V(1)
    if (qt > 0) {
#pragma unroll
        for (int p = 0; p < 2; p++) {
            int i = tid + p*512; int rr = i >> 3; int c16 = (i & 7) << 4;
            uint32_t so = SMEM_SWIZZLE_128B(rr*128 + c16);
            CP_ASYNC16(sb + ASM_K1H + so, kh + (size_t)(128+rr)*128 + c16);
            CP_ASYNC16(sb + ASM_K1L + so, kl + (size_t)(128+rr)*128 + c16);
        }
#pragma unroll
        for (int p = 0; p < 2; p++) {
            int i = tid + p*512; int d = i >> 4; int j = i & 15;
            uint32_t bo = (uint32_t)((((d>>3) + (j>>3)*8) << 10) + ((d & 7) << 7) + ((j & 7) << 4));
            CP_ASYNC16(sb + ASM_V + 16384 + SMEM_SWIZZLE_128B(bo),
                       vt + ((size_t)d*TT + 128 + j*8)*2);
        }
        CP_COMMIT();
    }

    float lsum = 0.f;
    // P blocked-atom byte base for this warp's 32x32 quadrant
    const uint32_t pbase = (uint32_t)((((r>>3) + (cq>>1)*16) << 10) + ((r & 7) << 7) + ((cq & 1) << 6));

    for (int kt = 0; kt <= qt; kt++) {
        const int buf = kt & 1;

        if (kt < qt) {
            CP_WAIT0();
            FENCE_PROXY_ASYNC();
            __syncthreads();
            if (w == 0 && elect_one()) {
                const int nb = (kt + 1) & 1;
#pragma unroll
                for (int ks = 0; ks < 4; ks++) {
                    mma_f16_ss_cg1(tmem + nb*128, dQh + ks*2, dK[nb][0] + ks*2, IDESC_S, ks > 0);
                    mma_f16_ss_cg1(tmem + nb*128, dQh + ks*2, dK[nb][1] + ks*2, IDESC_S, 1u);
                    mma_f16_ss_cg1(tmem + nb*128, dQl + ks*2, dK[nb][0] + ks*2, IDESC_S, 1u);
                }
                TCGEN05_COMMIT(mbS[nb]);
            }
        }

        MBARRIER_WAIT_PARITY(mbS[buf], (kt >> 1) & 1);
        TCGEN05_FENCE_AFTER();

        // epilogue: each warp one 32x32 quadrant
        const bool diag = (kt == qt);
        uint32_t sreg[32];
        LDTM_X32(sreg, tmem + buf*128 + cq*32);
        TCGEN05_WAIT_LD();
        uint32_t hp[16];
#pragma unroll
        for (int j2 = 0; j2 < 16; j2++) {
            float e0 = __expf(__uint_as_float(sreg[2*j2])   * ATT_SCALE);
            float e1 = __expf(__uint_as_float(sreg[2*j2+1]) * ATT_SCALE);
            if (diag) {
                int c = cq*32 + 2*j2;
                if (c     > r) e0 = 0.f;
                if (c + 1 > r) e1 = 0.f;
            }
            lsum += e0 + e1;
            __half2 hh = __floats2half2_rn(e0, e1);
            hp[j2] = *(uint32_t*)&hh;
        }

        // PV(kt-1) retired -> P writable (overlaps the exp work above)
        if (kt > 0) MBARRIER_WAIT_PARITY(sb + ASM_MBPV, (kt-1) & 1);
#pragma unroll
        for (int k4 = 0; k4 < 4; k4++) {
            uint32_t so = SMEM_SWIZZLE_128B(pbase + k4*16);
            *(uint4*)(smem + ASM_P + so) = ((uint4*)hp)[k4];
        }

        // prefetch K/V(kt+2)
        if (kt + 2 <= qt) {
            const int k2 = (kt + 2) * 128;
            const uint32_t nKH = sb + (buf ? ASM_K1H : ASM_K0H);
            const uint32_t nKL = sb + (buf ? ASM_K1L : ASM_K0L);
            const uint32_t nV  = sb + ASM_V + ((kt + 2) % 3) * 16384;
#pragma unroll
            for (int p = 0; p < 2; p++) {
                int i = tid + p*512; int rr = i >> 3; int c16 = (i & 7) << 4;
                uint32_t so = SMEM_SWIZZLE_128B(rr*128 + c16);
                CP_ASYNC16(nKH + so, kh + (size_t)(k2+rr)*128 + c16);
                CP_ASYNC16(nKL + so, kl + (size_t)(k2+rr)*128 + c16);
            }
#pragma unroll
            for (int p = 0; p < 2; p++) {
                int i = tid + p*512; int d = i >> 4; int j = i & 15;
                uint32_t bo = (uint32_t)((((d>>3) + (j>>3)*8) << 10) + ((d & 7) << 7) + ((j & 7) << 4));
                CP_ASYNC16(nV + SMEM_SWIZZLE_128B(bo), vt + ((size_t)d*TT + k2 + j*8)*2);
            }
            CP_COMMIT();
        }

        FENCE_PROXY_ASYNC();
        TCGEN05_FENCE_BEFORE();
        __syncthreads();

        if (w == 0 && elect_one()) {
            const uint64_t dV = MAKE_SMEM_DESC(sb + ASM_V + (kt % 3) * 16384);
#pragma unroll
            for (int ks = 0; ks < 8; ks++) {
                uint32_t po = (ks < 4) ? ks*2 : 1024 + (ks-4)*2;
                uint32_t vo = (ks < 4) ? ks*2 : 512  + (ks-4)*2;
                uint32_t en0 = (kt > 0 || ks > 0) ? 1u : 0u;
                mma_f16_ss_cg1(tmem + 256, dP + po, dV + vo, IDESC_PV_F16, en0);
            }
            TCGEN05_COMMIT(sb + ASM_MBPV);
        }
    }
    CP_WAIT0();
    MBARRIER_WAIT_PARITY(sb + ASM_MBPV, qt & 1);
    TCGEN05_FENCE_AFTER();

    // O epilogue
    *(float*)(smem + ASM_LP + (cq*128 + r)*4) = lsum;
    __syncthreads();
    if (cq < 2) {
        uint32_t oreg[32];
        LDTM_X32(oreg, tmem + 256 + cq*32);
        TCGEN05_WAIT_LD();
        float lt = *(float*)(smem + ASM_LP + r*4)
                 + *(float*)(smem + ASM_LP + (128 + r)*4)
                 + *(float*)(smem + ASM_LP + (256 + r)*4)
                 + *(float*)(smem + ASM_LP + (384 + r)*4);
        float inv = 1.f / lt;
        const int b2 = bh / HH, h2 = bh % HH;
        size_t oo = ((size_t)(b2*TT + q0 + r)*DD + h2*HDIM + cq*32) * 2;
        uint32_t hp[16], lp[16];
#pragma unroll
        for (int j2 = 0; j2 < 16; j2++) {
            float e0 = __uint_as_float(oreg[2*j2])   * inv;
            float e1 = __uint_as_float(oreg[2*j2+1]) * inv;
            __nv_bfloat16 h0 = __float2bfloat16(e0), h1 = __float2bfloat16(e1);
            __nv_bfloat16 l0 = __float2bfloat16(e0 - __bfloat162float(h0));
            __nv_bfloat16 l1 = __float2bfloat16(e1 - __bfloat162float(h1));
            __nv_bfloat162 hh = __halves2bfloat162(h0, h1);
            __nv_bfloat162 ll = __halves2bfloat162(l0, l1);
            hp[j2] = *(uint32_t*)&hh; lp[j2] = *(uint32_t*)&ll;
        }
#pragma unroll
        for (int k4 = 0; k4 < 4; k4++) {
            *(uint4*)((char*)g_ahi + oo + k4*16) = ((uint4*)hp)[k4];
            *(uint4*)((char*)g_alo + oo + k4*16) = ((uint4*)lp)[k4];
        }
    }
    __syncthreads();
    if (w == 0) TCGEN05_DEALLOC(tmem, 512);
#endif
}

// ---------------------------------------------------------------------------
extern "C" void kernel_launch(void* const* d_in, const int* in_sizes, int n_in,
                              void* d_out, int out_size)
{
    const float* x     = (const float*)d_in[0];
    const float* W_qkv = (const float*)d_in[1];
    const float* b_qkv = (const float*)d_in[2];
    const float* W_out = (const float*)d_in[3];
    const float* b_out = (const float*)d_in[4];
    float* out = (float*)d_out;

    void* p;
    cudaGetSymbolAddress(&p, g_xhi);    __nv_bfloat16* xhi = (__nv_bfloat16*)p;
    cudaGetSymbolAddress(&p, g_xlo);    __nv_bfloat16* xlo = (__nv_bfloat16*)p;
    cudaGetSymbolAddress(&p, g_ahi);    __nv_bfloat16* ahi = (__nv_bfloat16*)p;
    cudaGetSymbolAddress(&p, g_alo);    __nv_bfloat16* alo = (__nv_bfloat16*)p;
    cudaGetSymbolAddress(&p, g_wqt_hi); __nv_bfloat16* wqh = (__nv_bfloat16*)p;
    cudaGetSymbolAddress(&p, g_wqt_lo); __nv_bfloat16* wql = (__nv_bfloat16*)p;
    cudaGetSymbolAddress(&p, g_wot_hi); __nv_bfloat16* woh = (__nv_bfloat16*)p;
    cudaGetSymbolAddress(&p, g_wot_lo); __nv_bfloat16* wol = (__nv_bfloat16*)p;

    const int M = BB * TT;  // 8192

    {
        int n4 = M * DD / 4;
        split_hl<<<(n4 + 255) / 256, 256>>>(x, xhi, xlo, n4);
        tsplit_kernel<<<dim3(DD/32, QKV3/32), dim3(32, 8)>>>(W_qkv, wqh, wql, DD, QKV3);
        tsplit_kernel<<<dim3(DD/32, DD/32),   dim3(32, 8)>>>(W_out, woh, wol, DD, DD);
    }

    cudaFuncSetAttribute(gemm_any, cudaFuncAttributeMaxDynamicSharedMemorySize, GEMM_SMEM);

    // 1) QKV projection with fused split/transpose epilogue (mode 1)
    gemm_any<<<dim3(QKV3/256, M/128), 256, GEMM_SMEM>>>(
        xhi, xlo, wqh, wql, b_qkv, nullptr, M, QKV3, DD, 1);

    // 2) attention -> g_ahi/g_alo
    cudaFuncSetAttribute(attn_tc, cudaFuncAttributeMaxDynamicSharedMemorySize, ATT_SMEM);
    attn_tc<<<dim3(TT/128, BB*HH), 512, ATT_SMEM>>>();

    // 3) output projection (mode 0)
    gemm_any<<<dim3(DD/256, M/128), 256, GEMM_SMEM>>>(
        ahi, alo, woh, wol, b_out, out, M, DD, DD, 0);
}